// round 1
// baseline (speedup 1.0000x reference)
#include <cuda_runtime.h>
#include <cuda_bf16.h>
#include <math.h>

// Problem constants
constexpr int CB = 2, CS = 2048, CD = 256, CH = 4, CL = 4, CV = 50257, CHD = 64;
constexpr int CM = CB * CS;      // 4096 rows everywhere
constexpr int CFF = 4 * CD;      // 1024

// ----------------------------------------------------------------------------
// Scratch (static device globals — no allocation inside kernel_launch)
// ----------------------------------------------------------------------------
__device__ float g_h[CM * CD];
__device__ float g_n[CM * CD];
__device__ float g_q[CM * CD];
__device__ float g_k[CM * CD];
__device__ float g_v[CM * CD];
__device__ float g_att[CM * CD];
__device__ float g_mlp[CM * CFF];

// ----------------------------------------------------------------------------
// Embedding: h[b,s,:] = tok_emb[ids[b,s],:] + pos_emb[s,:]
// ----------------------------------------------------------------------------
__global__ void embed_kernel(const int* __restrict__ ids,
                             const float* __restrict__ tok,
                             const float* __restrict__ pos,
                             float* __restrict__ h) {
    int i = blockIdx.x;          // token index 0..4095
    int d = threadIdx.x;         // 0..255
    int s = i & (CS - 1);
    h[(size_t)i * CD + d] = tok[(size_t)ids[i] * CD + d] + pos[(size_t)s * CD + d];
}

// ----------------------------------------------------------------------------
// LayerNorm: one warp per row (D=256 -> 8 elements per lane)
// ----------------------------------------------------------------------------
__global__ void ln_kernel(const float* __restrict__ x,
                          const float* __restrict__ sc,
                          const float* __restrict__ bi,
                          float* __restrict__ y) {
    int row = blockIdx.x * 8 + threadIdx.y;   // blockDim = (32, 8)
    int lane = threadIdx.x;
    const float* xr = x + (size_t)row * CD;
    float v[8];
    float sum = 0.f, sq = 0.f;
#pragma unroll
    for (int j = 0; j < 8; j++) {
        v[j] = xr[lane + 32 * j];
        sum += v[j];
        sq += v[j] * v[j];
    }
#pragma unroll
    for (int o = 16; o > 0; o >>= 1) {
        sum += __shfl_xor_sync(0xffffffffu, sum, o);
        sq  += __shfl_xor_sync(0xffffffffu, sq, o);
    }
    float mean = sum * (1.f / CD);
    float var  = sq * (1.f / CD) - mean * mean;
    float inv  = rsqrtf(var + 1e-5f);
    float* yr = y + (size_t)row * CD;
#pragma unroll
    for (int j = 0; j < 8; j++) {
        int c = lane + 32 * j;
        yr[c] = (v[j] - mean) * inv * sc[c] + bi[c];
    }
}

// ----------------------------------------------------------------------------
// Generic fp32 GEMM: C[M=4096, N] = A[4096, K] @ B + bias (+ GELU) (+ resid)
// TRANSB=false: B is (K, N) row-major.  TRANSB=true: B is (N, K) row-major.
// Tiles: 128x128x8, 256 threads, 8x8 per thread.
// ----------------------------------------------------------------------------
template <bool TRANSB, bool GELU>
__global__ __launch_bounds__(256)
void gemm_kernel(const float* __restrict__ A, const float* __restrict__ Bw,
                 const float* __restrict__ bias, const float* __restrict__ resid,
                 float* __restrict__ C, int N, int K) {
    __shared__ float As[8][128];
    __shared__ float Bs[8][128];
    int m0 = blockIdx.y * 128;
    int n0 = blockIdx.x * 128;
    int t = threadIdx.x;
    int tx = t & 15, ty = t >> 4;
    float acc[8][8] = {};

    for (int k0 = 0; k0 < K; k0 += 8) {
        {   // A tile: 128 rows x 8 k (M=4096 multiple of 128, K multiple of 8)
            int row = t >> 1, kq = (t & 1) * 4;
            float4 av = *(const float4*)(A + (size_t)(m0 + row) * K + k0 + kq);
            As[kq + 0][row] = av.x; As[kq + 1][row] = av.y;
            As[kq + 2][row] = av.z; As[kq + 3][row] = av.w;
        }
        if (!TRANSB) {   // B (K,N): N is a multiple of 128 for all such uses
            int kk = t >> 5, n4 = (t & 31) * 4;
            float4 bv = *(const float4*)(Bw + (size_t)(k0 + kk) * N + n0 + n4);
            *(float4*)&Bs[kk][n4] = bv;
        } else {         // B (N,K): guard n (V=50257 not a multiple of 128)
            int n = t >> 1, kq = (t & 1) * 4;
            float4 bv = make_float4(0.f, 0.f, 0.f, 0.f);
            if (n0 + n < N)
                bv = *(const float4*)(Bw + (size_t)(n0 + n) * K + k0 + kq);
            Bs[kq + 0][n] = bv.x; Bs[kq + 1][n] = bv.y;
            Bs[kq + 2][n] = bv.z; Bs[kq + 3][n] = bv.w;
        }
        __syncthreads();
#pragma unroll
        for (int kk = 0; kk < 8; kk++) {
            float a[8], b[8];
            *(float4*)&a[0] = *(const float4*)&As[kk][ty * 8];
            *(float4*)&a[4] = *(const float4*)&As[kk][ty * 8 + 4];
            *(float4*)&b[0] = *(const float4*)&Bs[kk][tx * 8];
            *(float4*)&b[4] = *(const float4*)&Bs[kk][tx * 8 + 4];
#pragma unroll
            for (int i = 0; i < 8; i++)
#pragma unroll
                for (int j = 0; j < 8; j++)
                    acc[i][j] += a[i] * b[j];
        }
        __syncthreads();
    }

#pragma unroll
    for (int i = 0; i < 8; i++) {
        int m = m0 + ty * 8 + i;
#pragma unroll
        for (int j = 0; j < 8; j++) {
            int n = n0 + tx * 8 + j;
            if (TRANSB && n >= N) continue;
            float v = acc[i][j];
            if (bias) v += bias[n];
            if (GELU) v = 0.5f * v * (1.f + erff(v * 0.70710678118654752f));
            if (resid) v += resid[(size_t)m * N + n];
            C[(size_t)m * N + n] = v;
        }
    }
}

// ----------------------------------------------------------------------------
// Flash-style causal attention. Grid (S/64, B*H), 256 threads.
// Q/K/V/O are (B*S, D) with head offset h*64, row stride D.
// ----------------------------------------------------------------------------
constexpr int ATTN_SMEM = (64 * 64 + 64 * 65 + 64 * 64 + 64 * 64) * 4;  // 65792 B

__global__ __launch_bounds__(256)
void attn_kernel(const float* __restrict__ Q, const float* __restrict__ Km,
                 const float* __restrict__ Vm, float* __restrict__ O) {
    extern __shared__ float smem[];
    float* Qs = smem;             // [64][64]
    float* Ks = Qs + 64 * 64;     // [64][65]  (pad: 16-distinct-row column access)
    float* Vs = Ks + 64 * 65;     // [64][64]
    float* Ps = Vs + 64 * 64;     // [64][64]  scores / probabilities
    __shared__ float sm_m[64], sm_l[64], sm_f[64];

    int t = threadIdx.x;
    int sx = t & 15, sy = t >> 4;
    int bh = blockIdx.y;
    int b = bh >> 2, h = bh & 3;
    size_t base = (size_t)b * CS * CD + (size_t)h * CHD;
    int q0 = blockIdx.x * 64;

    // Load Q tile
    for (int x = t; x < 64 * 16; x += 256) {
        int r = x >> 4, d4 = x & 15;
        *(float4*)&Qs[r * 64 + d4 * 4] =
            *(const float4*)(Q + base + (size_t)(q0 + r) * CD + d4 * 4);
    }
    if (t < 64) { sm_m[t] = -1e30f; sm_l[t] = 0.f; }

    float acc[4][4] = {};
    int row = t >> 2, sub = t & 3;

    for (int kt = 0; kt <= (int)blockIdx.x; kt++) {
        int k0 = kt * 64;
        __syncthreads();   // prior-iteration Ps reads done; Q tile visible (iter 0)
        for (int x = t; x < 64 * 16; x += 256) {
            int r = x >> 4, d4 = x & 15;
            float4 kv = *(const float4*)(Km + base + (size_t)(k0 + r) * CD + d4 * 4);
            Ks[r * 65 + d4 * 4 + 0] = kv.x; Ks[r * 65 + d4 * 4 + 1] = kv.y;
            Ks[r * 65 + d4 * 4 + 2] = kv.z; Ks[r * 65 + d4 * 4 + 3] = kv.w;
            *(float4*)&Vs[r * 64 + d4 * 4] =
                *(const float4*)(Vm + base + (size_t)(k0 + r) * CD + d4 * 4);
        }
        __syncthreads();

        // Scores s[4sy+i][4sx+j] = dot64(Q, K) * 0.125
        float scr[4][4] = {};
#pragma unroll
        for (int d4 = 0; d4 < 16; d4++) {
            float4 a[4];
#pragma unroll
            for (int i = 0; i < 4; i++)
                a[i] = *(const float4*)&Qs[(sy * 4 + i) * 64 + d4 * 4];
#pragma unroll
            for (int j = 0; j < 4; j++) {
                const float* kr = &Ks[(sx * 4 + j) * 65 + d4 * 4];
                float b0 = kr[0], b1 = kr[1], b2 = kr[2], b3 = kr[3];
#pragma unroll
                for (int i = 0; i < 4; i++)
                    scr[i][j] += a[i].x * b0 + a[i].y * b1 + a[i].z * b2 + a[i].w * b3;
            }
        }
        bool diag = (kt == (int)blockIdx.x);
#pragma unroll
        for (int i = 0; i < 4; i++)
#pragma unroll
            for (int j = 0; j < 4; j++) {
                float s = scr[i][j] * 0.125f;
                if (diag && (sx * 4 + j) > (sy * 4 + i)) s = -1e30f;
                Ps[(sy * 4 + i) * 64 + sx * 4 + j] = s;
            }
        __syncthreads();

        // Online softmax: 4 lanes per row
        {
            float mprev = sm_m[row];
            float tmax = -1e30f;
#pragma unroll
            for (int kk = 0; kk < 16; kk++)
                tmax = fmaxf(tmax, Ps[row * 64 + sub * 16 + kk]);
            tmax = fmaxf(tmax, __shfl_xor_sync(0xffffffffu, tmax, 1));
            tmax = fmaxf(tmax, __shfl_xor_sync(0xffffffffu, tmax, 2));
            float mnew = fmaxf(mprev, tmax);
            float psum = 0.f;
#pragma unroll
            for (int kk = 0; kk < 16; kk++) {
                float p = __expf(Ps[row * 64 + sub * 16 + kk] - mnew);
                Ps[row * 64 + sub * 16 + kk] = p;
                psum += p;
            }
            psum += __shfl_xor_sync(0xffffffffu, psum, 1);
            psum += __shfl_xor_sync(0xffffffffu, psum, 2);
            if (sub == 0) {
                float fr = __expf(mprev - mnew);
                sm_f[row] = fr;
                sm_m[row] = mnew;
                sm_l[row] = sm_l[row] * fr + psum;
            }
        }
        __syncthreads();

        // Rescale accumulators, then acc += P @ V
#pragma unroll
        for (int i = 0; i < 4; i++) {
            float fr = sm_f[sy * 4 + i];
#pragma unroll
            for (int j = 0; j < 4; j++) acc[i][j] *= fr;
        }
#pragma unroll 4
        for (int kk = 0; kk < 64; kk++) {
            float a[4];
#pragma unroll
            for (int i = 0; i < 4; i++) a[i] = Ps[(sy * 4 + i) * 64 + kk];
            float4 bv = *(const float4*)&Vs[kk * 64 + sx * 4];
#pragma unroll
            for (int i = 0; i < 4; i++) {
                acc[i][0] += a[i] * bv.x; acc[i][1] += a[i] * bv.y;
                acc[i][2] += a[i] * bv.z; acc[i][3] += a[i] * bv.w;
            }
        }
    }

#pragma unroll
    for (int i = 0; i < 4; i++) {
        int qg = q0 + sy * 4 + i;
        float inv = 1.f / sm_l[sy * 4 + i];
#pragma unroll
        for (int j = 0; j < 4; j++)
            O[base + (size_t)qg * CD + sx * 4 + j] = acc[i][j] * inv;
    }
}

// ----------------------------------------------------------------------------
// Orchestration
// ----------------------------------------------------------------------------
extern "C" void kernel_launch(void* const* d_in, const int* in_sizes, int n_in,
                              void* d_out, int out_size) {
    const int*   ids  = (const int*)d_in[0];
    const float* tok  = (const float*)d_in[1];
    const float* pos  = (const float*)d_in[2];
    const float* Wq   = (const float*)d_in[3];
    const float* bq   = (const float*)d_in[4];
    const float* Wk   = (const float*)d_in[5];
    const float* bk   = (const float*)d_in[6];
    const float* Wv   = (const float*)d_in[7];
    const float* bv   = (const float*)d_in[8];
    const float* Wo   = (const float*)d_in[9];
    const float* bo   = (const float*)d_in[10];
    const float* ln1s = (const float*)d_in[11];
    const float* ln1b = (const float*)d_in[12];
    const float* ln2s = (const float*)d_in[13];
    const float* ln2b = (const float*)d_in[14];
    const float* W1   = (const float*)d_in[15];
    const float* b1   = (const float*)d_in[16];
    const float* W2   = (const float*)d_in[17];
    const float* b2   = (const float*)d_in[18];
    const float* lnfs = (const float*)d_in[19];
    const float* lnfb = (const float*)d_in[20];
    float* out = (float*)d_out;

    float *h, *n, *q, *k, *v, *att, *mlp;
    cudaGetSymbolAddress((void**)&h,   g_h);
    cudaGetSymbolAddress((void**)&n,   g_n);
    cudaGetSymbolAddress((void**)&q,   g_q);
    cudaGetSymbolAddress((void**)&k,   g_k);
    cudaGetSymbolAddress((void**)&v,   g_v);
    cudaGetSymbolAddress((void**)&att, g_att);
    cudaGetSymbolAddress((void**)&mlp, g_mlp);

    cudaFuncSetAttribute(attn_kernel,
                         cudaFuncAttributeMaxDynamicSharedMemorySize, ATTN_SMEM);

    dim3 lnb(32, 8);
    embed_kernel<<<CM, CD>>>(ids, tok, pos, h);

    for (int l = 0; l < CL; l++) {
        size_t wofs  = (size_t)l * CD * CD;
        size_t bofs  = (size_t)l * CD;
        size_t w1ofs = (size_t)l * CD * CFF;
        size_t b1ofs = (size_t)l * CFF;
        size_t w2ofs = (size_t)l * CFF * CD;

        ln_kernel<<<CM / 8, lnb>>>(h, ln1s + bofs, ln1b + bofs, n);
        gemm_kernel<false, false><<<dim3(CD / 128, CM / 128), 256>>>(
            n, Wq + wofs, bq + bofs, nullptr, q, CD, CD);
        gemm_kernel<false, false><<<dim3(CD / 128, CM / 128), 256>>>(
            n, Wk + wofs, bk + bofs, nullptr, k, CD, CD);
        gemm_kernel<false, false><<<dim3(CD / 128, CM / 128), 256>>>(
            n, Wv + wofs, bv + bofs, nullptr, v, CD, CD);

        attn_kernel<<<dim3(CS / 64, CB * CH), 256, ATTN_SMEM>>>(q, k, v, att);

        gemm_kernel<false, false><<<dim3(CD / 128, CM / 128), 256>>>(
            att, Wo + wofs, bo + bofs, h, h, CD, CD);

        ln_kernel<<<CM / 8, lnb>>>(h, ln2s + bofs, ln2b + bofs, n);
        gemm_kernel<false, true><<<dim3(CFF / 128, CM / 128), 256>>>(
            n, W1 + w1ofs, b1 + b1ofs, nullptr, mlp, CFF, CD);
        gemm_kernel<false, false><<<dim3(CD / 128, CM / 128), 256>>>(
            mlp, W2 + w2ofs, b2 + bofs, h, h, CD, CFF);
    }

    ln_kernel<<<CM / 8, lnb>>>(h, lnfs, lnfb, n);
    gemm_kernel<true, false><<<dim3((CV + 127) / 128, CM / 128), 256>>>(
        n, tok, nullptr, nullptr, out, CV, CD);
}

// round 3
// speedup vs baseline: 1.2193x; 1.2193x over previous
#include <cuda_runtime.h>
#include <cuda_bf16.h>
#include <math.h>

// Problem constants
constexpr int CB = 2, CS = 2048, CD = 256, CH = 4, CL = 4, CV = 50257, CHD = 64;
constexpr int CM = CB * CS;      // 4096 rows everywhere
constexpr int CFF = 4 * CD;      // 1024

// ----------------------------------------------------------------------------
// Scratch (static device globals — no allocation inside kernel_launch)
// ----------------------------------------------------------------------------
__device__ float g_h[CM * CD];
__device__ float g_n[CM * CD];
__device__ float g_q[CM * CD];
__device__ float g_k[CM * CD];
__device__ float g_v[CM * CD];
__device__ float g_att[CM * CD];
__device__ float g_mlp[CM * CFF];

// ----------------------------------------------------------------------------
// f32x2 helpers (Blackwell packed fp32 pipe: 2 FMAs per FFMA2 instruction)
// ----------------------------------------------------------------------------
__device__ __forceinline__ void ffma2(unsigned long long& d,
                                      unsigned long long a,
                                      unsigned long long b) {
    asm("fma.rn.f32x2 %0, %1, %2, %0;" : "+l"(d) : "l"(a), "l"(b));
}
__device__ __forceinline__ unsigned long long pack2(float x) {
    unsigned long long r;
    unsigned int u = __float_as_uint(x);
    asm("mov.b64 %0, {%1, %1};" : "=l"(r) : "r"(u));
    return r;
}
__device__ __forceinline__ float2 unpack2(unsigned long long v) {
    unsigned int lo, hi;
    asm("mov.b64 {%0, %1}, %2;" : "=r"(lo), "=r"(hi) : "l"(v));
    return make_float2(__uint_as_float(lo), __uint_as_float(hi));
}

// ----------------------------------------------------------------------------
// Embedding: h[b,s,:] = tok_emb[ids[b,s],:] + pos_emb[s,:]
// ----------------------------------------------------------------------------
__global__ void embed_kernel(const int* __restrict__ ids,
                             const float* __restrict__ tok,
                             const float* __restrict__ pos,
                             float* __restrict__ h) {
    int i = blockIdx.x;
    int d = threadIdx.x;
    int s = i & (CS - 1);
    h[(size_t)i * CD + d] = tok[(size_t)ids[i] * CD + d] + pos[(size_t)s * CD + d];
}

// ----------------------------------------------------------------------------
// LayerNorm: one warp per row (D=256 -> 8 elements per lane)
// ----------------------------------------------------------------------------
__global__ void ln_kernel(const float* __restrict__ x,
                          const float* __restrict__ sc,
                          const float* __restrict__ bi,
                          float* __restrict__ y) {
    int row = blockIdx.x * 8 + threadIdx.y;   // blockDim = (32, 8)
    int lane = threadIdx.x;
    const float* xr = x + (size_t)row * CD;
    float v[8];
    float sum = 0.f, sq = 0.f;
#pragma unroll
    for (int j = 0; j < 8; j++) {
        v[j] = xr[lane + 32 * j];
        sum += v[j];
        sq += v[j] * v[j];
    }
#pragma unroll
    for (int o = 16; o > 0; o >>= 1) {
        sum += __shfl_xor_sync(0xffffffffu, sum, o);
        sq  += __shfl_xor_sync(0xffffffffu, sq, o);
    }
    float mean = sum * (1.f / CD);
    float var  = sq * (1.f / CD) - mean * mean;
    float inv  = rsqrtf(var + 1e-5f);
    float* yr = y + (size_t)row * CD;
#pragma unroll
    for (int j = 0; j < 8; j++) {
        int c = lane + 32 * j;
        yr[c] = (v[j] - mean) * inv * sc[c] + bi[c];
    }
}

// ----------------------------------------------------------------------------
// Core fp32 GEMM tile: 128(M) x 128(N) x K, BK=16, 256 threads, FFMA2 mainloop.
// Thread microtile: 8(M: 4 f32x2 pairs) x 8(N).
// TRANSB=false: B is (K, N) row-major, N multiple of 128.
// TRANSB=true:  B is (N, K) row-major, arbitrary N (lm_head, N=50257 odd!)
//               -> epilogue must use SCALAR stores (row base not 16B aligned).
// ----------------------------------------------------------------------------
template <bool TRANSB, bool GELU>
__device__ __forceinline__ void gemm_core(
    const float* __restrict__ A, const float* __restrict__ Bw,
    const float* __restrict__ bias, const float* __restrict__ resid,
    float* __restrict__ C, int N, int K, int m0, int n0) {
    __shared__ alignas(16) float As[16][128];
    __shared__ alignas(16) float Bs[16][128];

    const int t = threadIdx.x;
    const int tx = t & 15, ty = t >> 4;

    unsigned long long acc[4][8] = {};

    // Loader indexing
    const int arow = t >> 1, akq = (t & 1) * 8;     // A: 128 rows x 16 k
    const float* aptr = A + (size_t)(m0 + arow) * K + akq;

    // B loader (two layouts)
    const int bkk = t >> 4, bn4 = (t & 15) * 8;     // !TRANSB: 16 k x 128 n
    const int brow = t >> 1, bkq = (t & 1) * 8;     // TRANSB: 128 n x 16 k
    const float* bptr;
    bool bvalid = true;
    if (!TRANSB) {
        bptr = Bw + (size_t)bkk * N + n0 + bn4;
    } else {
        bvalid = (n0 + brow) < N;
        bptr = Bw + (size_t)(bvalid ? (n0 + brow) : 0) * K + bkq;
    }

    float4 ra0, ra1, rb0, rb1;
    // Prefetch tile 0
    ra0 = *(const float4*)(aptr);
    ra1 = *(const float4*)(aptr + 4);
    if (!TRANSB) {
        rb0 = *(const float4*)(bptr);
        rb1 = *(const float4*)(bptr + 4);
    } else {
        rb0 = rb1 = make_float4(0.f, 0.f, 0.f, 0.f);
        if (bvalid) { rb0 = *(const float4*)(bptr); rb1 = *(const float4*)(bptr + 4); }
    }
    // Store tile 0
    {
        As[akq + 0][arow] = ra0.x; As[akq + 1][arow] = ra0.y;
        As[akq + 2][arow] = ra0.z; As[akq + 3][arow] = ra0.w;
        As[akq + 4][arow] = ra1.x; As[akq + 5][arow] = ra1.y;
        As[akq + 6][arow] = ra1.z; As[akq + 7][arow] = ra1.w;
        if (!TRANSB) {
            *(float4*)&Bs[bkk][bn4] = rb0;
            *(float4*)&Bs[bkk][bn4 + 4] = rb1;
        } else {
            Bs[bkq + 0][brow] = rb0.x; Bs[bkq + 1][brow] = rb0.y;
            Bs[bkq + 2][brow] = rb0.z; Bs[bkq + 3][brow] = rb0.w;
            Bs[bkq + 4][brow] = rb1.x; Bs[bkq + 5][brow] = rb1.y;
            Bs[bkq + 6][brow] = rb1.z; Bs[bkq + 7][brow] = rb1.w;
        }
    }

    for (int k0 = 0; k0 < K; k0 += 16) {
        __syncthreads();
        bool more = (k0 + 16) < K;
        if (more) {   // prefetch next tile into registers
            aptr += 16;
            ra0 = *(const float4*)(aptr);
            ra1 = *(const float4*)(aptr + 4);
            if (!TRANSB) {
                bptr += (size_t)16 * N;
                rb0 = *(const float4*)(bptr);
                rb1 = *(const float4*)(bptr + 4);
            } else {
                bptr += 16;
                if (bvalid) { rb0 = *(const float4*)(bptr); rb1 = *(const float4*)(bptr + 4); }
            }
        }
        // Compute on resident tile
#pragma unroll
        for (int kk = 0; kk < 16; kk++) {
            unsigned long long a2[4];
#pragma unroll
            for (int i = 0; i < 4; i++)
                a2[i] = *(const unsigned long long*)&As[kk][ty * 8 + 2 * i];
            float4 bv0 = *(const float4*)&Bs[kk][tx * 8];
            float4 bv1 = *(const float4*)&Bs[kk][tx * 8 + 4];
            unsigned long long bb[8];
            bb[0] = pack2(bv0.x); bb[1] = pack2(bv0.y);
            bb[2] = pack2(bv0.z); bb[3] = pack2(bv0.w);
            bb[4] = pack2(bv1.x); bb[5] = pack2(bv1.y);
            bb[6] = pack2(bv1.z); bb[7] = pack2(bv1.w);
#pragma unroll
            for (int i = 0; i < 4; i++)
#pragma unroll
                for (int j = 0; j < 8; j++)
                    ffma2(acc[i][j], a2[i], bb[j]);
        }
        __syncthreads();
        if (more) {   // commit prefetched tile
            As[akq + 0][arow] = ra0.x; As[akq + 1][arow] = ra0.y;
            As[akq + 2][arow] = ra0.z; As[akq + 3][arow] = ra0.w;
            As[akq + 4][arow] = ra1.x; As[akq + 5][arow] = ra1.y;
            As[akq + 6][arow] = ra1.z; As[akq + 7][arow] = ra1.w;
            if (!TRANSB) {
                *(float4*)&Bs[bkk][bn4] = rb0;
                *(float4*)&Bs[bkk][bn4 + 4] = rb1;
            } else {
                Bs[bkq + 0][brow] = rb0.x; Bs[bkq + 1][brow] = rb0.y;
                Bs[bkq + 2][brow] = rb0.z; Bs[bkq + 3][brow] = rb0.w;
                Bs[bkq + 4][brow] = rb1.x; Bs[bkq + 5][brow] = rb1.y;
                Bs[bkq + 6][brow] = rb1.z; Bs[bkq + 7][brow] = rb1.w;
            }
        }
    }

    // Epilogue
    float bcol[8];
#pragma unroll
    for (int j = 0; j < 8; j++) {
        int n = n0 + tx * 8 + j;
        bcol[j] = (bias && (!TRANSB || n < N)) ? bias[n] : 0.f;
    }
#pragma unroll
    for (int i = 0; i < 4; i++) {
        float f0[8], f1[8];
#pragma unroll
        for (int j = 0; j < 8; j++) {
            float2 p = unpack2(acc[i][j]);
            f0[j] = p.x + bcol[j];
            f1[j] = p.y + bcol[j];
            if (GELU) {
                f0[j] = 0.5f * f0[j] * (1.f + erff(f0[j] * 0.70710678118654752f));
                f1[j] = 0.5f * f1[j] * (1.f + erff(f1[j] * 0.70710678118654752f));
            }
        }
        int m = m0 + ty * 8 + 2 * i;
#pragma unroll
        for (int r = 0; r < 2; r++) {
            float* f = r ? f1 : f0;
            int row = m + r;
            size_t off = (size_t)row * N + n0 + tx * 8;
            if (resid) {
#pragma unroll
                for (int j = 0; j < 8; j++) f[j] += resid[off + j];
            }
            if (!TRANSB) {
                // N multiple of 128, row base 16B-aligned -> vector stores
                *(float4*)(C + off)     = make_float4(f[0], f[1], f[2], f[3]);
                *(float4*)(C + off + 4) = make_float4(f[4], f[5], f[6], f[7]);
            } else {
                // N may be odd (50257): scalar guarded stores only
#pragma unroll
                for (int j = 0; j < 8; j++)
                    if (n0 + tx * 8 + j < N) C[off + j] = f[j];
            }
        }
    }
}

template <bool TRANSB, bool GELU>
__global__ __launch_bounds__(256)
void gemm_kernel(const float* __restrict__ A, const float* __restrict__ Bw,
                 const float* __restrict__ bias, const float* __restrict__ resid,
                 float* __restrict__ C, int N, int K) {
    int m0, n0;
    if (TRANSB) {   // lm_head: M-tiles fast => concurrent CTAs share B tiles
        m0 = blockIdx.x * 128;
        n0 = blockIdx.y * 128;
    } else {
        n0 = blockIdx.x * 128;
        m0 = blockIdx.y * 128;
    }
    gemm_core<TRANSB, GELU>(A, Bw, bias, resid, C, N, K, m0, n0);
}

// Fused QKV: blockIdx.z selects weight/bias/output. Grid (2, 32, 3) = 192 CTAs.
__global__ __launch_bounds__(256)
void qkv_kernel(const float* __restrict__ A,
                const float* __restrict__ W0, const float* __restrict__ W1,
                const float* __restrict__ W2,
                const float* __restrict__ c0, const float* __restrict__ c1,
                const float* __restrict__ c2,
                float* __restrict__ o0, float* __restrict__ o1,
                float* __restrict__ o2) {
    int z = blockIdx.z;
    const float* Bw = (z == 0) ? W0 : (z == 1) ? W1 : W2;
    const float* bi = (z == 0) ? c0 : (z == 1) ? c1 : c2;
    float* C        = (z == 0) ? o0 : (z == 1) ? o1 : o2;
    gemm_core<false, false>(A, Bw, bi, nullptr, C,
                            CD, CD, blockIdx.y * 128, blockIdx.x * 128);
}

// ----------------------------------------------------------------------------
// Flash-style causal attention. Grid (S/64, B*H), 256 threads.
// ----------------------------------------------------------------------------
constexpr int ATTN_SMEM = (64 * 64 + 64 * 65 + 64 * 64 + 64 * 64) * 4;  // 65792 B

__global__ __launch_bounds__(256)
void attn_kernel(const float* __restrict__ Q, const float* __restrict__ Km,
                 const float* __restrict__ Vm, float* __restrict__ O) {
    extern __shared__ float smem[];
    float* Qs = smem;             // [64][64]
    float* Ks = Qs + 64 * 64;     // [64][65]
    float* Vs = Ks + 64 * 65;     // [64][64]
    float* Ps = Vs + 64 * 64;     // [64][64]
    __shared__ float sm_m[64], sm_l[64], sm_f[64];

    int t = threadIdx.x;
    int sx = t & 15, sy = t >> 4;
    int bh = blockIdx.y;
    int b = bh >> 2, h = bh & 3;
    size_t base = (size_t)b * CS * CD + (size_t)h * CHD;
    int q0 = blockIdx.x * 64;

    for (int x = t; x < 64 * 16; x += 256) {
        int r = x >> 4, d4 = x & 15;
        *(float4*)&Qs[r * 64 + d4 * 4] =
            *(const float4*)(Q + base + (size_t)(q0 + r) * CD + d4 * 4);
    }
    if (t < 64) { sm_m[t] = -1e30f; sm_l[t] = 0.f; }

    float acc[4][4] = {};
    int row = t >> 2, sub = t & 3;

    for (int kt = 0; kt <= (int)blockIdx.x; kt++) {
        int k0 = kt * 64;
        __syncthreads();
        for (int x = t; x < 64 * 16; x += 256) {
            int r = x >> 4, d4 = x & 15;
            float4 kv = *(const float4*)(Km + base + (size_t)(k0 + r) * CD + d4 * 4);
            Ks[r * 65 + d4 * 4 + 0] = kv.x; Ks[r * 65 + d4 * 4 + 1] = kv.y;
            Ks[r * 65 + d4 * 4 + 2] = kv.z; Ks[r * 65 + d4 * 4 + 3] = kv.w;
            *(float4*)&Vs[r * 64 + d4 * 4] =
                *(const float4*)(Vm + base + (size_t)(k0 + r) * CD + d4 * 4);
        }
        __syncthreads();

        float scr[4][4] = {};
#pragma unroll
        for (int d4 = 0; d4 < 16; d4++) {
            float4 a[4];
#pragma unroll
            for (int i = 0; i < 4; i++)
                a[i] = *(const float4*)&Qs[(sy * 4 + i) * 64 + d4 * 4];
#pragma unroll
            for (int j = 0; j < 4; j++) {
                const float* kr = &Ks[(sx * 4 + j) * 65 + d4 * 4];
                float b0 = kr[0], b1 = kr[1], b2 = kr[2], b3 = kr[3];
#pragma unroll
                for (int i = 0; i < 4; i++)
                    scr[i][j] += a[i].x * b0 + a[i].y * b1 + a[i].z * b2 + a[i].w * b3;
            }
        }
        bool diag = (kt == (int)blockIdx.x);
#pragma unroll
        for (int i = 0; i < 4; i++)
#pragma unroll
            for (int j = 0; j < 4; j++) {
                float s = scr[i][j] * 0.125f;
                if (diag && (sx * 4 + j) > (sy * 4 + i)) s = -1e30f;
                Ps[(sy * 4 + i) * 64 + sx * 4 + j] = s;
            }
        __syncthreads();

        {
            float mprev = sm_m[row];
            float tmax = -1e30f;
#pragma unroll
            for (int kk = 0; kk < 16; kk++)
                tmax = fmaxf(tmax, Ps[row * 64 + sub * 16 + kk]);
            tmax = fmaxf(tmax, __shfl_xor_sync(0xffffffffu, tmax, 1));
            tmax = fmaxf(tmax, __shfl_xor_sync(0xffffffffu, tmax, 2));
            float mnew = fmaxf(mprev, tmax);
            float psum = 0.f;
#pragma unroll
            for (int kk = 0; kk < 16; kk++) {
                float p = __expf(Ps[row * 64 + sub * 16 + kk] - mnew);
                Ps[row * 64 + sub * 16 + kk] = p;
                psum += p;
            }
            psum += __shfl_xor_sync(0xffffffffu, psum, 1);
            psum += __shfl_xor_sync(0xffffffffu, psum, 2);
            if (sub == 0) {
                float fr = __expf(mprev - mnew);
                sm_f[row] = fr;
                sm_m[row] = mnew;
                sm_l[row] = sm_l[row] * fr + psum;
            }
        }
        __syncthreads();

#pragma unroll
        for (int i = 0; i < 4; i++) {
            float fr = sm_f[sy * 4 + i];
#pragma unroll
            for (int j = 0; j < 4; j++) acc[i][j] *= fr;
        }
#pragma unroll 4
        for (int kk = 0; kk < 64; kk++) {
            float a[4];
#pragma unroll
            for (int i = 0; i < 4; i++) a[i] = Ps[(sy * 4 + i) * 64 + kk];
            float4 bv = *(const float4*)&Vs[kk * 64 + sx * 4];
#pragma unroll
            for (int i = 0; i < 4; i++) {
                acc[i][0] += a[i] * bv.x; acc[i][1] += a[i] * bv.y;
                acc[i][2] += a[i] * bv.z; acc[i][3] += a[i] * bv.w;
            }
        }
    }

#pragma unroll
    for (int i = 0; i < 4; i++) {
        int qg = q0 + sy * 4 + i;
        float inv = 1.f / sm_l[sy * 4 + i];
#pragma unroll
        for (int j = 0; j < 4; j++)
            O[base + (size_t)qg * CD + sx * 4 + j] = acc[i][j] * inv;
    }
}

// ----------------------------------------------------------------------------
// Orchestration
// ----------------------------------------------------------------------------
extern "C" void kernel_launch(void* const* d_in, const int* in_sizes, int n_in,
                              void* d_out, int out_size) {
    const int*   ids  = (const int*)d_in[0];
    const float* tok  = (const float*)d_in[1];
    const float* pos  = (const float*)d_in[2];
    const float* Wq   = (const float*)d_in[3];
    const float* bq   = (const float*)d_in[4];
    const float* Wk   = (const float*)d_in[5];
    const float* bk   = (const float*)d_in[6];
    const float* Wv   = (const float*)d_in[7];
    const float* bv   = (const float*)d_in[8];
    const float* Wo   = (const float*)d_in[9];
    const float* bo   = (const float*)d_in[10];
    const float* ln1s = (const float*)d_in[11];
    const float* ln1b = (const float*)d_in[12];
    const float* ln2s = (const float*)d_in[13];
    const float* ln2b = (const float*)d_in[14];
    const float* W1   = (const float*)d_in[15];
    const float* b1   = (const float*)d_in[16];
    const float* W2   = (const float*)d_in[17];
    const float* b2   = (const float*)d_in[18];
    const float* lnfs = (const float*)d_in[19];
    const float* lnfb = (const float*)d_in[20];
    float* out = (float*)d_out;

    float *h, *n, *q, *k, *v, *att, *mlp;
    cudaGetSymbolAddress((void**)&h,   g_h);
    cudaGetSymbolAddress((void**)&n,   g_n);
    cudaGetSymbolAddress((void**)&q,   g_q);
    cudaGetSymbolAddress((void**)&k,   g_k);
    cudaGetSymbolAddress((void**)&v,   g_v);
    cudaGetSymbolAddress((void**)&att, g_att);
    cudaGetSymbolAddress((void**)&mlp, g_mlp);

    cudaFuncSetAttribute(attn_kernel,
                         cudaFuncAttributeMaxDynamicSharedMemorySize, ATTN_SMEM);

    dim3 lnb(32, 8);
    embed_kernel<<<CM, CD>>>(ids, tok, pos, h);

    for (int l = 0; l < CL; l++) {
        size_t wofs  = (size_t)l * CD * CD;
        size_t bofs  = (size_t)l * CD;
        size_t w1ofs = (size_t)l * CD * CFF;
        size_t b1ofs = (size_t)l * CFF;
        size_t w2ofs = (size_t)l * CFF * CD;

        ln_kernel<<<CM / 8, lnb>>>(h, ln1s + bofs, ln1b + bofs, n);
        qkv_kernel<<<dim3(CD / 128, CM / 128, 3), 256>>>(
            n, Wq + wofs, Wk + wofs, Wv + wofs,
            bq + bofs, bk + bofs, bv + bofs, q, k, v);

        attn_kernel<<<dim3(CS / 64, CB * CH), 256, ATTN_SMEM>>>(q, k, v, att);

        gemm_kernel<false, false><<<dim3(CD / 128, CM / 128), 256>>>(
            att, Wo + wofs, bo + bofs, h, h, CD, CD);

        ln_kernel<<<CM / 8, lnb>>>(h, ln2s + bofs, ln2b + bofs, n);
        gemm_kernel<false, true><<<dim3(CFF / 128, CM / 128), 256>>>(
            n, W1 + w1ofs, b1 + b1ofs, nullptr, mlp, CFF, CD);
        gemm_kernel<false, false><<<dim3(CD / 128, CM / 128), 256>>>(
            mlp, W2 + w2ofs, b2 + bofs, h, h, CD, CFF);
    }

    ln_kernel<<<CM / 8, lnb>>>(h, lnfs, lnfb, n);
    gemm_kernel<true, false><<<dim3(CM / 128, (CV + 127) / 128), 256>>>(
        n, tok, nullptr, nullptr, out, CV, CD);
}

// round 5
// speedup vs baseline: 1.9242x; 1.5782x over previous
#include <cuda_runtime.h>
#include <cuda_bf16.h>
#include <math.h>
#include <stdint.h>

// Problem constants
constexpr int CB = 2, CS = 2048, CD = 256, CH = 4, CL = 4, CV = 50257, CHD = 64;
constexpr int CM = CB * CS;      // 4096 rows
constexpr int CFF = 4 * CD;      // 1024

// ----------------------------------------------------------------------------
// Scratch (static device globals — no allocation inside kernel_launch)
// ----------------------------------------------------------------------------
__device__ float g_h[CM * CD];
__device__ float g_n[CM * CD];
__device__ float g_q[CM * CD];
__device__ float g_k[CM * CD];
__device__ float g_v[CM * CD];
__device__ float g_att[CM * CD];
__device__ float g_mlp[CM * CFF];

// ----------------------------------------------------------------------------
// Helpers
// ----------------------------------------------------------------------------
__device__ __forceinline__ uint32_t smem_u32(const void* p) {
    uint32_t a;
    asm("{ .reg .u64 t; cvta.to.shared.u64 t, %1; cvt.u32.u64 %0, t; }"
        : "=r"(a) : "l"(p));
    return a;
}

__device__ __forceinline__ void ldsm4(uint32_t* r, uint32_t addr) {
    asm volatile("ldmatrix.sync.aligned.m8n8.x4.shared.b16 {%0,%1,%2,%3}, [%4];"
                 : "=r"(r[0]), "=r"(r[1]), "=r"(r[2]), "=r"(r[3]) : "r"(addr));
}
__device__ __forceinline__ void ldsm4t(uint32_t* r, uint32_t addr) {
    asm volatile("ldmatrix.sync.aligned.m8n8.x4.trans.shared.b16 {%0,%1,%2,%3}, [%4];"
                 : "=r"(r[0]), "=r"(r[1]), "=r"(r[2]), "=r"(r[3]) : "r"(addr));
}
__device__ __forceinline__ void mma16816(float* c, const uint32_t* a, const uint32_t* b) {
    asm volatile("mma.sync.aligned.m16n8k16.row.col.f32.bf16.bf16.f32 "
                 "{%0,%1,%2,%3}, {%4,%5,%6,%7}, {%8,%9}, {%0,%1,%2,%3};"
                 : "+f"(c[0]), "+f"(c[1]), "+f"(c[2]), "+f"(c[3])
                 : "r"(a[0]), "r"(a[1]), "r"(a[2]), "r"(a[3]),
                   "r"(b[0]), "r"(b[1]));
}

// Split 2 fp32 -> packed bf16x2 hi + lo (memory order: x in low half, y in high)
__device__ __forceinline__ void split2(float x, float y, uint32_t& h, uint32_t& l) {
    asm("cvt.rn.bf16x2.f32 %0, %1, %2;" : "=r"(h) : "f"(y), "f"(x));
    float hx = __uint_as_float(h << 16);
    float hy = __uint_as_float(h & 0xFFFF0000u);
    float lx = x - hx, ly = y - hy;
    asm("cvt.rn.bf16x2.f32 %0, %1, %2;" : "=r"(l) : "f"(ly), "f"(lx));
}
__device__ __forceinline__ void stage4(__nv_bfloat16* hiP, __nv_bfloat16* loP, float4 v) {
    uint32_t h0, l0, h1, l1;
    split2(v.x, v.y, h0, l0);
    split2(v.z, v.w, h1, l1);
    *(uint2*)hiP = make_uint2(h0, h1);
    *(uint2*)loP = make_uint2(l0, l1);
}

// ----------------------------------------------------------------------------
// HMMA split-bf16 GEMM core. 128(M)x128(N) tile, BK=32, 256 threads (8 warps,
// 2x4 layout; each warp 64x32 via m16n8k16). 3-term: AhBh + AlBh + AhBl.
// TRANSB=false: B is (K,N) row-major (weights). TRANSB=true: B is (N,K) (lm_head).
// ----------------------------------------------------------------------------
template <bool TRANSB, bool GELU>
__device__ __forceinline__ void hmma_core(
    const float* __restrict__ A, const float* __restrict__ Bw,
    const float* __restrict__ bias, const float* __restrict__ resid,
    float* __restrict__ C, int N, int K, int m0, int n0) {
    constexpr int PA = 40;   // row pitch (bf16 elems) for A and TRANSB-B tiles (80B)
    constexpr int PB = 136;  // row pitch for normal-B tiles (272B)
    __shared__ alignas(16) __nv_bfloat16 sAh[128 * PA];
    __shared__ alignas(16) __nv_bfloat16 sAl[128 * PA];
    __shared__ alignas(16) __nv_bfloat16 sBh[128 * PA];   // >= 32*PB too
    __shared__ alignas(16) __nv_bfloat16 sBl[128 * PA];

    const int t = threadIdx.x;
    const int lane = t & 31, wid = t >> 5;
    const int wm = wid & 1, wn = wid >> 1;

    // Staging: A tile 128 rows x 32 k; thread -> row t>>1, 16 consecutive k.
    const int ar = t >> 1, akq = (t & 1) * 16;
    const float* aptr = A + (size_t)(m0 + ar) * K + akq;

    // B staging
    const int bkr = t >> 3, bnq = (t & 7) * 16;   // normal: 32 k-rows x 128 n
    const float* bptr;
    bool bok = true;
    if (!TRANSB) {
        bptr = Bw + (size_t)bkr * N + n0 + bnq;
    } else {
        bok = (n0 + ar) < N;
        bptr = Bw + (size_t)(bok ? (n0 + ar) : 0) * K + akq;
    }

    float4 pa[4], pb[4];
#pragma unroll
    for (int q = 0; q < 4; q++) pa[q] = *(const float4*)(aptr + q * 4);
#pragma unroll
    for (int q = 0; q < 4; q++)
        pb[q] = bok ? *(const float4*)(bptr + q * 4) : make_float4(0.f, 0.f, 0.f, 0.f);

    auto commit = [&]() {
#pragma unroll
        for (int q = 0; q < 4; q++)
            stage4(&sAh[ar * PA + akq + q * 4], &sAl[ar * PA + akq + q * 4], pa[q]);
#pragma unroll
        for (int q = 0; q < 4; q++) {
            int off = TRANSB ? (ar * PA + akq + q * 4) : (bkr * PB + bnq + q * 4);
            stage4(&sBh[off], &sBl[off], pb[q]);
        }
    };
    commit();

    const uint32_t AhU = smem_u32(sAh), AlU = smem_u32(sAl);
    const uint32_t BhU = smem_u32(sBh), BlU = smem_u32(sBl);
    // ldmatrix per-lane base offsets
    const uint32_t aoff =
        (uint32_t)((wm * 64 + (lane & 7) + ((lane >> 3) & 1) * 8) * (PA * 2) +
                   ((lane >> 4) * 8) * 2);
    uint32_t boff;
    if (!TRANSB)
        boff = (uint32_t)(((lane & 7) + ((lane >> 3) & 1) * 8) * (PB * 2) +
                          (wn * 32 + (lane >> 4) * 8) * 2);
    else
        boff = (uint32_t)((wn * 32 + (lane & 7) + (lane >> 4) * 8) * (PA * 2) +
                          (((lane >> 3) & 1) * 8) * 2);

    float acc[4][4][4] = {};

    for (int k0 = 0; k0 < K; k0 += 32) {
        __syncthreads();
        const bool more = (k0 + 32) < K;
        if (more) {
            aptr += 32;
#pragma unroll
            for (int q = 0; q < 4; q++) pa[q] = *(const float4*)(aptr + q * 4);
            if (!TRANSB) bptr += (size_t)32 * N; else bptr += 32;
#pragma unroll
            for (int q = 0; q < 4; q++)
                pb[q] = bok ? *(const float4*)(bptr + q * 4) : make_float4(0.f, 0.f, 0.f, 0.f);
        }
#pragma unroll
        for (int ks = 0; ks < 2; ks++) {
            uint32_t ah[4][4], al[4][4], bh[2][4], bl[2][4];
#pragma unroll
            for (int mi = 0; mi < 4; mi++) {
                ldsm4(ah[mi], AhU + aoff + mi * (16 * PA * 2) + ks * 32);
                ldsm4(al[mi], AlU + aoff + mi * (16 * PA * 2) + ks * 32);
            }
#pragma unroll
            for (int n2 = 0; n2 < 2; n2++) {
                if (!TRANSB) {
                    ldsm4t(bh[n2], BhU + boff + n2 * 32 + ks * (16 * PB * 2));
                    ldsm4t(bl[n2], BlU + boff + n2 * 32 + ks * (16 * PB * 2));
                } else {
                    ldsm4(bh[n2], BhU + boff + n2 * (16 * PA * 2) + ks * 32);
                    ldsm4(bl[n2], BlU + boff + n2 * (16 * PA * 2) + ks * 32);
                }
            }
#pragma unroll
            for (int mi = 0; mi < 4; mi++)
#pragma unroll
                for (int ni = 0; ni < 4; ni++) {
                    const uint32_t* bhp = &bh[ni >> 1][(ni & 1) * 2];
                    const uint32_t* blp = &bl[ni >> 1][(ni & 1) * 2];
                    mma16816(acc[mi][ni], ah[mi], bhp);
                    mma16816(acc[mi][ni], al[mi], bhp);
                    mma16816(acc[mi][ni], ah[mi], blp);
                }
        }
        __syncthreads();
        if (more) commit();
    }

    // Epilogue. c0,c1 -> (row g, col 2c,2c+1); c2,c3 -> (row g+8).
#pragma unroll
    for (int mi = 0; mi < 4; mi++) {
        const int r0 = m0 + wm * 64 + mi * 16 + (lane >> 2);
#pragma unroll
        for (int ni = 0; ni < 4; ni++) {
            const int col = n0 + wn * 32 + ni * 8 + (lane & 3) * 2;
            float v0 = acc[mi][ni][0], v1 = acc[mi][ni][1];
            float v2 = acc[mi][ni][2], v3 = acc[mi][ni][3];
            if (bias) {
                float b0 = (!TRANSB || col < N) ? bias[col] : 0.f;
                float b1 = (!TRANSB || col + 1 < N) ? bias[col + 1] : 0.f;
                v0 += b0; v1 += b1; v2 += b0; v3 += b1;
            }
            if (GELU) {
                v0 = 0.5f * v0 * (1.f + erff(v0 * 0.70710678118654752f));
                v1 = 0.5f * v1 * (1.f + erff(v1 * 0.70710678118654752f));
                v2 = 0.5f * v2 * (1.f + erff(v2 * 0.70710678118654752f));
                v3 = 0.5f * v3 * (1.f + erff(v3 * 0.70710678118654752f));
            }
            size_t o0 = (size_t)r0 * N + col;
            size_t o1 = o0 + (size_t)8 * N;
            if (!TRANSB) {
                if (resid) {
                    float2 rr0 = *(const float2*)(resid + o0);
                    float2 rr1 = *(const float2*)(resid + o1);
                    v0 += rr0.x; v1 += rr0.y; v2 += rr1.x; v3 += rr1.y;
                }
                *(float2*)(C + o0) = make_float2(v0, v1);
                *(float2*)(C + o1) = make_float2(v2, v3);
            } else {
                if (col < N)     { C[o0] = v0; C[o1] = v2; }
                if (col + 1 < N) { C[o0 + 1] = v1; C[o1 + 1] = v3; }
            }
        }
    }
}

template <bool GELU>
__global__ __launch_bounds__(256)
void hgemm_kernel(const float* __restrict__ A, const float* __restrict__ Bw,
                  const float* __restrict__ bias, const float* __restrict__ resid,
                  float* __restrict__ C, int N, int K) {
    hmma_core<false, GELU>(A, Bw, bias, resid, C, N, K,
                           blockIdx.y * 128, blockIdx.x * 128);
}

// lm_head: out = A @ tok^T, M-tiles on fast grid axis (B tiles shared via L2)
__global__ __launch_bounds__(256)
void lmhead_kernel(const float* __restrict__ A, const float* __restrict__ tok,
                   float* __restrict__ out) {
    hmma_core<true, false>(A, tok, nullptr, nullptr, out, CV, CD,
                           blockIdx.x * 128, blockIdx.y * 128);
}

// Fused QKV: blockIdx.z selects weight/bias/output. Grid (2, 32, 3) = 192 CTAs.
__global__ __launch_bounds__(256)
void qkv_kernel(const float* __restrict__ A,
                const float* __restrict__ W0, const float* __restrict__ W1,
                const float* __restrict__ W2,
                const float* __restrict__ c0, const float* __restrict__ c1,
                const float* __restrict__ c2,
                float* __restrict__ o0, float* __restrict__ o1,
                float* __restrict__ o2) {
    int z = blockIdx.z;
    const float* Bw = (z == 0) ? W0 : (z == 1) ? W1 : W2;
    const float* bi = (z == 0) ? c0 : (z == 1) ? c1 : c2;
    float* C        = (z == 0) ? o0 : (z == 1) ? o1 : o2;
    hmma_core<false, false>(A, Bw, bi, nullptr, C, CD, CD,
                            blockIdx.y * 128, blockIdx.x * 128);
}

// ----------------------------------------------------------------------------
// Embedding
// ----------------------------------------------------------------------------
__global__ void embed_kernel(const int* __restrict__ ids,
                             const float* __restrict__ tok,
                             const float* __restrict__ pos,
                             float* __restrict__ h) {
    int i = blockIdx.x;
    int d = threadIdx.x;
    int s = i & (CS - 1);
    h[(size_t)i * CD + d] = tok[(size_t)ids[i] * CD + d] + pos[(size_t)s * CD + d];
}

// ----------------------------------------------------------------------------
// LayerNorm: one warp per row
// ----------------------------------------------------------------------------
__global__ void ln_kernel(const float* __restrict__ x,
                          const float* __restrict__ sc,
                          const float* __restrict__ bi,
                          float* __restrict__ y) {
    int row = blockIdx.x * 8 + threadIdx.y;
    int lane = threadIdx.x;
    const float* xr = x + (size_t)row * CD;
    float v[8];
    float sum = 0.f, sq = 0.f;
#pragma unroll
    for (int j = 0; j < 8; j++) {
        v[j] = xr[lane + 32 * j];
        sum += v[j];
        sq += v[j] * v[j];
    }
#pragma unroll
    for (int o = 16; o > 0; o >>= 1) {
        sum += __shfl_xor_sync(0xffffffffu, sum, o);
        sq  += __shfl_xor_sync(0xffffffffu, sq, o);
    }
    float mean = sum * (1.f / CD);
    float var  = sq * (1.f / CD) - mean * mean;
    float inv  = rsqrtf(var + 1e-5f);
    float* yr = y + (size_t)row * CD;
#pragma unroll
    for (int j = 0; j < 8; j++) {
        int c = lane + 32 * j;
        yr[c] = (v[j] - mean) * inv * sc[c] + bi[c];
    }
}

// ----------------------------------------------------------------------------
// Flash-style causal attention. Grid (S/64, B*H), 256 threads.
// ----------------------------------------------------------------------------
constexpr int ATTN_SMEM = (64 * 64 + 64 * 65 + 64 * 64 + 64 * 64) * 4;  // 65792 B

__global__ __launch_bounds__(256)
void attn_kernel(const float* __restrict__ Q, const float* __restrict__ Km,
                 const float* __restrict__ Vm, float* __restrict__ O) {
    extern __shared__ float smem[];
    float* Qs = smem;
    float* Ks = Qs + 64 * 64;
    float* Vs = Ks + 64 * 65;
    float* Ps = Vs + 64 * 64;
    __shared__ float sm_m[64], sm_l[64], sm_f[64];

    int t = threadIdx.x;
    int sx = t & 15, sy = t >> 4;
    int bh = blockIdx.y;
    int b = bh >> 2, h = bh & 3;
    size_t base = (size_t)b * CS * CD + (size_t)h * CHD;
    int q0 = blockIdx.x * 64;

    for (int x = t; x < 64 * 16; x += 256) {
        int r = x >> 4, d4 = x & 15;
        *(float4*)&Qs[r * 64 + d4 * 4] =
            *(const float4*)(Q + base + (size_t)(q0 + r) * CD + d4 * 4);
    }
    if (t < 64) { sm_m[t] = -1e30f; sm_l[t] = 0.f; }

    float acc[4][4] = {};
    int row = t >> 2, sub = t & 3;

    for (int kt = 0; kt <= (int)blockIdx.x; kt++) {
        int k0 = kt * 64;
        __syncthreads();
        for (int x = t; x < 64 * 16; x += 256) {
            int r = x >> 4, d4 = x & 15;
            float4 kv = *(const float4*)(Km + base + (size_t)(k0 + r) * CD + d4 * 4);
            Ks[r * 65 + d4 * 4 + 0] = kv.x; Ks[r * 65 + d4 * 4 + 1] = kv.y;
            Ks[r * 65 + d4 * 4 + 2] = kv.z; Ks[r * 65 + d4 * 4 + 3] = kv.w;
            *(float4*)&Vs[r * 64 + d4 * 4] =
                *(const float4*)(Vm + base + (size_t)(k0 + r) * CD + d4 * 4);
        }
        __syncthreads();

        float scr[4][4] = {};
#pragma unroll
        for (int d4 = 0; d4 < 16; d4++) {
            float4 a[4];
#pragma unroll
            for (int i = 0; i < 4; i++)
                a[i] = *(const float4*)&Qs[(sy * 4 + i) * 64 + d4 * 4];
#pragma unroll
            for (int j = 0; j < 4; j++) {
                const float* kr = &Ks[(sx * 4 + j) * 65 + d4 * 4];
                float b0 = kr[0], b1 = kr[1], b2 = kr[2], b3 = kr[3];
#pragma unroll
                for (int i = 0; i < 4; i++)
                    scr[i][j] += a[i].x * b0 + a[i].y * b1 + a[i].z * b2 + a[i].w * b3;
            }
        }
        bool diag = (kt == (int)blockIdx.x);
#pragma unroll
        for (int i = 0; i < 4; i++)
#pragma unroll
            for (int j = 0; j < 4; j++) {
                float s = scr[i][j] * 0.125f;
                if (diag && (sx * 4 + j) > (sy * 4 + i)) s = -1e30f;
                Ps[(sy * 4 + i) * 64 + sx * 4 + j] = s;
            }
        __syncthreads();

        {
            float mprev = sm_m[row];
            float tmax = -1e30f;
#pragma unroll
            for (int kk = 0; kk < 16; kk++)
                tmax = fmaxf(tmax, Ps[row * 64 + sub * 16 + kk]);
            tmax = fmaxf(tmax, __shfl_xor_sync(0xffffffffu, tmax, 1));
            tmax = fmaxf(tmax, __shfl_xor_sync(0xffffffffu, tmax, 2));
            float mnew = fmaxf(mprev, tmax);
            float psum = 0.f;
#pragma unroll
            for (int kk = 0; kk < 16; kk++) {
                float p = __expf(Ps[row * 64 + sub * 16 + kk] - mnew);
                Ps[row * 64 + sub * 16 + kk] = p;
                psum += p;
            }
            psum += __shfl_xor_sync(0xffffffffu, psum, 1);
            psum += __shfl_xor_sync(0xffffffffu, psum, 2);
            if (sub == 0) {
                float fr = __expf(mprev - mnew);
                sm_f[row] = fr;
                sm_m[row] = mnew;
                sm_l[row] = sm_l[row] * fr + psum;
            }
        }
        __syncthreads();

#pragma unroll
        for (int i = 0; i < 4; i++) {
            float fr = sm_f[sy * 4 + i];
#pragma unroll
            for (int j = 0; j < 4; j++) acc[i][j] *= fr;
        }
#pragma unroll 4
        for (int kk = 0; kk < 64; kk++) {
            float a[4];
#pragma unroll
            for (int i = 0; i < 4; i++) a[i] = Ps[(sy * 4 + i) * 64 + kk];
            float4 bv = *(const float4*)&Vs[kk * 64 + sx * 4];
#pragma unroll
            for (int i = 0; i < 4; i++) {
                acc[i][0] += a[i] * bv.x; acc[i][1] += a[i] * bv.y;
                acc[i][2] += a[i] * bv.z; acc[i][3] += a[i] * bv.w;
            }
        }
    }

#pragma unroll
    for (int i = 0; i < 4; i++) {
        int qg = q0 + sy * 4 + i;
        float inv = 1.f / sm_l[sy * 4 + i];
#pragma unroll
        for (int j = 0; j < 4; j++)
            O[base + (size_t)qg * CD + sx * 4 + j] = acc[i][j] * inv;
    }
}

// ----------------------------------------------------------------------------
// Orchestration
// ----------------------------------------------------------------------------
extern "C" void kernel_launch(void* const* d_in, const int* in_sizes, int n_in,
                              void* d_out, int out_size) {
    const int*   ids  = (const int*)d_in[0];
    const float* tok  = (const float*)d_in[1];
    const float* pos  = (const float*)d_in[2];
    const float* Wq   = (const float*)d_in[3];
    const float* bq   = (const float*)d_in[4];
    const float* Wk   = (const float*)d_in[5];
    const float* bk   = (const float*)d_in[6];
    const float* Wv   = (const float*)d_in[7];
    const float* bv   = (const float*)d_in[8];
    const float* Wo   = (const float*)d_in[9];
    const float* bo   = (const float*)d_in[10];
    const float* ln1s = (const float*)d_in[11];
    const float* ln1b = (const float*)d_in[12];
    const float* ln2s = (const float*)d_in[13];
    const float* ln2b = (const float*)d_in[14];
    const float* W1   = (const float*)d_in[15];
    const float* b1   = (const float*)d_in[16];
    const float* W2   = (const float*)d_in[17];
    const float* b2   = (const float*)d_in[18];
    const float* lnfs = (const float*)d_in[19];
    const float* lnfb = (const float*)d_in[20];
    float* out = (float*)d_out;

    float *h, *n, *q, *k, *v, *att, *mlp;
    cudaGetSymbolAddress((void**)&h,   g_h);
    cudaGetSymbolAddress((void**)&n,   g_n);
    cudaGetSymbolAddress((void**)&q,   g_q);
    cudaGetSymbolAddress((void**)&k,   g_k);
    cudaGetSymbolAddress((void**)&v,   g_v);
    cudaGetSymbolAddress((void**)&att, g_att);
    cudaGetSymbolAddress((void**)&mlp, g_mlp);

    cudaFuncSetAttribute(attn_kernel,
                         cudaFuncAttributeMaxDynamicSharedMemorySize, ATTN_SMEM);

    dim3 lnb(32, 8);
    embed_kernel<<<CM, CD>>>(ids, tok, pos, h);

    for (int l = 0; l < CL; l++) {
        size_t wofs  = (size_t)l * CD * CD;
        size_t bofs  = (size_t)l * CD;
        size_t w1ofs = (size_t)l * CD * CFF;
        size_t b1ofs = (size_t)l * CFF;
        size_t w2ofs = (size_t)l * CFF * CD;

        ln_kernel<<<CM / 8, lnb>>>(h, ln1s + bofs, ln1b + bofs, n);
        qkv_kernel<<<dim3(CD / 128, CM / 128, 3), 256>>>(
            n, Wq + wofs, Wk + wofs, Wv + wofs,
            bq + bofs, bk + bofs, bv + bofs, q, k, v);

        attn_kernel<<<dim3(CS / 64, CB * CH), 256, ATTN_SMEM>>>(q, k, v, att);

        hgemm_kernel<false><<<dim3(CD / 128, CM / 128), 256>>>(
            att, Wo + wofs, bo + bofs, h, h, CD, CD);

        ln_kernel<<<CM / 8, lnb>>>(h, ln2s + bofs, ln2b + bofs, n);
        hgemm_kernel<true><<<dim3(CFF / 128, CM / 128), 256>>>(
            n, W1 + w1ofs, b1 + b1ofs, nullptr, mlp, CFF, CD);
        hgemm_kernel<false><<<dim3(CD / 128, CM / 128), 256>>>(
            mlp, W2 + w2ofs, b2 + bofs, h, h, CD, CFF);
    }

    ln_kernel<<<CM / 8, lnb>>>(h, lnfs, lnfb, n);
    lmhead_kernel<<<dim3(CM / 128, (CV + 127) / 128), 256>>>(n, tok, out);
}

// round 6
// speedup vs baseline: 2.6746x; 1.3899x over previous
#include <cuda_runtime.h>
#include <cuda_bf16.h>
#include <math.h>
#include <stdint.h>

// Problem constants
constexpr int CB = 2, CS = 2048, CD = 256, CH = 4, CL = 4, CV = 50257, CHD = 64;
constexpr int CM = CB * CS;      // 4096 rows
constexpr int CFF = 4 * CD;      // 1024

// ----------------------------------------------------------------------------
// Scratch (static device globals — no allocation inside kernel_launch)
// ----------------------------------------------------------------------------
__device__ float g_h[CM * CD];
__device__ float g_n[CM * CD];
__device__ float g_att[CM * CD];
__device__ float g_mlp[CM * CFF];
// Split-bf16 Q/K/V (written by qkv_kernel epilogue)
__device__ __nv_bfloat16 g_qh[CM * CD];
__device__ __nv_bfloat16 g_ql[CM * CD];
__device__ __nv_bfloat16 g_kh[CM * CD];
__device__ __nv_bfloat16 g_kl[CM * CD];
__device__ __nv_bfloat16 g_vh[CM * CD];
__device__ __nv_bfloat16 g_vl[CM * CD];

// ----------------------------------------------------------------------------
// Helpers
// ----------------------------------------------------------------------------
__device__ __forceinline__ uint32_t smem_u32(const void* p) {
    uint32_t a;
    asm("{ .reg .u64 t; cvta.to.shared.u64 t, %1; cvt.u32.u64 %0, t; }"
        : "=r"(a) : "l"(p));
    return a;
}
__device__ __forceinline__ void ldsm4(uint32_t* r, uint32_t addr) {
    asm volatile("ldmatrix.sync.aligned.m8n8.x4.shared.b16 {%0,%1,%2,%3}, [%4];"
                 : "=r"(r[0]), "=r"(r[1]), "=r"(r[2]), "=r"(r[3]) : "r"(addr));
}
__device__ __forceinline__ void ldsm4t(uint32_t* r, uint32_t addr) {
    asm volatile("ldmatrix.sync.aligned.m8n8.x4.trans.shared.b16 {%0,%1,%2,%3}, [%4];"
                 : "=r"(r[0]), "=r"(r[1]), "=r"(r[2]), "=r"(r[3]) : "r"(addr));
}
__device__ __forceinline__ void mma16816(float* c, const uint32_t* a, const uint32_t* b) {
    asm volatile("mma.sync.aligned.m16n8k16.row.col.f32.bf16.bf16.f32 "
                 "{%0,%1,%2,%3}, {%4,%5,%6,%7}, {%8,%9}, {%0,%1,%2,%3};"
                 : "+f"(c[0]), "+f"(c[1]), "+f"(c[2]), "+f"(c[3])
                 : "r"(a[0]), "r"(a[1]), "r"(a[2]), "r"(a[3]),
                   "r"(b[0]), "r"(b[1]));
}
// Split 2 fp32 -> packed bf16x2 hi + lo (x low half, y high half)
__device__ __forceinline__ void split2(float x, float y, uint32_t& h, uint32_t& l) {
    asm("cvt.rn.bf16x2.f32 %0, %1, %2;" : "=r"(h) : "f"(y), "f"(x));
    float hx = __uint_as_float(h << 16);
    float hy = __uint_as_float(h & 0xFFFF0000u);
    float lx = x - hx, ly = y - hy;
    asm("cvt.rn.bf16x2.f32 %0, %1, %2;" : "=r"(l) : "f"(ly), "f"(lx));
}
__device__ __forceinline__ void stage4(__nv_bfloat16* hiP, __nv_bfloat16* loP, float4 v) {
    uint32_t h0, l0, h1, l1;
    split2(v.x, v.y, h0, l0);
    split2(v.z, v.w, h1, l1);
    *(uint2*)hiP = make_uint2(h0, h1);
    *(uint2*)loP = make_uint2(l0, l1);
}
// cp.async
__device__ __forceinline__ void cp16(uint32_t dst, const void* src) {
    asm volatile("cp.async.ca.shared.global [%0], [%1], 16;" :: "r"(dst), "l"(src));
}
__device__ __forceinline__ void cp_commit() {
    asm volatile("cp.async.commit_group;" ::: "memory");
}
template <int N>
__device__ __forceinline__ void cp_wait() {
    asm volatile("cp.async.wait_group %0;" :: "n"(N) : "memory");
}

// ----------------------------------------------------------------------------
// HMMA split-bf16 GEMM core (unchanged mainloop from round 5).
// SPLIT=true: epilogue writes bf16 hi/lo instead of fp32 C.
// ----------------------------------------------------------------------------
template <bool TRANSB, bool GELU, bool SPLIT>
__device__ __forceinline__ void hmma_core(
    const float* __restrict__ A, const float* __restrict__ Bw,
    const float* __restrict__ bias, const float* __restrict__ resid,
    float* __restrict__ C, __nv_bfloat16* __restrict__ Oh,
    __nv_bfloat16* __restrict__ Ol, int N, int K, int m0, int n0) {
    constexpr int PA = 40;
    constexpr int PB = 136;
    __shared__ alignas(16) __nv_bfloat16 sAh[128 * PA];
    __shared__ alignas(16) __nv_bfloat16 sAl[128 * PA];
    __shared__ alignas(16) __nv_bfloat16 sBh[128 * PA];
    __shared__ alignas(16) __nv_bfloat16 sBl[128 * PA];

    const int t = threadIdx.x;
    const int lane = t & 31, wid = t >> 5;
    const int wm = wid & 1, wn = wid >> 1;

    const int ar = t >> 1, akq = (t & 1) * 16;
    const float* aptr = A + (size_t)(m0 + ar) * K + akq;

    const int bkr = t >> 3, bnq = (t & 7) * 16;
    const float* bptr;
    bool bok = true;
    if (!TRANSB) {
        bptr = Bw + (size_t)bkr * N + n0 + bnq;
    } else {
        bok = (n0 + ar) < N;
        bptr = Bw + (size_t)(bok ? (n0 + ar) : 0) * K + akq;
    }

    float4 pa[4], pb[4];
#pragma unroll
    for (int q = 0; q < 4; q++) pa[q] = *(const float4*)(aptr + q * 4);
#pragma unroll
    for (int q = 0; q < 4; q++)
        pb[q] = bok ? *(const float4*)(bptr + q * 4) : make_float4(0.f, 0.f, 0.f, 0.f);

    auto commit = [&]() {
#pragma unroll
        for (int q = 0; q < 4; q++)
            stage4(&sAh[ar * PA + akq + q * 4], &sAl[ar * PA + akq + q * 4], pa[q]);
#pragma unroll
        for (int q = 0; q < 4; q++) {
            int off = TRANSB ? (ar * PA + akq + q * 4) : (bkr * PB + bnq + q * 4);
            stage4(&sBh[off], &sBl[off], pb[q]);
        }
    };
    commit();

    const uint32_t AhU = smem_u32(sAh), AlU = smem_u32(sAl);
    const uint32_t BhU = smem_u32(sBh), BlU = smem_u32(sBl);
    const uint32_t aoff =
        (uint32_t)((wm * 64 + (lane & 7) + ((lane >> 3) & 1) * 8) * (PA * 2) +
                   ((lane >> 4) * 8) * 2);
    uint32_t boff;
    if (!TRANSB)
        boff = (uint32_t)(((lane & 7) + ((lane >> 3) & 1) * 8) * (PB * 2) +
                          (wn * 32 + (lane >> 4) * 8) * 2);
    else
        boff = (uint32_t)((wn * 32 + (lane & 7) + (lane >> 4) * 8) * (PA * 2) +
                          (((lane >> 3) & 1) * 8) * 2);

    float acc[4][4][4] = {};

    for (int k0 = 0; k0 < K; k0 += 32) {
        __syncthreads();
        const bool more = (k0 + 32) < K;
        if (more) {
            aptr += 32;
#pragma unroll
            for (int q = 0; q < 4; q++) pa[q] = *(const float4*)(aptr + q * 4);
            if (!TRANSB) bptr += (size_t)32 * N; else bptr += 32;
#pragma unroll
            for (int q = 0; q < 4; q++)
                pb[q] = bok ? *(const float4*)(bptr + q * 4) : make_float4(0.f, 0.f, 0.f, 0.f);
        }
#pragma unroll
        for (int ks = 0; ks < 2; ks++) {
            uint32_t ah[4][4], al[4][4], bh[2][4], bl[2][4];
#pragma unroll
            for (int mi = 0; mi < 4; mi++) {
                ldsm4(ah[mi], AhU + aoff + mi * (16 * PA * 2) + ks * 32);
                ldsm4(al[mi], AlU + aoff + mi * (16 * PA * 2) + ks * 32);
            }
#pragma unroll
            for (int n2 = 0; n2 < 2; n2++) {
                if (!TRANSB) {
                    ldsm4t(bh[n2], BhU + boff + n2 * 32 + ks * (16 * PB * 2));
                    ldsm4t(bl[n2], BlU + boff + n2 * 32 + ks * (16 * PB * 2));
                } else {
                    ldsm4(bh[n2], BhU + boff + n2 * (16 * PA * 2) + ks * 32);
                    ldsm4(bl[n2], BlU + boff + n2 * (16 * PA * 2) + ks * 32);
                }
            }
#pragma unroll
            for (int mi = 0; mi < 4; mi++)
#pragma unroll
                for (int ni = 0; ni < 4; ni++) {
                    const uint32_t* bhp = &bh[ni >> 1][(ni & 1) * 2];
                    const uint32_t* blp = &bl[ni >> 1][(ni & 1) * 2];
                    mma16816(acc[mi][ni], ah[mi], bhp);
                    mma16816(acc[mi][ni], al[mi], bhp);
                    mma16816(acc[mi][ni], ah[mi], blp);
                }
        }
        __syncthreads();
        if (more) commit();
    }

#pragma unroll
    for (int mi = 0; mi < 4; mi++) {
        const int r0 = m0 + wm * 64 + mi * 16 + (lane >> 2);
#pragma unroll
        for (int ni = 0; ni < 4; ni++) {
            const int col = n0 + wn * 32 + ni * 8 + (lane & 3) * 2;
            float v0 = acc[mi][ni][0], v1 = acc[mi][ni][1];
            float v2 = acc[mi][ni][2], v3 = acc[mi][ni][3];
            if (bias) {
                float b0 = (!TRANSB || col < N) ? bias[col] : 0.f;
                float b1 = (!TRANSB || col + 1 < N) ? bias[col + 1] : 0.f;
                v0 += b0; v1 += b1; v2 += b0; v3 += b1;
            }
            if (GELU) {
                v0 = 0.5f * v0 * (1.f + erff(v0 * 0.70710678118654752f));
                v1 = 0.5f * v1 * (1.f + erff(v1 * 0.70710678118654752f));
                v2 = 0.5f * v2 * (1.f + erff(v2 * 0.70710678118654752f));
                v3 = 0.5f * v3 * (1.f + erff(v3 * 0.70710678118654752f));
            }
            size_t o0 = (size_t)r0 * N + col;
            size_t o1 = o0 + (size_t)8 * N;
            if (SPLIT) {
                uint32_t hh, ll;
                split2(v0, v1, hh, ll);
                *(uint32_t*)(Oh + o0) = hh;
                *(uint32_t*)(Ol + o0) = ll;
                split2(v2, v3, hh, ll);
                *(uint32_t*)(Oh + o1) = hh;
                *(uint32_t*)(Ol + o1) = ll;
            } else if (!TRANSB) {
                if (resid) {
                    float2 rr0 = *(const float2*)(resid + o0);
                    float2 rr1 = *(const float2*)(resid + o1);
                    v0 += rr0.x; v1 += rr0.y; v2 += rr1.x; v3 += rr1.y;
                }
                *(float2*)(C + o0) = make_float2(v0, v1);
                *(float2*)(C + o1) = make_float2(v2, v3);
            } else {
                if (col < N)     { C[o0] = v0; C[o1] = v2; }
                if (col + 1 < N) { C[o0 + 1] = v1; C[o1 + 1] = v3; }
            }
        }
    }
}

template <bool GELU>
__global__ __launch_bounds__(256)
void hgemm_kernel(const float* __restrict__ A, const float* __restrict__ Bw,
                  const float* __restrict__ bias, const float* __restrict__ resid,
                  float* __restrict__ C, int N, int K) {
    hmma_core<false, GELU, false>(A, Bw, bias, resid, C, nullptr, nullptr, N, K,
                                  blockIdx.y * 128, blockIdx.x * 128);
}

__global__ __launch_bounds__(256)
void lmhead_kernel(const float* __restrict__ A, const float* __restrict__ tok,
                   float* __restrict__ out) {
    hmma_core<true, false, false>(A, tok, nullptr, nullptr, out, nullptr, nullptr,
                                  CV, CD, blockIdx.x * 128, blockIdx.y * 128);
}

// Fused QKV with split-bf16 outputs. Grid (2, 32, 3).
__global__ __launch_bounds__(256)
void qkv_kernel(const float* __restrict__ A,
                const float* __restrict__ W0, const float* __restrict__ W1,
                const float* __restrict__ W2,
                const float* __restrict__ c0, const float* __restrict__ c1,
                const float* __restrict__ c2,
                __nv_bfloat16* __restrict__ qh, __nv_bfloat16* __restrict__ ql,
                __nv_bfloat16* __restrict__ kh, __nv_bfloat16* __restrict__ kl,
                __nv_bfloat16* __restrict__ vh, __nv_bfloat16* __restrict__ vl) {
    int z = blockIdx.z;
    const float* Bw = (z == 0) ? W0 : (z == 1) ? W1 : W2;
    const float* bi = (z == 0) ? c0 : (z == 1) ? c1 : c2;
    __nv_bfloat16* oh = (z == 0) ? qh : (z == 1) ? kh : vh;
    __nv_bfloat16* ol = (z == 0) ? ql : (z == 1) ? kl : vl;
    hmma_core<false, false, true>(A, Bw, bi, nullptr, nullptr, oh, ol, CD, CD,
                                  blockIdx.y * 128, blockIdx.x * 128);
}

// ----------------------------------------------------------------------------
// HMMA flash attention. Grid (S/64, B*H), 128 threads (4 warps x 16 q-rows).
// Split-bf16 3-term for both S = Q@K^T and O += P@V. cp.async double-buffered KV.
// ----------------------------------------------------------------------------
constexpr int AP = 72;                          // bf16 row pitch (144 B)
constexpr int TILEB = 64 * AP * 2;              // 9216 B per 64x64 bf16 tile
constexpr int ATTN_SMEM = 10 * TILEB;           // Q hi/lo + 2 KV bufs x 4 tiles

__global__ __launch_bounds__(128)
void attn_kernel(const __nv_bfloat16* __restrict__ Qh,
                 const __nv_bfloat16* __restrict__ Ql,
                 const __nv_bfloat16* __restrict__ Kh,
                 const __nv_bfloat16* __restrict__ Kl,
                 const __nv_bfloat16* __restrict__ Vh,
                 const __nv_bfloat16* __restrict__ Vl,
                 float* __restrict__ O) {
    extern __shared__ char sm[];
    const uint32_t smU = smem_u32(sm);
    const uint32_t qU = smU;                    // Q hi at 0, Q lo at +TILEB
    const uint32_t kvU = smU + 2 * TILEB;       // [buf][Kh,Kl,Vh,Vl]

    const int t = threadIdx.x;
    const int lane = t & 31, w = t >> 5;
    const int bx = blockIdx.x;
    const int bh = blockIdx.y;
    const int b = bh >> 2, h = bh & 3;
    const size_t base = (size_t)b * CS * CD + (size_t)h * CHD;
    const int q0 = bx * 64;

    // ---- issue KV tile 0 (cp.async) ----
    auto load_kv = [&](int buf, int kt) {
        const int k0 = kt * 64;
#pragma unroll
        for (int a = 0; a < 4; a++) {
            const __nv_bfloat16* src =
                ((a == 0) ? Kh : (a == 1) ? Kl : (a == 2) ? Vh : Vl) +
                base + (size_t)k0 * CD;
            const uint32_t dbase = kvU + (buf * 4 + a) * TILEB;
#pragma unroll
            for (int i = 0; i < 4; i++) {
                int e = t + i * 128;            // 0..511
                int row = e >> 3, c = e & 7;
                cp16(dbase + row * (AP * 2) + c * 16, src + (size_t)row * CD + c * 8);
            }
        }
        cp_commit();
    };
    load_kv(0, 0);

    // ---- stage Q (hi/lo), then load Q fragments into registers ----
#pragma unroll
    for (int a = 0; a < 2; a++) {
        const __nv_bfloat16* src = (a ? Ql : Qh) + base + (size_t)q0 * CD;
        char* dst = sm + a * TILEB;
#pragma unroll
        for (int i = 0; i < 4; i++) {
            int e = t + i * 128;
            int row = e >> 3, c = e & 7;
            *(uint4*)(dst + row * (AP * 2) + c * 16) =
                *(const uint4*)(src + (size_t)row * CD + c * 8);
        }
    }
    __syncthreads();

    uint32_t qfh[4][4], qfl[4][4];
    {
        const uint32_t aoff =
            (uint32_t)((w * 16 + (lane & 7) + ((lane >> 3) & 1) * 8) * (AP * 2) +
                       (lane >> 4) * 16);
#pragma unroll
        for (int ks = 0; ks < 4; ks++) {
            ldsm4(qfh[ks], qU + aoff + ks * 32);
            ldsm4(qfl[ks], qU + TILEB + aoff + ks * 32);
        }
    }

    float acc[8][4] = {};
    float m_0 = -1e30f, m_1 = -1e30f, l_0 = 0.f, l_1 = 0.f;
    const int rl0 = w * 16 + (lane >> 2);

    for (int kt = 0; kt <= bx; kt++) {
        const int buf = kt & 1;
        const bool more = kt < bx;
        if (more) load_kv(buf ^ 1, kt + 1);
        if (more) cp_wait<1>(); else cp_wait<0>();
        __syncthreads();

        const uint32_t kBufH = kvU + (buf * 4 + 0) * TILEB;
        const uint32_t kBufL = kvU + (buf * 4 + 1) * TILEB;
        const uint32_t vBufH = kvU + (buf * 4 + 2) * TILEB;
        const uint32_t vBufL = kvU + (buf * 4 + 3) * TILEB;

        // ---- S = Q @ K^T (3-term split) ----
        float st[8][4] = {};
#pragma unroll
        for (int ks = 0; ks < 4; ks++) {
            uint32_t kh4[4][4], kl4[4][4];
#pragma unroll
            for (int nt = 0; nt < 4; nt++) {
                uint32_t ko =
                    (uint32_t)((nt * 16 + (lane & 7) + (lane >> 4) * 8) * (AP * 2) +
                               ((lane >> 3) & 1) * 16 + ks * 32);
                ldsm4(kh4[nt], kBufH + ko);
                ldsm4(kl4[nt], kBufL + ko);
            }
#pragma unroll
            for (int ni = 0; ni < 8; ni++) {
                const uint32_t* bhp = &kh4[ni >> 1][(ni & 1) * 2];
                const uint32_t* blp = &kl4[ni >> 1][(ni & 1) * 2];
                mma16816(st[ni], qfh[ks], bhp);
                mma16816(st[ni], qfl[ks], bhp);
                mma16816(st[ni], qfh[ks], blp);
            }
        }

        // ---- scale + causal mask ----
#pragma unroll
        for (int ni = 0; ni < 8; ni++) {
#pragma unroll
            for (int e = 0; e < 4; e++) st[ni][e] *= 0.125f;
        }
        if (kt == bx) {
#pragma unroll
            for (int ni = 0; ni < 8; ni++) {
                int cb = ni * 8 + (lane & 3) * 2;
                if (cb > rl0)         st[ni][0] = -1e30f;
                if (cb + 1 > rl0)     st[ni][1] = -1e30f;
                if (cb > rl0 + 8)     st[ni][2] = -1e30f;
                if (cb + 1 > rl0 + 8) st[ni][3] = -1e30f;
            }
        }

        // ---- online softmax ----
        float t0 = -1e30f, t1 = -1e30f;
#pragma unroll
        for (int ni = 0; ni < 8; ni++) {
            t0 = fmaxf(t0, fmaxf(st[ni][0], st[ni][1]));
            t1 = fmaxf(t1, fmaxf(st[ni][2], st[ni][3]));
        }
        t0 = fmaxf(t0, __shfl_xor_sync(0xffffffffu, t0, 1));
        t0 = fmaxf(t0, __shfl_xor_sync(0xffffffffu, t0, 2));
        t1 = fmaxf(t1, __shfl_xor_sync(0xffffffffu, t1, 1));
        t1 = fmaxf(t1, __shfl_xor_sync(0xffffffffu, t1, 2));
        float mn0 = fmaxf(m_0, t0), mn1 = fmaxf(m_1, t1);
        float fr0 = __expf(m_0 - mn0), fr1 = __expf(m_1 - mn1);
        m_0 = mn0; m_1 = mn1;
        float ps0 = 0.f, ps1 = 0.f;
#pragma unroll
        for (int ni = 0; ni < 8; ni++) {
            float p0 = __expf(st[ni][0] - mn0); st[ni][0] = p0; ps0 += p0;
            float p1 = __expf(st[ni][1] - mn0); st[ni][1] = p1; ps0 += p1;
            float p2 = __expf(st[ni][2] - mn1); st[ni][2] = p2; ps1 += p2;
            float p3 = __expf(st[ni][3] - mn1); st[ni][3] = p3; ps1 += p3;
        }
        ps0 += __shfl_xor_sync(0xffffffffu, ps0, 1);
        ps0 += __shfl_xor_sync(0xffffffffu, ps0, 2);
        ps1 += __shfl_xor_sync(0xffffffffu, ps1, 1);
        ps1 += __shfl_xor_sync(0xffffffffu, ps1, 2);
        l_0 = l_0 * fr0 + ps0;
        l_1 = l_1 * fr1 + ps1;
#pragma unroll
        for (int ni = 0; ni < 8; ni++) {
            acc[ni][0] *= fr0; acc[ni][1] *= fr0;
            acc[ni][2] *= fr1; acc[ni][3] *= fr1;
        }

        // ---- O += P @ V (3-term split) ----
#pragma unroll
        for (int ks = 0; ks < 4; ks++) {
            uint32_t pah[4], pal[4];
            split2(st[2 * ks][0],     st[2 * ks][1],     pah[0], pal[0]);
            split2(st[2 * ks][2],     st[2 * ks][3],     pah[1], pal[1]);
            split2(st[2 * ks + 1][0], st[2 * ks + 1][1], pah[2], pal[2]);
            split2(st[2 * ks + 1][2], st[2 * ks + 1][3], pah[3], pal[3]);
            uint32_t vh4[4][4], vl4[4][4];
#pragma unroll
            for (int vt = 0; vt < 4; vt++) {
                uint32_t vo =
                    (uint32_t)(((lane & 7) + ((lane >> 3) & 1) * 8 + ks * 16) * (AP * 2) +
                               (vt * 16 + (lane >> 4) * 8) * 2);
                ldsm4t(vh4[vt], vBufH + vo);
                ldsm4t(vl4[vt], vBufL + vo);
            }
#pragma unroll
            for (int ni = 0; ni < 8; ni++) {
                const uint32_t* vhp = &vh4[ni >> 1][(ni & 1) * 2];
                const uint32_t* vlp = &vl4[ni >> 1][(ni & 1) * 2];
                mma16816(acc[ni], pah, vhp);
                mma16816(acc[ni], pal, vhp);
                mma16816(acc[ni], pah, vlp);
            }
        }
        __syncthreads();   // done reading buf before it gets refilled
    }

    // ---- epilogue ----
    float i0 = 1.f / l_0, i1 = 1.f / l_1;
    const int r0 = q0 + rl0;
#pragma unroll
    for (int ni = 0; ni < 8; ni++) {
        int col = ni * 8 + (lane & 3) * 2;
        size_t o = base + (size_t)r0 * CD + col;
        *(float2*)(O + o) = make_float2(acc[ni][0] * i0, acc[ni][1] * i0);
        *(float2*)(O + o + (size_t)8 * CD) = make_float2(acc[ni][2] * i1, acc[ni][3] * i1);
    }
}

// ----------------------------------------------------------------------------
// Embedding
// ----------------------------------------------------------------------------
__global__ void embed_kernel(const int* __restrict__ ids,
                             const float* __restrict__ tok,
                             const float* __restrict__ pos,
                             float* __restrict__ h) {
    int i = blockIdx.x;
    int d = threadIdx.x;
    int s = i & (CS - 1);
    h[(size_t)i * CD + d] = tok[(size_t)ids[i] * CD + d] + pos[(size_t)s * CD + d];
}

// ----------------------------------------------------------------------------
// LayerNorm: one warp per row
// ----------------------------------------------------------------------------
__global__ void ln_kernel(const float* __restrict__ x,
                          const float* __restrict__ sc,
                          const float* __restrict__ bi,
                          float* __restrict__ y) {
    int row = blockIdx.x * 8 + threadIdx.y;
    int lane = threadIdx.x;
    const float* xr = x + (size_t)row * CD;
    float v[8];
    float sum = 0.f, sq = 0.f;
#pragma unroll
    for (int j = 0; j < 8; j++) {
        v[j] = xr[lane + 32 * j];
        sum += v[j];
        sq += v[j] * v[j];
    }
#pragma unroll
    for (int o = 16; o > 0; o >>= 1) {
        sum += __shfl_xor_sync(0xffffffffu, sum, o);
        sq  += __shfl_xor_sync(0xffffffffu, sq, o);
    }
    float mean = sum * (1.f / CD);
    float var  = sq * (1.f / CD) - mean * mean;
    float inv  = rsqrtf(var + 1e-5f);
    float* yr = y + (size_t)row * CD;
#pragma unroll
    for (int j = 0; j < 8; j++) {
        int c = lane + 32 * j;
        yr[c] = (v[j] - mean) * inv * sc[c] + bi[c];
    }
}

// ----------------------------------------------------------------------------
// Orchestration
// ----------------------------------------------------------------------------
extern "C" void kernel_launch(void* const* d_in, const int* in_sizes, int n_in,
                              void* d_out, int out_size) {
    const int*   ids  = (const int*)d_in[0];
    const float* tok  = (const float*)d_in[1];
    const float* pos  = (const float*)d_in[2];
    const float* Wq   = (const float*)d_in[3];
    const float* bq   = (const float*)d_in[4];
    const float* Wk   = (const float*)d_in[5];
    const float* bk   = (const float*)d_in[6];
    const float* Wv   = (const float*)d_in[7];
    const float* bv   = (const float*)d_in[8];
    const float* Wo   = (const float*)d_in[9];
    const float* bo   = (const float*)d_in[10];
    const float* ln1s = (const float*)d_in[11];
    const float* ln1b = (const float*)d_in[12];
    const float* ln2s = (const float*)d_in[13];
    const float* ln2b = (const float*)d_in[14];
    const float* W1   = (const float*)d_in[15];
    const float* b1   = (const float*)d_in[16];
    const float* W2   = (const float*)d_in[17];
    const float* b2   = (const float*)d_in[18];
    const float* lnfs = (const float*)d_in[19];
    const float* lnfb = (const float*)d_in[20];
    float* out = (float*)d_out;

    float *h, *n, *att, *mlp;
    __nv_bfloat16 *qh, *ql, *kh, *kl, *vh, *vl;
    cudaGetSymbolAddress((void**)&h,   g_h);
    cudaGetSymbolAddress((void**)&n,   g_n);
    cudaGetSymbolAddress((void**)&att, g_att);
    cudaGetSymbolAddress((void**)&mlp, g_mlp);
    cudaGetSymbolAddress((void**)&qh,  g_qh);
    cudaGetSymbolAddress((void**)&ql,  g_ql);
    cudaGetSymbolAddress((void**)&kh,  g_kh);
    cudaGetSymbolAddress((void**)&kl,  g_kl);
    cudaGetSymbolAddress((void**)&vh,  g_vh);
    cudaGetSymbolAddress((void**)&vl,  g_vl);

    cudaFuncSetAttribute(attn_kernel,
                         cudaFuncAttributeMaxDynamicSharedMemorySize, ATTN_SMEM);

    dim3 lnb(32, 8);
    embed_kernel<<<CM, CD>>>(ids, tok, pos, h);

    for (int l = 0; l < CL; l++) {
        size_t wofs  = (size_t)l * CD * CD;
        size_t bofs  = (size_t)l * CD;
        size_t w1ofs = (size_t)l * CD * CFF;
        size_t b1ofs = (size_t)l * CFF;
        size_t w2ofs = (size_t)l * CFF * CD;

        ln_kernel<<<CM / 8, lnb>>>(h, ln1s + bofs, ln1b + bofs, n);
        qkv_kernel<<<dim3(CD / 128, CM / 128, 3), 256>>>(
            n, Wq + wofs, Wk + wofs, Wv + wofs,
            bq + bofs, bk + bofs, bv + bofs, qh, ql, kh, kl, vh, vl);

        attn_kernel<<<dim3(CS / 64, CB * CH), 128, ATTN_SMEM>>>(
            qh, ql, kh, kl, vh, vl, att);

        hgemm_kernel<false><<<dim3(CD / 128, CM / 128), 256>>>(
            att, Wo + wofs, bo + bofs, h, h, CD, CD);

        ln_kernel<<<CM / 8, lnb>>>(h, ln2s + bofs, ln2b + bofs, n);
        hgemm_kernel<true><<<dim3(CFF / 128, CM / 128), 256>>>(
            n, W1 + w1ofs, b1 + b1ofs, nullptr, mlp, CFF, CD);
        hgemm_kernel<false><<<dim3(CD / 128, CM / 128), 256>>>(
            mlp, W2 + w2ofs, b2 + bofs, h, h, CD, CFF);
    }

    ln_kernel<<<CM / 8, lnb>>>(h, lnfs, lnfb, n);
    lmhead_kernel<<<dim3(CM / 128, (CV + 127) / 128), 256>>>(n, tok, out);
}

// round 7
// speedup vs baseline: 3.0566x; 1.1428x over previous
#include <cuda_runtime.h>
#include <cuda_bf16.h>
#include <math.h>
#include <stdint.h>

typedef __nv_bfloat16 bf16;

// Problem constants
constexpr int CB = 2, CS = 2048, CD = 256, CH = 4, CL = 4, CV = 50257, CHD = 64;
constexpr int CM = CB * CS;      // 4096 rows
constexpr int CFF = 4 * CD;      // 1024

// ----------------------------------------------------------------------------
// Scratch (static device globals — no allocation inside kernel_launch)
// ----------------------------------------------------------------------------
__device__ float g_h[CM * CD];
// Activations, split bf16
__device__ bf16 g_nh[CM * CD],  g_nl[CM * CD];      // LN output
__device__ bf16 g_ath[CM * CD], g_atl[CM * CD];     // attention output
__device__ bf16 g_mh[CM * CFF], g_ml[CM * CFF];     // MLP hidden
__device__ bf16 g_qh[CM * CD], g_ql[CM * CD];
__device__ bf16 g_kh[CM * CD], g_kl[CM * CD];
__device__ bf16 g_vh[CM * CD], g_vl[CM * CD];
// Weights, split bf16 (filled once per launch)
__device__ bf16 g_th[(size_t)CV * CD],  g_tl[(size_t)CV * CD];
__device__ bf16 g_wqh[CL * CD * CD],  g_wql[CL * CD * CD];
__device__ bf16 g_wkh[CL * CD * CD],  g_wkl[CL * CD * CD];
__device__ bf16 g_wvh[CL * CD * CD],  g_wvl[CL * CD * CD];
__device__ bf16 g_woh[CL * CD * CD],  g_wol[CL * CD * CD];
__device__ bf16 g_w1h[CL * CD * CFF], g_w1l[CL * CD * CFF];
__device__ bf16 g_w2h[CL * CD * CFF], g_w2l[CL * CD * CFF];

// ----------------------------------------------------------------------------
// Helpers
// ----------------------------------------------------------------------------
__device__ __forceinline__ uint32_t smem_u32(const void* p) {
    uint32_t a;
    asm("{ .reg .u64 t; cvta.to.shared.u64 t, %1; cvt.u32.u64 %0, t; }"
        : "=r"(a) : "l"(p));
    return a;
}
__device__ __forceinline__ void ldsm4(uint32_t* r, uint32_t addr) {
    asm volatile("ldmatrix.sync.aligned.m8n8.x4.shared.b16 {%0,%1,%2,%3}, [%4];"
                 : "=r"(r[0]), "=r"(r[1]), "=r"(r[2]), "=r"(r[3]) : "r"(addr));
}
__device__ __forceinline__ void ldsm4t(uint32_t* r, uint32_t addr) {
    asm volatile("ldmatrix.sync.aligned.m8n8.x4.trans.shared.b16 {%0,%1,%2,%3}, [%4];"
                 : "=r"(r[0]), "=r"(r[1]), "=r"(r[2]), "=r"(r[3]) : "r"(addr));
}
__device__ __forceinline__ void mma16816(float* c, const uint32_t* a, const uint32_t* b) {
    asm volatile("mma.sync.aligned.m16n8k16.row.col.f32.bf16.bf16.f32 "
                 "{%0,%1,%2,%3}, {%4,%5,%6,%7}, {%8,%9}, {%0,%1,%2,%3};"
                 : "+f"(c[0]), "+f"(c[1]), "+f"(c[2]), "+f"(c[3])
                 : "r"(a[0]), "r"(a[1]), "r"(a[2]), "r"(a[3]),
                   "r"(b[0]), "r"(b[1]));
}
// Split 2 fp32 -> packed bf16x2 hi + lo (x low half, y high half)
__device__ __forceinline__ void split2(float x, float y, uint32_t& h, uint32_t& l) {
    asm("cvt.rn.bf16x2.f32 %0, %1, %2;" : "=r"(h) : "f"(y), "f"(x));
    float hx = __uint_as_float(h << 16);
    float hy = __uint_as_float(h & 0xFFFF0000u);
    float lx = x - hx, ly = y - hy;
    asm("cvt.rn.bf16x2.f32 %0, %1, %2;" : "=r"(l) : "f"(ly), "f"(lx));
}
// cp.async
__device__ __forceinline__ void cp16(uint32_t dst, const void* src) {
    asm volatile("cp.async.ca.shared.global [%0], [%1], 16;" :: "r"(dst), "l"(src));
}
__device__ __forceinline__ void cp_commit() {
    asm volatile("cp.async.commit_group;" ::: "memory");
}
template <int N>
__device__ __forceinline__ void cp_wait() {
    asm volatile("cp.async.wait_group %0;" :: "n"(N) : "memory");
}

// ----------------------------------------------------------------------------
// fp32 -> (bf16 hi, bf16 lo) bulk splitter (runs once per launch for weights)
// ----------------------------------------------------------------------------
__global__ void split_kernel(const float* __restrict__ src,
                             bf16* __restrict__ hi, bf16* __restrict__ lo,
                             size_t npairs) {
    size_t i = (size_t)blockIdx.x * blockDim.x + threadIdx.x;
    if (i >= npairs) return;
    float2 x = *(const float2*)(src + 2 * i);
    uint32_t h, l;
    split2(x.x, x.y, h, l);
    *(uint32_t*)(hi + 2 * i) = h;
    *(uint32_t*)(lo + 2 * i) = l;
}

// ----------------------------------------------------------------------------
// All-bf16 HMMA GEMM core. 128x128 tile, BK=32, 256 thr (8 warps 2x4),
// 2-stage cp.async pipeline, 3-term split: AhBh + AlBh + AhBl.
// TRANSB=false: B (K,N). TRANSB=true: B (N,K) (lm_head, N=50257).
// Dynamic smem: 2 stages x 4 components x 10240 B = 81920 B.
// ----------------------------------------------------------------------------
constexpr int GSLOT = 10240;
constexpr int GEMM_SMEM = 2 * 4 * GSLOT;

template <bool TRANSB, bool GELU, bool SPLIT>
__device__ __forceinline__ void bgemm_core(
    const bf16* __restrict__ Ah, const bf16* __restrict__ Al,
    const bf16* __restrict__ Bh, const bf16* __restrict__ Bl,
    const float* __restrict__ bias, const float* __restrict__ resid,
    float* __restrict__ C, bf16* __restrict__ Oh, bf16* __restrict__ Ol,
    int N, int K, int m0, int n0, char* smbase) {
    const int t = threadIdx.x;
    const int lane = t & 31, wid = t >> 5;
    const int wm = wid & 1, wn = wid >> 1;
    const uint32_t sU = smem_u32(smbase);

    auto slot = [&](int s, int comp) -> uint32_t {
        return sU + (uint32_t)((s * 4 + comp) * GSLOT);
    };

    auto load_tile = [&](int s, int kc) {
        const int k0 = kc * 32;
#pragma unroll
        for (int comp = 0; comp < 2; comp++) {        // A hi / A lo: 128r x 32k
            const bf16* src = comp ? Al : Ah;
            const uint32_t dst = slot(s, comp);
#pragma unroll
            for (int i = 0; i < 2; i++) {
                int e = t + i * 256;
                int row = e >> 2, c = e & 3;
                cp16(dst + row * 80 + c * 16,
                     src + (size_t)(m0 + row) * K + k0 + c * 8);
            }
        }
#pragma unroll
        for (int comp = 2; comp < 4; comp++) {        // B hi / B lo
            const bf16* src = (comp == 2) ? Bh : Bl;
            const uint32_t dst = slot(s, comp);
            if (!TRANSB) {                            // 32k x 128n
#pragma unroll
                for (int i = 0; i < 2; i++) {
                    int e = t + i * 256;
                    int row = e >> 4, c = e & 15;
                    cp16(dst + row * 272 + c * 16,
                         src + (size_t)(k0 + row) * N + n0 + c * 8);
                }
            } else {                                  // 128n x 32k
#pragma unroll
                for (int i = 0; i < 2; i++) {
                    int e = t + i * 256;
                    int row = e >> 2, c = e & 3;
                    int nr = n0 + row;
                    if (nr >= N) nr = 0;              // clamp; masked at store
                    cp16(dst + row * 80 + c * 16,
                         src + (size_t)nr * K + k0 + c * 8);
                }
            }
        }
        cp_commit();
    };

    const uint32_t aoff =
        (uint32_t)((wm * 64 + (lane & 7) + ((lane >> 3) & 1) * 8) * 80 +
                   (lane >> 4) * 16);
    uint32_t boff;
    if (!TRANSB)
        boff = (uint32_t)(((lane & 7) + ((lane >> 3) & 1) * 8) * 272 +
                          (wn * 32 + (lane >> 4) * 8) * 2);
    else
        boff = (uint32_t)((wn * 32 + (lane & 7) + (lane >> 4) * 8) * 80 +
                          ((lane >> 3) & 1) * 16);

    float acc[4][4][4] = {};
    const int KT = K / 32;
    load_tile(0, 0);

    for (int kc = 0; kc < KT; kc++) {
        if (kc + 1 < KT) { load_tile((kc + 1) & 1, kc + 1); cp_wait<1>(); }
        else             { cp_wait<0>(); }
        __syncthreads();
        const int s = kc & 1;
        const uint32_t sAh = slot(s, 0), sAl = slot(s, 1);
        const uint32_t sBh = slot(s, 2), sBl = slot(s, 3);
#pragma unroll
        for (int ks = 0; ks < 2; ks++) {
            uint32_t ah[4][4], al[4][4], bh[2][4], bl[2][4];
#pragma unroll
            for (int mi = 0; mi < 4; mi++) {
                ldsm4(ah[mi], sAh + aoff + mi * (16 * 80) + ks * 32);
                ldsm4(al[mi], sAl + aoff + mi * (16 * 80) + ks * 32);
            }
#pragma unroll
            for (int n2 = 0; n2 < 2; n2++) {
                if (!TRANSB) {
                    ldsm4t(bh[n2], sBh + boff + n2 * 32 + ks * (16 * 272));
                    ldsm4t(bl[n2], sBl + boff + n2 * 32 + ks * (16 * 272));
                } else {
                    ldsm4(bh[n2], sBh + boff + n2 * (16 * 80) + ks * 32);
                    ldsm4(bl[n2], sBl + boff + n2 * (16 * 80) + ks * 32);
                }
            }
#pragma unroll
            for (int mi = 0; mi < 4; mi++)
#pragma unroll
                for (int ni = 0; ni < 4; ni++) {
                    const uint32_t* bhp = &bh[ni >> 1][(ni & 1) * 2];
                    const uint32_t* blp = &bl[ni >> 1][(ni & 1) * 2];
                    mma16816(acc[mi][ni], ah[mi], bhp);
                    mma16816(acc[mi][ni], al[mi], bhp);
                    mma16816(acc[mi][ni], ah[mi], blp);
                }
        }
        __syncthreads();
    }

    // Epilogue
#pragma unroll
    for (int mi = 0; mi < 4; mi++) {
        const int r0 = m0 + wm * 64 + mi * 16 + (lane >> 2);
#pragma unroll
        for (int ni = 0; ni < 4; ni++) {
            const int col = n0 + wn * 32 + ni * 8 + (lane & 3) * 2;
            float v0 = acc[mi][ni][0], v1 = acc[mi][ni][1];
            float v2 = acc[mi][ni][2], v3 = acc[mi][ni][3];
            if (bias) {
                float b0 = (!TRANSB || col < N) ? bias[col] : 0.f;
                float b1 = (!TRANSB || col + 1 < N) ? bias[col + 1] : 0.f;
                v0 += b0; v1 += b1; v2 += b0; v3 += b1;
            }
            if (GELU) {
                v0 = 0.5f * v0 * (1.f + erff(v0 * 0.70710678118654752f));
                v1 = 0.5f * v1 * (1.f + erff(v1 * 0.70710678118654752f));
                v2 = 0.5f * v2 * (1.f + erff(v2 * 0.70710678118654752f));
                v3 = 0.5f * v3 * (1.f + erff(v3 * 0.70710678118654752f));
            }
            size_t o0 = (size_t)r0 * N + col;
            size_t o1 = o0 + (size_t)8 * N;
            if (SPLIT) {
                uint32_t hh, ll;
                split2(v0, v1, hh, ll);
                *(uint32_t*)(Oh + o0) = hh;
                *(uint32_t*)(Ol + o0) = ll;
                split2(v2, v3, hh, ll);
                *(uint32_t*)(Oh + o1) = hh;
                *(uint32_t*)(Ol + o1) = ll;
            } else if (!TRANSB) {
                if (resid) {
                    float2 rr0 = *(const float2*)(resid + o0);
                    float2 rr1 = *(const float2*)(resid + o1);
                    v0 += rr0.x; v1 += rr0.y; v2 += rr1.x; v3 += rr1.y;
                }
                *(float2*)(C + o0) = make_float2(v0, v1);
                *(float2*)(C + o1) = make_float2(v2, v3);
            } else {
                if (col < N)     { C[o0] = v0; C[o1] = v2; }
                if (col + 1 < N) { C[o0 + 1] = v1; C[o1 + 1] = v3; }
            }
        }
    }
}

// GEMM with fp32 output + residual (Wo, W2)
__global__ __launch_bounds__(256)
void gemm_res_kernel(const bf16* __restrict__ Ah, const bf16* __restrict__ Al,
                     const bf16* __restrict__ Bh, const bf16* __restrict__ Bl,
                     const float* __restrict__ bias, const float* __restrict__ resid,
                     float* __restrict__ C, int N, int K) {
    extern __shared__ char sm[];
    bgemm_core<false, false, false>(Ah, Al, Bh, Bl, bias, resid, C,
                                    nullptr, nullptr, N, K,
                                    blockIdx.y * 128, blockIdx.x * 128, sm);
}

// W1: GELU + split-bf16 output
__global__ __launch_bounds__(256)
void gemm_gelu_kernel(const bf16* __restrict__ Ah, const bf16* __restrict__ Al,
                      const bf16* __restrict__ Bh, const bf16* __restrict__ Bl,
                      const float* __restrict__ bias,
                      bf16* __restrict__ Oh, bf16* __restrict__ Ol, int N, int K) {
    extern __shared__ char sm[];
    bgemm_core<false, true, true>(Ah, Al, Bh, Bl, bias, nullptr, nullptr,
                                  Oh, Ol, N, K,
                                  blockIdx.y * 128, blockIdx.x * 128, sm);
}

// QKV fused: z selects weight/bias/output; split-bf16 outputs
__global__ __launch_bounds__(256)
void qkv_kernel(const bf16* __restrict__ Ah, const bf16* __restrict__ Al,
                const bf16* __restrict__ Wh0, const bf16* __restrict__ Wl0,
                const bf16* __restrict__ Wh1, const bf16* __restrict__ Wl1,
                const bf16* __restrict__ Wh2, const bf16* __restrict__ Wl2,
                const float* __restrict__ c0, const float* __restrict__ c1,
                const float* __restrict__ c2,
                bf16* __restrict__ qh, bf16* __restrict__ ql,
                bf16* __restrict__ kh, bf16* __restrict__ kl,
                bf16* __restrict__ vh, bf16* __restrict__ vl) {
    extern __shared__ char sm[];
    int z = blockIdx.z;
    const bf16* Bh = (z == 0) ? Wh0 : (z == 1) ? Wh1 : Wh2;
    const bf16* Bl = (z == 0) ? Wl0 : (z == 1) ? Wl1 : Wl2;
    const float* bi = (z == 0) ? c0 : (z == 1) ? c1 : c2;
    bf16* oh = (z == 0) ? qh : (z == 1) ? kh : vh;
    bf16* ol = (z == 0) ? ql : (z == 1) ? kl : vl;
    bgemm_core<false, false, true>(Ah, Al, Bh, Bl, bi, nullptr, nullptr,
                                   oh, ol, CD, CD,
                                   blockIdx.y * 128, blockIdx.x * 128, sm);
}

// lm_head: out = A @ tok^T, m-fast grid
__global__ __launch_bounds__(256)
void lmhead_kernel(const bf16* __restrict__ Ah, const bf16* __restrict__ Al,
                   const bf16* __restrict__ Th, const bf16* __restrict__ Tl,
                   float* __restrict__ out) {
    extern __shared__ char sm[];
    bgemm_core<true, false, false>(Ah, Al, Th, Tl, nullptr, nullptr, out,
                                   nullptr, nullptr, CV, CD,
                                   blockIdx.x * 128, blockIdx.y * 128, sm);
}

// ----------------------------------------------------------------------------
// HMMA flash attention, causal-folded: grid (16, B*H); CTA bx handles q-tiles
// bx and 31-bx (33 KV tiles each — perfectly balanced). 128 threads.
// ----------------------------------------------------------------------------
constexpr int AP = 72;
constexpr int TILEB = 64 * AP * 2;
constexpr int ATTN_SMEM = 10 * TILEB;

__global__ __launch_bounds__(128)
void attn_kernel(const bf16* __restrict__ Qh, const bf16* __restrict__ Ql,
                 const bf16* __restrict__ Kh, const bf16* __restrict__ Kl,
                 const bf16* __restrict__ Vh, const bf16* __restrict__ Vl,
                 bf16* __restrict__ Ath, bf16* __restrict__ Atl) {
    extern __shared__ char sm[];
    const uint32_t smU = smem_u32(sm);
    const uint32_t qU = smU;
    const uint32_t kvU = smU + 2 * TILEB;

    const int t = threadIdx.x;
    const int lane = t & 31, w = t >> 5;
    const int bh = blockIdx.y;
    const int b = bh >> 2, h = bh & 3;
    const size_t base = (size_t)b * CS * CD + (size_t)h * CHD;

    auto load_kv = [&](int buf, int kt) {
        const int k0 = kt * 64;
#pragma unroll
        for (int a = 0; a < 4; a++) {
            const bf16* src =
                ((a == 0) ? Kh : (a == 1) ? Kl : (a == 2) ? Vh : Vl) +
                base + (size_t)k0 * CD;
            const uint32_t dbase = kvU + (buf * 4 + a) * TILEB;
#pragma unroll
            for (int i = 0; i < 4; i++) {
                int e = t + i * 128;
                int row = e >> 3, c = e & 7;
                cp16(dbase + row * (AP * 2) + c * 16, src + (size_t)row * CD + c * 8);
            }
        }
        cp_commit();
    };

    for (int half = 0; half < 2; half++) {
        const int qt = half ? (31 - (int)blockIdx.x) : (int)blockIdx.x;
        const int q0 = qt * 64;
        __syncthreads();

        load_kv(0, 0);
        // stage Q hi/lo
#pragma unroll
        for (int a = 0; a < 2; a++) {
            const bf16* src = (a ? Ql : Qh) + base + (size_t)q0 * CD;
            char* dst = sm + a * TILEB;
#pragma unroll
            for (int i = 0; i < 4; i++) {
                int e = t + i * 128;
                int row = e >> 3, c = e & 7;
                *(uint4*)(dst + row * (AP * 2) + c * 16) =
                    *(const uint4*)(src + (size_t)row * CD + c * 8);
            }
        }
        __syncthreads();

        uint32_t qfh[4][4], qfl[4][4];
        {
            const uint32_t aoff =
                (uint32_t)((w * 16 + (lane & 7) + ((lane >> 3) & 1) * 8) * (AP * 2) +
                           (lane >> 4) * 16);
#pragma unroll
            for (int ks = 0; ks < 4; ks++) {
                ldsm4(qfh[ks], qU + aoff + ks * 32);
                ldsm4(qfl[ks], qU + TILEB + aoff + ks * 32);
            }
        }

        float acc[8][4] = {};
        float m_0 = -1e30f, m_1 = -1e30f, l_0 = 0.f, l_1 = 0.f;
        const int rl0 = w * 16 + (lane >> 2);

        for (int kt = 0; kt <= qt; kt++) {
            const int buf = kt & 1;
            const bool more = kt < qt;
            if (more) { load_kv(buf ^ 1, kt + 1); cp_wait<1>(); }
            else      { cp_wait<0>(); }
            __syncthreads();

            const uint32_t kBufH = kvU + (buf * 4 + 0) * TILEB;
            const uint32_t kBufL = kvU + (buf * 4 + 1) * TILEB;
            const uint32_t vBufH = kvU + (buf * 4 + 2) * TILEB;
            const uint32_t vBufL = kvU + (buf * 4 + 3) * TILEB;

            float st[8][4] = {};
#pragma unroll
            for (int ks = 0; ks < 4; ks++) {
                uint32_t kh4[4][4], kl4[4][4];
#pragma unroll
                for (int nt = 0; nt < 4; nt++) {
                    uint32_t ko =
                        (uint32_t)((nt * 16 + (lane & 7) + (lane >> 4) * 8) * (AP * 2) +
                                   ((lane >> 3) & 1) * 16 + ks * 32);
                    ldsm4(kh4[nt], kBufH + ko);
                    ldsm4(kl4[nt], kBufL + ko);
                }
#pragma unroll
                for (int ni = 0; ni < 8; ni++) {
                    const uint32_t* bhp = &kh4[ni >> 1][(ni & 1) * 2];
                    const uint32_t* blp = &kl4[ni >> 1][(ni & 1) * 2];
                    mma16816(st[ni], qfh[ks], bhp);
                    mma16816(st[ni], qfl[ks], bhp);
                    mma16816(st[ni], qfh[ks], blp);
                }
            }

#pragma unroll
            for (int ni = 0; ni < 8; ni++)
#pragma unroll
                for (int e = 0; e < 4; e++) st[ni][e] *= 0.125f;
            if (kt == qt) {
#pragma unroll
                for (int ni = 0; ni < 8; ni++) {
                    int cb = ni * 8 + (lane & 3) * 2;
                    if (cb > rl0)         st[ni][0] = -1e30f;
                    if (cb + 1 > rl0)     st[ni][1] = -1e30f;
                    if (cb > rl0 + 8)     st[ni][2] = -1e30f;
                    if (cb + 1 > rl0 + 8) st[ni][3] = -1e30f;
                }
            }

            float t0 = -1e30f, t1 = -1e30f;
#pragma unroll
            for (int ni = 0; ni < 8; ni++) {
                t0 = fmaxf(t0, fmaxf(st[ni][0], st[ni][1]));
                t1 = fmaxf(t1, fmaxf(st[ni][2], st[ni][3]));
            }
            t0 = fmaxf(t0, __shfl_xor_sync(0xffffffffu, t0, 1));
            t0 = fmaxf(t0, __shfl_xor_sync(0xffffffffu, t0, 2));
            t1 = fmaxf(t1, __shfl_xor_sync(0xffffffffu, t1, 1));
            t1 = fmaxf(t1, __shfl_xor_sync(0xffffffffu, t1, 2));
            float mn0 = fmaxf(m_0, t0), mn1 = fmaxf(m_1, t1);
            float fr0 = __expf(m_0 - mn0), fr1 = __expf(m_1 - mn1);
            m_0 = mn0; m_1 = mn1;
            float ps0 = 0.f, ps1 = 0.f;
#pragma unroll
            for (int ni = 0; ni < 8; ni++) {
                float p0 = __expf(st[ni][0] - mn0); st[ni][0] = p0; ps0 += p0;
                float p1 = __expf(st[ni][1] - mn0); st[ni][1] = p1; ps0 += p1;
                float p2 = __expf(st[ni][2] - mn1); st[ni][2] = p2; ps1 += p2;
                float p3 = __expf(st[ni][3] - mn1); st[ni][3] = p3; ps1 += p3;
            }
            ps0 += __shfl_xor_sync(0xffffffffu, ps0, 1);
            ps0 += __shfl_xor_sync(0xffffffffu, ps0, 2);
            ps1 += __shfl_xor_sync(0xffffffffu, ps1, 1);
            ps1 += __shfl_xor_sync(0xffffffffu, ps1, 2);
            l_0 = l_0 * fr0 + ps0;
            l_1 = l_1 * fr1 + ps1;
#pragma unroll
            for (int ni = 0; ni < 8; ni++) {
                acc[ni][0] *= fr0; acc[ni][1] *= fr0;
                acc[ni][2] *= fr1; acc[ni][3] *= fr1;
            }

#pragma unroll
            for (int ks = 0; ks < 4; ks++) {
                uint32_t pah[4], pal[4];
                split2(st[2 * ks][0],     st[2 * ks][1],     pah[0], pal[0]);
                split2(st[2 * ks][2],     st[2 * ks][3],     pah[1], pal[1]);
                split2(st[2 * ks + 1][0], st[2 * ks + 1][1], pah[2], pal[2]);
                split2(st[2 * ks + 1][2], st[2 * ks + 1][3], pah[3], pal[3]);
                uint32_t vh4[4][4], vl4[4][4];
#pragma unroll
                for (int vt = 0; vt < 4; vt++) {
                    uint32_t vo =
                        (uint32_t)(((lane & 7) + ((lane >> 3) & 1) * 8 + ks * 16) * (AP * 2) +
                                   (vt * 16 + (lane >> 4) * 8) * 2);
                    ldsm4t(vh4[vt], vBufH + vo);
                    ldsm4t(vl4[vt], vBufL + vo);
                }
#pragma unroll
                for (int ni = 0; ni < 8; ni++) {
                    const uint32_t* vhp = &vh4[ni >> 1][(ni & 1) * 2];
                    const uint32_t* vlp = &vl4[ni >> 1][(ni & 1) * 2];
                    mma16816(acc[ni], pah, vhp);
                    mma16816(acc[ni], pal, vhp);
                    mma16816(acc[ni], pah, vlp);
                }
            }
            __syncthreads();
        }

        // epilogue: split-bf16 store
        float i0 = 1.f / l_0, i1 = 1.f / l_1;
        const int r0 = q0 + rl0;
#pragma unroll
        for (int ni = 0; ni < 8; ni++) {
            int col = ni * 8 + (lane & 3) * 2;
            size_t o = base + (size_t)r0 * CD + col;
            uint32_t hh, ll;
            split2(acc[ni][0] * i0, acc[ni][1] * i0, hh, ll);
            *(uint32_t*)(Ath + o) = hh;
            *(uint32_t*)(Atl + o) = ll;
            split2(acc[ni][2] * i1, acc[ni][3] * i1, hh, ll);
            *(uint32_t*)(Ath + o + (size_t)8 * CD) = hh;
            *(uint32_t*)(Atl + o + (size_t)8 * CD) = ll;
        }
    }
}

// ----------------------------------------------------------------------------
// Embedding
// ----------------------------------------------------------------------------
__global__ void embed_kernel(const int* __restrict__ ids,
                             const float* __restrict__ tok,
                             const float* __restrict__ pos,
                             float* __restrict__ h) {
    int i = blockIdx.x;
    int d = threadIdx.x;
    int s = i & (CS - 1);
    h[(size_t)i * CD + d] = tok[(size_t)ids[i] * CD + d] + pos[(size_t)s * CD + d];
}

// ----------------------------------------------------------------------------
// LayerNorm -> split-bf16 output
// ----------------------------------------------------------------------------
__global__ void ln_kernel(const float* __restrict__ x,
                          const float* __restrict__ sc,
                          const float* __restrict__ bi,
                          bf16* __restrict__ yh, bf16* __restrict__ yl) {
    int row = blockIdx.x * 8 + threadIdx.y;   // blockDim (32, 8)
    int lane = threadIdx.x;
    const float* xr = x + (size_t)row * CD;
    float v[8];
    float sum = 0.f, sq = 0.f;
#pragma unroll
    for (int j = 0; j < 8; j++) {
        v[j] = xr[lane * 8 + j];              // 8 contiguous per lane
        sum += v[j];
        sq += v[j] * v[j];
    }
#pragma unroll
    for (int o = 16; o > 0; o >>= 1) {
        sum += __shfl_xor_sync(0xffffffffu, sum, o);
        sq  += __shfl_xor_sync(0xffffffffu, sq, o);
    }
    float mean = sum * (1.f / CD);
    float var  = sq * (1.f / CD) - mean * mean;
    float inv  = rsqrtf(var + 1e-5f);
    size_t off = (size_t)row * CD + lane * 8;
    uint32_t hbuf[4], lbuf[4];
#pragma unroll
    for (int j = 0; j < 4; j++) {
        int c = lane * 8 + 2 * j;
        float y0 = (v[2 * j]     - mean) * inv * sc[c]     + bi[c];
        float y1 = (v[2 * j + 1] - mean) * inv * sc[c + 1] + bi[c + 1];
        split2(y0, y1, hbuf[j], lbuf[j]);
    }
    *(uint4*)(yh + off) = make_uint4(hbuf[0], hbuf[1], hbuf[2], hbuf[3]);
    *(uint4*)(yl + off) = make_uint4(lbuf[0], lbuf[1], lbuf[2], lbuf[3]);
}

// ----------------------------------------------------------------------------
// Orchestration
// ----------------------------------------------------------------------------
extern "C" void kernel_launch(void* const* d_in, const int* in_sizes, int n_in,
                              void* d_out, int out_size) {
    const int*   ids  = (const int*)d_in[0];
    const float* tok  = (const float*)d_in[1];
    const float* pos  = (const float*)d_in[2];
    const float* Wq   = (const float*)d_in[3];
    const float* bq   = (const float*)d_in[4];
    const float* Wk   = (const float*)d_in[5];
    const float* bk   = (const float*)d_in[6];
    const float* Wv   = (const float*)d_in[7];
    const float* bv   = (const float*)d_in[8];
    const float* Wo   = (const float*)d_in[9];
    const float* bo   = (const float*)d_in[10];
    const float* ln1s = (const float*)d_in[11];
    const float* ln1b = (const float*)d_in[12];
    const float* ln2s = (const float*)d_in[13];
    const float* ln2b = (const float*)d_in[14];
    const float* W1   = (const float*)d_in[15];
    const float* b1   = (const float*)d_in[16];
    const float* W2   = (const float*)d_in[17];
    const float* b2   = (const float*)d_in[18];
    const float* lnfs = (const float*)d_in[19];
    const float* lnfb = (const float*)d_in[20];
    float* out = (float*)d_out;

    float* h;
    bf16 *nh, *nl, *ath, *atl, *mh, *ml, *qh, *ql, *kh, *kl, *vh, *vl;
    bf16 *th, *tl, *wqh, *wql, *wkh, *wkl, *wvh, *wvl, *woh, *wol;
    bf16 *w1h, *w1l, *w2h, *w2l;
    cudaGetSymbolAddress((void**)&h,   g_h);
    cudaGetSymbolAddress((void**)&nh,  g_nh);   cudaGetSymbolAddress((void**)&nl,  g_nl);
    cudaGetSymbolAddress((void**)&ath, g_ath);  cudaGetSymbolAddress((void**)&atl, g_atl);
    cudaGetSymbolAddress((void**)&mh,  g_mh);   cudaGetSymbolAddress((void**)&ml,  g_ml);
    cudaGetSymbolAddress((void**)&qh,  g_qh);   cudaGetSymbolAddress((void**)&ql,  g_ql);
    cudaGetSymbolAddress((void**)&kh,  g_kh);   cudaGetSymbolAddress((void**)&kl,  g_kl);
    cudaGetSymbolAddress((void**)&vh,  g_vh);   cudaGetSymbolAddress((void**)&vl,  g_vl);
    cudaGetSymbolAddress((void**)&th,  g_th);   cudaGetSymbolAddress((void**)&tl,  g_tl);
    cudaGetSymbolAddress((void**)&wqh, g_wqh);  cudaGetSymbolAddress((void**)&wql, g_wql);
    cudaGetSymbolAddress((void**)&wkh, g_wkh);  cudaGetSymbolAddress((void**)&wkl, g_wkl);
    cudaGetSymbolAddress((void**)&wvh, g_wvh);  cudaGetSymbolAddress((void**)&wvl, g_wvl);
    cudaGetSymbolAddress((void**)&woh, g_woh);  cudaGetSymbolAddress((void**)&wol, g_wol);
    cudaGetSymbolAddress((void**)&w1h, g_w1h);  cudaGetSymbolAddress((void**)&w1l, g_w1l);
    cudaGetSymbolAddress((void**)&w2h, g_w2h);  cudaGetSymbolAddress((void**)&w2l, g_w2l);

    cudaFuncSetAttribute(attn_kernel,
                         cudaFuncAttributeMaxDynamicSharedMemorySize, ATTN_SMEM);
    cudaFuncSetAttribute(gemm_res_kernel,
                         cudaFuncAttributeMaxDynamicSharedMemorySize, GEMM_SMEM);
    cudaFuncSetAttribute(gemm_gelu_kernel,
                         cudaFuncAttributeMaxDynamicSharedMemorySize, GEMM_SMEM);
    cudaFuncSetAttribute(qkv_kernel,
                         cudaFuncAttributeMaxDynamicSharedMemorySize, GEMM_SMEM);
    cudaFuncSetAttribute(lmhead_kernel,
                         cudaFuncAttributeMaxDynamicSharedMemorySize, GEMM_SMEM);

    // One-time weight splits (included in timing; ~64 MB traffic total)
    auto split = [&](const float* s, bf16* hh, bf16* ll, size_t count) {
        size_t np = count / 2;
        split_kernel<<<(unsigned)((np + 255) / 256), 256>>>(s, hh, ll, np);
    };
    split(tok, th, tl, (size_t)CV * CD);
    split(Wq, wqh, wql, (size_t)CL * CD * CD);
    split(Wk, wkh, wkl, (size_t)CL * CD * CD);
    split(Wv, wvh, wvl, (size_t)CL * CD * CD);
    split(Wo, woh, wol, (size_t)CL * CD * CD);
    split(W1, w1h, w1l, (size_t)CL * CD * CFF);
    split(W2, w2h, w2l, (size_t)CL * CD * CFF);

    dim3 lnb(32, 8);
    embed_kernel<<<CM, CD>>>(ids, tok, pos, h);

    for (int l = 0; l < CL; l++) {
        size_t wofs  = (size_t)l * CD * CD;
        size_t bofs  = (size_t)l * CD;
        size_t w1ofs = (size_t)l * CD * CFF;
        size_t b1ofs = (size_t)l * CFF;
        size_t w2ofs = (size_t)l * CFF * CD;

        ln_kernel<<<CM / 8, lnb>>>(h, ln1s + bofs, ln1b + bofs, nh, nl);
        qkv_kernel<<<dim3(CD / 128, CM / 128, 3), 256, GEMM_SMEM>>>(
            nh, nl, wqh + wofs, wql + wofs, wkh + wofs, wkl + wofs,
            wvh + wofs, wvl + wofs, bq + bofs, bk + bofs, bv + bofs,
            qh, ql, kh, kl, vh, vl);

        attn_kernel<<<dim3(16, CB * CH), 128, ATTN_SMEM>>>(
            qh, ql, kh, kl, vh, vl, ath, atl);

        gemm_res_kernel<<<dim3(CD / 128, CM / 128), 256, GEMM_SMEM>>>(
            ath, atl, woh + wofs, wol + wofs, bo + bofs, h, h, CD, CD);

        ln_kernel<<<CM / 8, lnb>>>(h, ln2s + bofs, ln2b + bofs, nh, nl);
        gemm_gelu_kernel<<<dim3(CFF / 128, CM / 128), 256, GEMM_SMEM>>>(
            nh, nl, w1h + w1ofs, w1l + w1ofs, b1 + b1ofs, mh, ml, CFF, CD);
        gemm_res_kernel<<<dim3(CD / 128, CM / 128), 256, GEMM_SMEM>>>(
            mh, ml, w2h + w2ofs, w2l + w2ofs, b2 + bofs, h, h, CD, CFF);
    }

    ln_kernel<<<CM / 8, lnb>>>(h, lnfs, lnfb, nh, nl);
    lmhead_kernel<<<dim3(CM / 128, (CV + 127) / 128), 256, GEMM_SMEM>>>(
        nh, nl, th, tl, out);
}

// round 8
// speedup vs baseline: 3.1407x; 1.0275x over previous
#include <cuda_runtime.h>
#include <cuda_bf16.h>
#include <math.h>
#include <stdint.h>

typedef __nv_bfloat16 bf16;

// Problem constants
constexpr int CB = 2, CS = 2048, CD = 256, CH = 4, CL = 4, CV = 50257, CHD = 64;
constexpr int CM = CB * CS;      // 4096 rows
constexpr int CFF = 4 * CD;      // 1024

// ----------------------------------------------------------------------------
// Scratch (static device globals — no allocation inside kernel_launch)
// ----------------------------------------------------------------------------
__device__ float g_h[CM * CD];
__device__ bf16 g_nh[CM * CD],  g_nl[CM * CD];
__device__ bf16 g_ath[CM * CD], g_atl[CM * CD];
__device__ bf16 g_mh[CM * CFF], g_ml[CM * CFF];
__device__ bf16 g_qh[CM * CD], g_ql[CM * CD];
__device__ bf16 g_kh[CM * CD], g_kl[CM * CD];
__device__ bf16 g_vh[CM * CD], g_vl[CM * CD];
__device__ bf16 g_th[(size_t)CV * CD],  g_tl[(size_t)CV * CD];
__device__ bf16 g_wqh[CL * CD * CD],  g_wql[CL * CD * CD];
__device__ bf16 g_wkh[CL * CD * CD],  g_wkl[CL * CD * CD];
__device__ bf16 g_wvh[CL * CD * CD],  g_wvl[CL * CD * CD];
__device__ bf16 g_woh[CL * CD * CD],  g_wol[CL * CD * CD];
__device__ bf16 g_w1h[CL * CD * CFF], g_w1l[CL * CD * CFF];
__device__ bf16 g_w2h[CL * CD * CFF], g_w2l[CL * CD * CFF];

// ----------------------------------------------------------------------------
// Helpers
// ----------------------------------------------------------------------------
__device__ __forceinline__ uint32_t smem_u32(const void* p) {
    uint32_t a;
    asm("{ .reg .u64 t; cvta.to.shared.u64 t, %1; cvt.u32.u64 %0, t; }"
        : "=r"(a) : "l"(p));
    return a;
}
__device__ __forceinline__ void ldsm4(uint32_t* r, uint32_t addr) {
    asm volatile("ldmatrix.sync.aligned.m8n8.x4.shared.b16 {%0,%1,%2,%3}, [%4];"
                 : "=r"(r[0]), "=r"(r[1]), "=r"(r[2]), "=r"(r[3]) : "r"(addr));
}
__device__ __forceinline__ void ldsm4t(uint32_t* r, uint32_t addr) {
    asm volatile("ldmatrix.sync.aligned.m8n8.x4.trans.shared.b16 {%0,%1,%2,%3}, [%4];"
                 : "=r"(r[0]), "=r"(r[1]), "=r"(r[2]), "=r"(r[3]) : "r"(addr));
}
__device__ __forceinline__ void mma16816(float* c, const uint32_t* a, const uint32_t* b) {
    asm volatile("mma.sync.aligned.m16n8k16.row.col.f32.bf16.bf16.f32 "
                 "{%0,%1,%2,%3}, {%4,%5,%6,%7}, {%8,%9}, {%0,%1,%2,%3};"
                 : "+f"(c[0]), "+f"(c[1]), "+f"(c[2]), "+f"(c[3])
                 : "r"(a[0]), "r"(a[1]), "r"(a[2]), "r"(a[3]),
                   "r"(b[0]), "r"(b[1]));
}
__device__ __forceinline__ void split2(float x, float y, uint32_t& h, uint32_t& l) {
    asm("cvt.rn.bf16x2.f32 %0, %1, %2;" : "=r"(h) : "f"(y), "f"(x));
    float hx = __uint_as_float(h << 16);
    float hy = __uint_as_float(h & 0xFFFF0000u);
    float lx = x - hx, ly = y - hy;
    asm("cvt.rn.bf16x2.f32 %0, %1, %2;" : "=r"(l) : "f"(ly), "f"(lx));
}
__device__ __forceinline__ void cp16(uint32_t dst, const void* src) {
    asm volatile("cp.async.ca.shared.global [%0], [%1], 16;" :: "r"(dst), "l"(src));
}
__device__ __forceinline__ void cp_commit() {
    asm volatile("cp.async.commit_group;" ::: "memory");
}
template <int N>
__device__ __forceinline__ void cp_wait() {
    asm volatile("cp.async.wait_group %0;" :: "n"(N) : "memory");
}

// ----------------------------------------------------------------------------
// Merged one-launch weight splitter (compile-time segment table)
// ----------------------------------------------------------------------------
constexpr size_t NP_TOK = (size_t)CV * CD / 2;          // 6432896
constexpr size_t NP_W   = (size_t)CL * CD * CD / 2;     // 524288
constexpr size_t NP_WF  = (size_t)CL * CD * CFF / 2;    // 2097152
constexpr size_t NP_TOT = NP_TOK + 4 * NP_W + 2 * NP_WF;

__global__ void split_all_kernel(
    const float* __restrict__ tok, const float* __restrict__ Wq,
    const float* __restrict__ Wk, const float* __restrict__ Wv,
    const float* __restrict__ Wo, const float* __restrict__ W1,
    const float* __restrict__ W2,
    bf16* __restrict__ th, bf16* __restrict__ tl,
    bf16* __restrict__ wqh, bf16* __restrict__ wql,
    bf16* __restrict__ wkh, bf16* __restrict__ wkl,
    bf16* __restrict__ wvh, bf16* __restrict__ wvl,
    bf16* __restrict__ woh, bf16* __restrict__ wol,
    bf16* __restrict__ w1h, bf16* __restrict__ w1l,
    bf16* __restrict__ w2h, bf16* __restrict__ w2l) {
    size_t i = (size_t)blockIdx.x * blockDim.x + threadIdx.x;
    if (i >= NP_TOT) return;
    const float* src; bf16 *hi, *lo;
    if (i < NP_TOK) { src = tok; hi = th; lo = tl; }
    else {
        i -= NP_TOK;
        if (i < NP_W)          { src = Wq; hi = wqh; lo = wql; }
        else if (i < 2 * NP_W) { i -= NP_W;     src = Wk; hi = wkh; lo = wkl; }
        else if (i < 3 * NP_W) { i -= 2 * NP_W; src = Wv; hi = wvh; lo = wvl; }
        else if (i < 4 * NP_W) { i -= 3 * NP_W; src = Wo; hi = woh; lo = wol; }
        else if (i < 4 * NP_W + NP_WF) { i -= 4 * NP_W; src = W1; hi = w1h; lo = w1l; }
        else { i -= 4 * NP_W + NP_WF; src = W2; hi = w2h; lo = w2l; }
    }
    float2 x = *(const float2*)(src + 2 * i);
    uint32_t h, l;
    split2(x.x, x.y, h, l);
    *(uint32_t*)(hi + 2 * i) = h;
    *(uint32_t*)(lo + 2 * i) = l;
}

// ----------------------------------------------------------------------------
// All-bf16 HMMA GEMM core. 128(M) x NTILE(N) tile (NTILE 64 or 128), BK=32,
// 256 thr (8 warps 2x4), 2-stage cp.async pipeline, 3-term split.
// ----------------------------------------------------------------------------
constexpr int GSLOT = 10240;
constexpr int GEMM_SMEM = 2 * 4 * GSLOT;

template <int NTILE, bool TRANSB, bool GELU, bool SPLIT>
__device__ __forceinline__ void bgemm_core(
    const bf16* __restrict__ Ah, const bf16* __restrict__ Al,
    const bf16* __restrict__ Bh, const bf16* __restrict__ Bl,
    const float* __restrict__ bias, const float* __restrict__ resid,
    float* __restrict__ C, bf16* __restrict__ Oh, bf16* __restrict__ Ol,
    int N, int K, int m0, int n0, char* smbase) {
    constexpr int NI = NTILE / 32;            // n-mma per warp (2 or 4)
    constexpr int NB2 = NTILE / 64;           // ldsm4t groups per warp (1 or 2)
    constexpr int BPITCH = NTILE * 2 + 16;    // !TRANSB B row pitch (144/272)
    const int t = threadIdx.x;
    const int lane = t & 31, wid = t >> 5;
    const int wm = wid & 1, wn = wid >> 1;
    const uint32_t sU = smem_u32(smbase);

    auto slot = [&](int s, int comp) -> uint32_t {
        return sU + (uint32_t)((s * 4 + comp) * GSLOT);
    };

    auto load_tile = [&](int s, int kc) {
        const int k0 = kc * 32;
#pragma unroll
        for (int comp = 0; comp < 2; comp++) {        // A: 128 rows x 32 k
            const bf16* src = comp ? Al : Ah;
            const uint32_t dst = slot(s, comp);
#pragma unroll
            for (int i = 0; i < 2; i++) {
                int e = t + i * 256;
                int row = e >> 2, c = e & 3;
                cp16(dst + row * 80 + c * 16,
                     src + (size_t)(m0 + row) * K + k0 + c * 8);
            }
        }
#pragma unroll
        for (int comp = 2; comp < 4; comp++) {        // B hi / lo
            const bf16* src = (comp == 2) ? Bh : Bl;
            const uint32_t dst = slot(s, comp);
            if (!TRANSB) {                            // 32 k-rows x NTILE n
                constexpr int ITER = (32 * NTILE / 8 + 255) / 256;
#pragma unroll
                for (int i = 0; i < ITER; i++) {
                    int e = t + i * 256;
                    if (32 * NTILE / 8 < 256 || e < 32 * NTILE / 8) {
                        int row = e / (NTILE / 8), c = e % (NTILE / 8);
                        cp16(dst + row * BPITCH + c * 16,
                             src + (size_t)(k0 + row) * N + n0 + c * 8);
                    }
                }
            } else {                                  // NTILE n-rows x 32 k
#pragma unroll
                for (int i = 0; i < NTILE / 64; i++) {
                    int e = t + i * 256;
                    int row = e >> 2, c = e & 3;
                    int nr = n0 + row;
                    if (nr >= N) nr = 0;
                    cp16(dst + row * 80 + c * 16,
                         src + (size_t)nr * K + k0 + c * 8);
                }
            }
        }
        cp_commit();
    };

    const uint32_t aoff =
        (uint32_t)((wm * 64 + (lane & 7) + ((lane >> 3) & 1) * 8) * 80 +
                   (lane >> 4) * 16);
    uint32_t boff;
    if (!TRANSB)
        boff = (uint32_t)(((lane & 7) + ((lane >> 3) & 1) * 8) * BPITCH +
                          (wn * (NTILE / 4) + (lane >> 4) * 8) * 2);
    else
        boff = (uint32_t)((wn * (NTILE / 4) + (lane & 7) + (lane >> 4) * 8) * 80 +
                          ((lane >> 3) & 1) * 16);

    float acc[4][NI][4] = {};
    const int KT = K / 32;
    load_tile(0, 0);

    for (int kc = 0; kc < KT; kc++) {
        if (kc + 1 < KT) { load_tile((kc + 1) & 1, kc + 1); cp_wait<1>(); }
        else             { cp_wait<0>(); }
        __syncthreads();
        const int s = kc & 1;
        const uint32_t sAh = slot(s, 0), sAl = slot(s, 1);
        const uint32_t sBh = slot(s, 2), sBl = slot(s, 3);
#pragma unroll
        for (int ks = 0; ks < 2; ks++) {
            uint32_t ah[4][4], al[4][4], bh[NB2][4], bl[NB2][4];
#pragma unroll
            for (int mi = 0; mi < 4; mi++) {
                ldsm4(ah[mi], sAh + aoff + mi * (16 * 80) + ks * 32);
                ldsm4(al[mi], sAl + aoff + mi * (16 * 80) + ks * 32);
            }
#pragma unroll
            for (int n2 = 0; n2 < NB2; n2++) {
                if (!TRANSB) {
                    ldsm4t(bh[n2], sBh + boff + n2 * 32 + ks * (16 * BPITCH));
                    ldsm4t(bl[n2], sBl + boff + n2 * 32 + ks * (16 * BPITCH));
                } else {
                    ldsm4(bh[n2], sBh + boff + n2 * (16 * 80) + ks * 32);
                    ldsm4(bl[n2], sBl + boff + n2 * (16 * 80) + ks * 32);
                }
            }
#pragma unroll
            for (int mi = 0; mi < 4; mi++)
#pragma unroll
                for (int ni = 0; ni < NI; ni++) {
                    const uint32_t* bhp = &bh[ni >> 1][(ni & 1) * 2];
                    const uint32_t* blp = &bl[ni >> 1][(ni & 1) * 2];
                    mma16816(acc[mi][ni], ah[mi], bhp);
                    mma16816(acc[mi][ni], al[mi], bhp);
                    mma16816(acc[mi][ni], ah[mi], blp);
                }
        }
        __syncthreads();
    }

    // Epilogue
#pragma unroll
    for (int mi = 0; mi < 4; mi++) {
        const int r0 = m0 + wm * 64 + mi * 16 + (lane >> 2);
#pragma unroll
        for (int ni = 0; ni < NI; ni++) {
            const int col = n0 + wn * (NTILE / 4) + ni * 8 + (lane & 3) * 2;
            float v0 = acc[mi][ni][0], v1 = acc[mi][ni][1];
            float v2 = acc[mi][ni][2], v3 = acc[mi][ni][3];
            if (bias) {
                float b0 = (!TRANSB || col < N) ? bias[col] : 0.f;
                float b1 = (!TRANSB || col + 1 < N) ? bias[col + 1] : 0.f;
                v0 += b0; v1 += b1; v2 += b0; v3 += b1;
            }
            if (GELU) {
                v0 = 0.5f * v0 * (1.f + erff(v0 * 0.70710678118654752f));
                v1 = 0.5f * v1 * (1.f + erff(v1 * 0.70710678118654752f));
                v2 = 0.5f * v2 * (1.f + erff(v2 * 0.70710678118654752f));
                v3 = 0.5f * v3 * (1.f + erff(v3 * 0.70710678118654752f));
            }
            size_t o0 = (size_t)r0 * N + col;
            size_t o1 = o0 + (size_t)8 * N;
            if (SPLIT) {
                uint32_t hh, ll;
                split2(v0, v1, hh, ll);
                *(uint32_t*)(Oh + o0) = hh;
                *(uint32_t*)(Ol + o0) = ll;
                split2(v2, v3, hh, ll);
                *(uint32_t*)(Oh + o1) = hh;
                *(uint32_t*)(Ol + o1) = ll;
            } else if (!TRANSB) {
                if (resid) {
                    float2 rr0 = *(const float2*)(resid + o0);
                    float2 rr1 = *(const float2*)(resid + o1);
                    v0 += rr0.x; v1 += rr0.y; v2 += rr1.x; v3 += rr1.y;
                }
                *(float2*)(C + o0) = make_float2(v0, v1);
                *(float2*)(C + o1) = make_float2(v2, v3);
            } else {
                if (col < N)     { C[o0] = v0; C[o1] = v2; }
                if (col + 1 < N) { C[o0 + 1] = v1; C[o1 + 1] = v3; }
            }
        }
    }
}

// Wo / W2: fp32 + residual output, NTILE=64 (128-CTA grids)
__global__ __launch_bounds__(256)
void gemm_res_kernel(const bf16* __restrict__ Ah, const bf16* __restrict__ Al,
                     const bf16* __restrict__ Bh, const bf16* __restrict__ Bl,
                     const float* __restrict__ bias, const float* __restrict__ resid,
                     float* __restrict__ C, int N, int K) {
    extern __shared__ char sm[];
    bgemm_core<64, false, false, false>(Ah, Al, Bh, Bl, bias, resid, C,
                                        nullptr, nullptr, N, K,
                                        blockIdx.y * 128, blockIdx.x * 64, sm);
}

// W1: GELU + split-bf16 output
__global__ __launch_bounds__(256)
void gemm_gelu_kernel(const bf16* __restrict__ Ah, const bf16* __restrict__ Al,
                      const bf16* __restrict__ Bh, const bf16* __restrict__ Bl,
                      const float* __restrict__ bias,
                      bf16* __restrict__ Oh, bf16* __restrict__ Ol, int N, int K) {
    extern __shared__ char sm[];
    bgemm_core<128, false, true, true>(Ah, Al, Bh, Bl, bias, nullptr, nullptr,
                                       Oh, Ol, N, K,
                                       blockIdx.y * 128, blockIdx.x * 128, sm);
}

// QKV fused
__global__ __launch_bounds__(256)
void qkv_kernel(const bf16* __restrict__ Ah, const bf16* __restrict__ Al,
                const bf16* __restrict__ Wh0, const bf16* __restrict__ Wl0,
                const bf16* __restrict__ Wh1, const bf16* __restrict__ Wl1,
                const bf16* __restrict__ Wh2, const bf16* __restrict__ Wl2,
                const float* __restrict__ c0, const float* __restrict__ c1,
                const float* __restrict__ c2,
                bf16* __restrict__ qh, bf16* __restrict__ ql,
                bf16* __restrict__ kh, bf16* __restrict__ kl,
                bf16* __restrict__ vh, bf16* __restrict__ vl) {
    extern __shared__ char sm[];
    int z = blockIdx.z;
    const bf16* Bh = (z == 0) ? Wh0 : (z == 1) ? Wh1 : Wh2;
    const bf16* Bl = (z == 0) ? Wl0 : (z == 1) ? Wl1 : Wl2;
    const float* bi = (z == 0) ? c0 : (z == 1) ? c1 : c2;
    bf16* oh = (z == 0) ? qh : (z == 1) ? kh : vh;
    bf16* ol = (z == 0) ? ql : (z == 1) ? kl : vl;
    bgemm_core<128, false, false, true>(Ah, Al, Bh, Bl, bi, nullptr, nullptr,
                                        oh, ol, CD, CD,
                                        blockIdx.y * 128, blockIdx.x * 128, sm);
}

// lm_head
__global__ __launch_bounds__(256)
void lmhead_kernel(const bf16* __restrict__ Ah, const bf16* __restrict__ Al,
                   const bf16* __restrict__ Th, const bf16* __restrict__ Tl,
                   float* __restrict__ out) {
    extern __shared__ char sm[];
    bgemm_core<128, true, false, false>(Ah, Al, Th, Tl, nullptr, nullptr, out,
                                        nullptr, nullptr, CV, CD,
                                        blockIdx.x * 128, blockIdx.y * 128, sm);
}

// ----------------------------------------------------------------------------
// HMMA flash attention, causal-folded: grid (16, B*H), 128 threads.
// ----------------------------------------------------------------------------
constexpr int AP = 72;
constexpr int TILEB = 64 * AP * 2;
constexpr int ATTN_SMEM = 10 * TILEB;

__global__ __launch_bounds__(128)
void attn_kernel(const bf16* __restrict__ Qh, const bf16* __restrict__ Ql,
                 const bf16* __restrict__ Kh, const bf16* __restrict__ Kl,
                 const bf16* __restrict__ Vh, const bf16* __restrict__ Vl,
                 bf16* __restrict__ Ath, bf16* __restrict__ Atl) {
    extern __shared__ char sm[];
    const uint32_t smU = smem_u32(sm);
    const uint32_t qU = smU;
    const uint32_t kvU = smU + 2 * TILEB;

    const int t = threadIdx.x;
    const int lane = t & 31, w = t >> 5;
    const int bh = blockIdx.y;
    const int b = bh >> 2, h = bh & 3;
    const size_t base = (size_t)b * CS * CD + (size_t)h * CHD;

    auto load_kv = [&](int buf, int kt) {
        const int k0 = kt * 64;
#pragma unroll
        for (int a = 0; a < 4; a++) {
            const bf16* src =
                ((a == 0) ? Kh : (a == 1) ? Kl : (a == 2) ? Vh : Vl) +
                base + (size_t)k0 * CD;
            const uint32_t dbase = kvU + (buf * 4 + a) * TILEB;
#pragma unroll
            for (int i = 0; i < 4; i++) {
                int e = t + i * 128;
                int row = e >> 3, c = e & 7;
                cp16(dbase + row * (AP * 2) + c * 16, src + (size_t)row * CD + c * 8);
            }
        }
        cp_commit();
    };

    for (int half = 0; half < 2; half++) {
        const int qt = half ? (31 - (int)blockIdx.x) : (int)blockIdx.x;
        const int q0 = qt * 64;
        __syncthreads();

        load_kv(0, 0);
#pragma unroll
        for (int a = 0; a < 2; a++) {
            const bf16* src = (a ? Ql : Qh) + base + (size_t)q0 * CD;
            char* dst = sm + a * TILEB;
#pragma unroll
            for (int i = 0; i < 4; i++) {
                int e = t + i * 128;
                int row = e >> 3, c = e & 7;
                *(uint4*)(dst + row * (AP * 2) + c * 16) =
                    *(const uint4*)(src + (size_t)row * CD + c * 8);
            }
        }
        __syncthreads();

        uint32_t qfh[4][4], qfl[4][4];
        {
            const uint32_t aoff =
                (uint32_t)((w * 16 + (lane & 7) + ((lane >> 3) & 1) * 8) * (AP * 2) +
                           (lane >> 4) * 16);
#pragma unroll
            for (int ks = 0; ks < 4; ks++) {
                ldsm4(qfh[ks], qU + aoff + ks * 32);
                ldsm4(qfl[ks], qU + TILEB + aoff + ks * 32);
            }
        }

        float acc[8][4] = {};
        float m_0 = -1e30f, m_1 = -1e30f, l_0 = 0.f, l_1 = 0.f;
        const int rl0 = w * 16 + (lane >> 2);

        for (int kt = 0; kt <= qt; kt++) {
            const int buf = kt & 1;
            const bool more = kt < qt;
            if (more) { load_kv(buf ^ 1, kt + 1); cp_wait<1>(); }
            else      { cp_wait<0>(); }
            __syncthreads();

            const uint32_t kBufH = kvU + (buf * 4 + 0) * TILEB;
            const uint32_t kBufL = kvU + (buf * 4 + 1) * TILEB;
            const uint32_t vBufH = kvU + (buf * 4 + 2) * TILEB;
            const uint32_t vBufL = kvU + (buf * 4 + 3) * TILEB;

            float st[8][4] = {};
#pragma unroll
            for (int ks = 0; ks < 4; ks++) {
                uint32_t kh4[4][4], kl4[4][4];
#pragma unroll
                for (int nt = 0; nt < 4; nt++) {
                    uint32_t ko =
                        (uint32_t)((nt * 16 + (lane & 7) + (lane >> 4) * 8) * (AP * 2) +
                                   ((lane >> 3) & 1) * 16 + ks * 32);
                    ldsm4(kh4[nt], kBufH + ko);
                    ldsm4(kl4[nt], kBufL + ko);
                }
#pragma unroll
                for (int ni = 0; ni < 8; ni++) {
                    const uint32_t* bhp = &kh4[ni >> 1][(ni & 1) * 2];
                    const uint32_t* blp = &kl4[ni >> 1][(ni & 1) * 2];
                    mma16816(st[ni], qfh[ks], bhp);
                    mma16816(st[ni], qfl[ks], bhp);
                    mma16816(st[ni], qfh[ks], blp);
                }
            }

#pragma unroll
            for (int ni = 0; ni < 8; ni++)
#pragma unroll
                for (int e = 0; e < 4; e++) st[ni][e] *= 0.125f;
            if (kt == qt) {
#pragma unroll
                for (int ni = 0; ni < 8; ni++) {
                    int cb = ni * 8 + (lane & 3) * 2;
                    if (cb > rl0)         st[ni][0] = -1e30f;
                    if (cb + 1 > rl0)     st[ni][1] = -1e30f;
                    if (cb > rl0 + 8)     st[ni][2] = -1e30f;
                    if (cb + 1 > rl0 + 8) st[ni][3] = -1e30f;
                }
            }

            float t0 = -1e30f, t1 = -1e30f;
#pragma unroll
            for (int ni = 0; ni < 8; ni++) {
                t0 = fmaxf(t0, fmaxf(st[ni][0], st[ni][1]));
                t1 = fmaxf(t1, fmaxf(st[ni][2], st[ni][3]));
            }
            t0 = fmaxf(t0, __shfl_xor_sync(0xffffffffu, t0, 1));
            t0 = fmaxf(t0, __shfl_xor_sync(0xffffffffu, t0, 2));
            t1 = fmaxf(t1, __shfl_xor_sync(0xffffffffu, t1, 1));
            t1 = fmaxf(t1, __shfl_xor_sync(0xffffffffu, t1, 2));
            float mn0 = fmaxf(m_0, t0), mn1 = fmaxf(m_1, t1);
            float fr0 = __expf(m_0 - mn0), fr1 = __expf(m_1 - mn1);
            m_0 = mn0; m_1 = mn1;
            float ps0 = 0.f, ps1 = 0.f;
#pragma unroll
            for (int ni = 0; ni < 8; ni++) {
                float p0 = __expf(st[ni][0] - mn0); st[ni][0] = p0; ps0 += p0;
                float p1 = __expf(st[ni][1] - mn0); st[ni][1] = p1; ps0 += p1;
                float p2 = __expf(st[ni][2] - mn1); st[ni][2] = p2; ps1 += p2;
                float p3 = __expf(st[ni][3] - mn1); st[ni][3] = p3; ps1 += p3;
            }
            ps0 += __shfl_xor_sync(0xffffffffu, ps0, 1);
            ps0 += __shfl_xor_sync(0xffffffffu, ps0, 2);
            ps1 += __shfl_xor_sync(0xffffffffu, ps1, 1);
            ps1 += __shfl_xor_sync(0xffffffffu, ps1, 2);
            l_0 = l_0 * fr0 + ps0;
            l_1 = l_1 * fr1 + ps1;
#pragma unroll
            for (int ni = 0; ni < 8; ni++) {
                acc[ni][0] *= fr0; acc[ni][1] *= fr0;
                acc[ni][2] *= fr1; acc[ni][3] *= fr1;
            }

#pragma unroll
            for (int ks = 0; ks < 4; ks++) {
                uint32_t pah[4], pal[4];
                split2(st[2 * ks][0],     st[2 * ks][1],     pah[0], pal[0]);
                split2(st[2 * ks][2],     st[2 * ks][3],     pah[1], pal[1]);
                split2(st[2 * ks + 1][0], st[2 * ks + 1][1], pah[2], pal[2]);
                split2(st[2 * ks + 1][2], st[2 * ks + 1][3], pah[3], pal[3]);
                uint32_t vh4[4][4], vl4[4][4];
#pragma unroll
                for (int vt = 0; vt < 4; vt++) {
                    uint32_t vo =
                        (uint32_t)(((lane & 7) + ((lane >> 3) & 1) * 8 + ks * 16) * (AP * 2) +
                                   (vt * 16 + (lane >> 4) * 8) * 2);
                    ldsm4t(vh4[vt], vBufH + vo);
                    ldsm4t(vl4[vt], vBufL + vo);
                }
#pragma unroll
                for (int ni = 0; ni < 8; ni++) {
                    const uint32_t* vhp = &vh4[ni >> 1][(ni & 1) * 2];
                    const uint32_t* vlp = &vl4[ni >> 1][(ni & 1) * 2];
                    mma16816(acc[ni], pah, vhp);
                    mma16816(acc[ni], pal, vhp);
                    mma16816(acc[ni], pah, vlp);
                }
            }
            __syncthreads();
        }

        float i0 = 1.f / l_0, i1 = 1.f / l_1;
        const int r0 = q0 + rl0;
#pragma unroll
        for (int ni = 0; ni < 8; ni++) {
            int col = ni * 8 + (lane & 3) * 2;
            size_t o = base + (size_t)r0 * CD + col;
            uint32_t hh, ll;
            split2(acc[ni][0] * i0, acc[ni][1] * i0, hh, ll);
            *(uint32_t*)(Ath + o) = hh;
            *(uint32_t*)(Atl + o) = ll;
            split2(acc[ni][2] * i1, acc[ni][3] * i1, hh, ll);
            *(uint32_t*)(Ath + o + (size_t)8 * CD) = hh;
            *(uint32_t*)(Atl + o + (size_t)8 * CD) = ll;
        }
    }
}

// ----------------------------------------------------------------------------
// Embedding
// ----------------------------------------------------------------------------
__global__ void embed_kernel(const int* __restrict__ ids,
                             const float* __restrict__ tok,
                             const float* __restrict__ pos,
                             float* __restrict__ h) {
    int i = blockIdx.x;
    int d = threadIdx.x;
    int s = i & (CS - 1);
    h[(size_t)i * CD + d] = tok[(size_t)ids[i] * CD + d] + pos[(size_t)s * CD + d];
}

// ----------------------------------------------------------------------------
// LayerNorm -> split-bf16 output
// ----------------------------------------------------------------------------
__global__ void ln_kernel(const float* __restrict__ x,
                          const float* __restrict__ sc,
                          const float* __restrict__ bi,
                          bf16* __restrict__ yh, bf16* __restrict__ yl) {
    int row = blockIdx.x * 8 + threadIdx.y;   // blockDim (32, 8)
    int lane = threadIdx.x;
    const float* xr = x + (size_t)row * CD;
    float v[8];
    float sum = 0.f, sq = 0.f;
#pragma unroll
    for (int j = 0; j < 8; j++) {
        v[j] = xr[lane * 8 + j];
        sum += v[j];
        sq += v[j] * v[j];
    }
#pragma unroll
    for (int o = 16; o > 0; o >>= 1) {
        sum += __shfl_xor_sync(0xffffffffu, sum, o);
        sq  += __shfl_xor_sync(0xffffffffu, sq, o);
    }
    float mean = sum * (1.f / CD);
    float var  = sq * (1.f / CD) - mean * mean;
    float inv  = rsqrtf(var + 1e-5f);
    size_t off = (size_t)row * CD + lane * 8;
    uint32_t hbuf[4], lbuf[4];
#pragma unroll
    for (int j = 0; j < 4; j++) {
        int c = lane * 8 + 2 * j;
        float y0 = (v[2 * j]     - mean) * inv * sc[c]     + bi[c];
        float y1 = (v[2 * j + 1] - mean) * inv * sc[c + 1] + bi[c + 1];
        split2(y0, y1, hbuf[j], lbuf[j]);
    }
    *(uint4*)(yh + off) = make_uint4(hbuf[0], hbuf[1], hbuf[2], hbuf[3]);
    *(uint4*)(yl + off) = make_uint4(lbuf[0], lbuf[1], lbuf[2], lbuf[3]);
}

// ----------------------------------------------------------------------------
// Orchestration
// ----------------------------------------------------------------------------
extern "C" void kernel_launch(void* const* d_in, const int* in_sizes, int n_in,
                              void* d_out, int out_size) {
    const int*   ids  = (const int*)d_in[0];
    const float* tok  = (const float*)d_in[1];
    const float* pos  = (const float*)d_in[2];
    const float* Wq   = (const float*)d_in[3];
    const float* bq   = (const float*)d_in[4];
    const float* Wk   = (const float*)d_in[5];
    const float* bk   = (const float*)d_in[6];
    const float* Wv   = (const float*)d_in[7];
    const float* bv   = (const float*)d_in[8];
    const float* Wo   = (const float*)d_in[9];
    const float* bo   = (const float*)d_in[10];
    const float* ln1s = (const float*)d_in[11];
    const float* ln1b = (const float*)d_in[12];
    const float* ln2s = (const float*)d_in[13];
    const float* ln2b = (const float*)d_in[14];
    const float* W1   = (const float*)d_in[15];
    const float* b1   = (const float*)d_in[16];
    const float* W2   = (const float*)d_in[17];
    const float* b2   = (const float*)d_in[18];
    const float* lnfs = (const float*)d_in[19];
    const float* lnfb = (const float*)d_in[20];
    float* out = (float*)d_out;

    float* h;
    bf16 *nh, *nl, *ath, *atl, *mh, *ml, *qh, *ql, *kh, *kl, *vh, *vl;
    bf16 *th, *tl, *wqh, *wql, *wkh, *wkl, *wvh, *wvl, *woh, *wol;
    bf16 *w1h, *w1l, *w2h, *w2l;
    cudaGetSymbolAddress((void**)&h,   g_h);
    cudaGetSymbolAddress((void**)&nh,  g_nh);   cudaGetSymbolAddress((void**)&nl,  g_nl);
    cudaGetSymbolAddress((void**)&ath, g_ath);  cudaGetSymbolAddress((void**)&atl, g_atl);
    cudaGetSymbolAddress((void**)&mh,  g_mh);   cudaGetSymbolAddress((void**)&ml,  g_ml);
    cudaGetSymbolAddress((void**)&qh,  g_qh);   cudaGetSymbolAddress((void**)&ql,  g_ql);
    cudaGetSymbolAddress((void**)&kh,  g_kh);   cudaGetSymbolAddress((void**)&kl,  g_kl);
    cudaGetSymbolAddress((void**)&vh,  g_vh);   cudaGetSymbolAddress((void**)&vl,  g_vl);
    cudaGetSymbolAddress((void**)&th,  g_th);   cudaGetSymbolAddress((void**)&tl,  g_tl);
    cudaGetSymbolAddress((void**)&wqh, g_wqh);  cudaGetSymbolAddress((void**)&wql, g_wql);
    cudaGetSymbolAddress((void**)&wkh, g_wkh);  cudaGetSymbolAddress((void**)&wkl, g_wkl);
    cudaGetSymbolAddress((void**)&wvh, g_wvh);  cudaGetSymbolAddress((void**)&wvl, g_wvl);
    cudaGetSymbolAddress((void**)&woh, g_woh);  cudaGetSymbolAddress((void**)&wol, g_wol);
    cudaGetSymbolAddress((void**)&w1h, g_w1h);  cudaGetSymbolAddress((void**)&w1l, g_w1l);
    cudaGetSymbolAddress((void**)&w2h, g_w2h);  cudaGetSymbolAddress((void**)&w2l, g_w2l);

    cudaFuncSetAttribute(attn_kernel,
                         cudaFuncAttributeMaxDynamicSharedMemorySize, ATTN_SMEM);
    cudaFuncSetAttribute(gemm_res_kernel,
                         cudaFuncAttributeMaxDynamicSharedMemorySize, GEMM_SMEM);
    cudaFuncSetAttribute(gemm_gelu_kernel,
                         cudaFuncAttributeMaxDynamicSharedMemorySize, GEMM_SMEM);
    cudaFuncSetAttribute(qkv_kernel,
                         cudaFuncAttributeMaxDynamicSharedMemorySize, GEMM_SMEM);
    cudaFuncSetAttribute(lmhead_kernel,
                         cudaFuncAttributeMaxDynamicSharedMemorySize, GEMM_SMEM);

    // One launch: split all weights + tok_emb into bf16 hi/lo
    split_all_kernel<<<(unsigned)((NP_TOT + 255) / 256), 256>>>(
        tok, Wq, Wk, Wv, Wo, W1, W2,
        th, tl, wqh, wql, wkh, wkl, wvh, wvl, woh, wol, w1h, w1l, w2h, w2l);

    dim3 lnb(32, 8);
    embed_kernel<<<CM, CD>>>(ids, tok, pos, h);

    for (int l = 0; l < CL; l++) {
        size_t wofs  = (size_t)l * CD * CD;
        size_t bofs  = (size_t)l * CD;
        size_t w1ofs = (size_t)l * CD * CFF;
        size_t b1ofs = (size_t)l * CFF;
        size_t w2ofs = (size_t)l * CFF * CD;

        ln_kernel<<<CM / 8, lnb>>>(h, ln1s + bofs, ln1b + bofs, nh, nl);
        qkv_kernel<<<dim3(CD / 128, CM / 128, 3), 256, GEMM_SMEM>>>(
            nh, nl, wqh + wofs, wql + wofs, wkh + wofs, wkl + wofs,
            wvh + wofs, wvl + wofs, bq + bofs, bk + bofs, bv + bofs,
            qh, ql, kh, kl, vh, vl);

        attn_kernel<<<dim3(16, CB * CH), 128, ATTN_SMEM>>>(
            qh, ql, kh, kl, vh, vl, ath, atl);

        gemm_res_kernel<<<dim3(CD / 64, CM / 128), 256, GEMM_SMEM>>>(
            ath, atl, woh + wofs, wol + wofs, bo + bofs, h, h, CD, CD);

        ln_kernel<<<CM / 8, lnb>>>(h, ln2s + bofs, ln2b + bofs, nh, nl);
        gemm_gelu_kernel<<<dim3(CFF / 128, CM / 128), 256, GEMM_SMEM>>>(
            nh, nl, w1h + w1ofs, w1l + w1ofs, b1 + b1ofs, mh, ml, CFF, CD);
        gemm_res_kernel<<<dim3(CD / 64, CM / 128), 256, GEMM_SMEM>>>(
            mh, ml, w2h + w2ofs, w2l + w2ofs, b2 + bofs, h, h, CD, CFF);
    }

    ln_kernel<<<CM / 8, lnb>>>(h, lnfs, lnfb, nh, nl);
    lmhead_kernel<<<dim3(CM / 128, (CV + 127) / 128), 256, GEMM_SMEM>>>(
        nh, nl, th, tl, out);
}

// round 9
// speedup vs baseline: 3.2275x; 1.0276x over previous
#include <cuda_runtime.h>
#include <cuda_bf16.h>
#include <math.h>
#include <stdint.h>

typedef __nv_bfloat16 bf16;

// Problem constants
constexpr int CB = 2, CS = 2048, CD = 256, CH = 4, CL = 4, CV = 50257, CHD = 64;
constexpr int CM = CB * CS;      // 4096 rows
constexpr int CFF = 4 * CD;      // 1024

// ----------------------------------------------------------------------------
// Scratch (static device globals — no allocation inside kernel_launch)
// ----------------------------------------------------------------------------
__device__ float g_h[CM * CD];
__device__ bf16 g_nh[CM * CD],  g_nl[CM * CD];
__device__ bf16 g_ath[CM * CD], g_atl[CM * CD];
__device__ bf16 g_mh[CM * CFF], g_ml[CM * CFF];
__device__ bf16 g_qh[CM * CD], g_ql[CM * CD];
__device__ bf16 g_kh[CM * CD], g_kl[CM * CD];
__device__ bf16 g_vh[CM * CD], g_vl[CM * CD];
__device__ bf16 g_th[(size_t)CV * CD],  g_tl[(size_t)CV * CD];
__device__ bf16 g_wqh[CL * CD * CD],  g_wql[CL * CD * CD];
__device__ bf16 g_wkh[CL * CD * CD],  g_wkl[CL * CD * CD];
__device__ bf16 g_wvh[CL * CD * CD],  g_wvl[CL * CD * CD];
__device__ bf16 g_woh[CL * CD * CD],  g_wol[CL * CD * CD];
__device__ bf16 g_w1h[CL * CD * CFF], g_w1l[CL * CD * CFF];
__device__ bf16 g_w2h[CL * CD * CFF], g_w2l[CL * CD * CFF];

// ----------------------------------------------------------------------------
// Helpers
// ----------------------------------------------------------------------------
__device__ __forceinline__ uint32_t smem_u32(const void* p) {
    uint32_t a;
    asm("{ .reg .u64 t; cvta.to.shared.u64 t, %1; cvt.u32.u64 %0, t; }"
        : "=r"(a) : "l"(p));
    return a;
}
__device__ __forceinline__ void ldsm4(uint32_t* r, uint32_t addr) {
    asm volatile("ldmatrix.sync.aligned.m8n8.x4.shared.b16 {%0,%1,%2,%3}, [%4];"
                 : "=r"(r[0]), "=r"(r[1]), "=r"(r[2]), "=r"(r[3]) : "r"(addr));
}
__device__ __forceinline__ void ldsm4t(uint32_t* r, uint32_t addr) {
    asm volatile("ldmatrix.sync.aligned.m8n8.x4.trans.shared.b16 {%0,%1,%2,%3}, [%4];"
                 : "=r"(r[0]), "=r"(r[1]), "=r"(r[2]), "=r"(r[3]) : "r"(addr));
}
__device__ __forceinline__ void mma16816(float* c, const uint32_t* a, const uint32_t* b) {
    asm volatile("mma.sync.aligned.m16n8k16.row.col.f32.bf16.bf16.f32 "
                 "{%0,%1,%2,%3}, {%4,%5,%6,%7}, {%8,%9}, {%0,%1,%2,%3};"
                 : "+f"(c[0]), "+f"(c[1]), "+f"(c[2]), "+f"(c[3])
                 : "r"(a[0]), "r"(a[1]), "r"(a[2]), "r"(a[3]),
                   "r"(b[0]), "r"(b[1]));
}
__device__ __forceinline__ void split2(float x, float y, uint32_t& h, uint32_t& l) {
    asm("cvt.rn.bf16x2.f32 %0, %1, %2;" : "=r"(h) : "f"(y), "f"(x));
    float hx = __uint_as_float(h << 16);
    float hy = __uint_as_float(h & 0xFFFF0000u);
    float lx = x - hx, ly = y - hy;
    asm("cvt.rn.bf16x2.f32 %0, %1, %2;" : "=r"(l) : "f"(ly), "f"(lx));
}
__device__ __forceinline__ void cp16(uint32_t dst, const void* src) {
    asm volatile("cp.async.ca.shared.global [%0], [%1], 16;" :: "r"(dst), "l"(src));
}
__device__ __forceinline__ void cp_commit() {
    asm volatile("cp.async.commit_group;" ::: "memory");
}
template <int N>
__device__ __forceinline__ void cp_wait() {
    asm volatile("cp.async.wait_group %0;" :: "n"(N) : "memory");
}

// ----------------------------------------------------------------------------
// Merged one-launch weight splitter
// ----------------------------------------------------------------------------
constexpr size_t NP_TOK = (size_t)CV * CD / 2;
constexpr size_t NP_W   = (size_t)CL * CD * CD / 2;
constexpr size_t NP_WF  = (size_t)CL * CD * CFF / 2;
constexpr size_t NP_TOT = NP_TOK + 4 * NP_W + 2 * NP_WF;

__global__ void split_all_kernel(
    const float* __restrict__ tok, const float* __restrict__ Wq,
    const float* __restrict__ Wk, const float* __restrict__ Wv,
    const float* __restrict__ Wo, const float* __restrict__ W1,
    const float* __restrict__ W2,
    bf16* __restrict__ th, bf16* __restrict__ tl,
    bf16* __restrict__ wqh, bf16* __restrict__ wql,
    bf16* __restrict__ wkh, bf16* __restrict__ wkl,
    bf16* __restrict__ wvh, bf16* __restrict__ wvl,
    bf16* __restrict__ woh, bf16* __restrict__ wol,
    bf16* __restrict__ w1h, bf16* __restrict__ w1l,
    bf16* __restrict__ w2h, bf16* __restrict__ w2l) {
    size_t i = (size_t)blockIdx.x * blockDim.x + threadIdx.x;
    if (i >= NP_TOT) return;
    const float* src; bf16 *hi, *lo;
    if (i < NP_TOK) { src = tok; hi = th; lo = tl; }
    else {
        i -= NP_TOK;
        if (i < NP_W)          { src = Wq; hi = wqh; lo = wql; }
        else if (i < 2 * NP_W) { i -= NP_W;     src = Wk; hi = wkh; lo = wkl; }
        else if (i < 3 * NP_W) { i -= 2 * NP_W; src = Wv; hi = wvh; lo = wvl; }
        else if (i < 4 * NP_W) { i -= 3 * NP_W; src = Wo; hi = woh; lo = wol; }
        else if (i < 4 * NP_W + NP_WF) { i -= 4 * NP_W; src = W1; hi = w1h; lo = w1l; }
        else { i -= 4 * NP_W + NP_WF; src = W2; hi = w2h; lo = w2l; }
    }
    float2 x = *(const float2*)(src + 2 * i);
    uint32_t h, l;
    split2(x.x, x.y, h, l);
    *(uint32_t*)(hi + 2 * i) = h;
    *(uint32_t*)(lo + 2 * i) = l;
}

// ----------------------------------------------------------------------------
// All-bf16 HMMA GEMM core, parameterized MTILE x NTILE.
// 8 warps as (WM = MTILE/64) x (WN = 8/WM); each warp: 64 x (NTILE/WN).
// BK=32, 2-stage cp.async pipeline, 3-term split: AhBh + AlBh + AhBl.
// ----------------------------------------------------------------------------
template <int MTILE, int NTILE, bool TRANSB>
struct GCfg {
    static constexpr int WM = MTILE / 64;
    static constexpr int WN = 8 / WM;
    static constexpr int WARP_N = NTILE / WN;
    static constexpr int NI = WARP_N / 8;
    static constexpr int NB2 = WARP_N / 16;
    static constexpr int BPITCH = NTILE * 2 + 16;
    static constexpr int ASLOT = MTILE * 80;
    static constexpr int BSLOT = TRANSB ? NTILE * 80 : 32 * BPITCH;
    static constexpr int STAGE = 2 * ASLOT + 2 * BSLOT;
    static constexpr int SMEM = 2 * STAGE;
};

template <int MTILE, int NTILE, bool TRANSB, bool GELU, bool SPLIT>
__device__ __forceinline__ void bgemm_core(
    const bf16* __restrict__ Ah, const bf16* __restrict__ Al,
    const bf16* __restrict__ Bh, const bf16* __restrict__ Bl,
    const float* __restrict__ bias, const float* __restrict__ resid,
    float* __restrict__ C, bf16* __restrict__ Oh, bf16* __restrict__ Ol,
    int N, int K, int m0, int n0, char* smbase) {
    using CF = GCfg<MTILE, NTILE, TRANSB>;
    const int t = threadIdx.x;
    const int lane = t & 31, wid = t >> 5;
    const int wm = wid % CF::WM, wn = wid / CF::WM;
    const uint32_t sU = smem_u32(smbase);

    auto load_tile = [&](int s, int kc) {
        const int k0 = kc * 32;
        const uint32_t sb = sU + (uint32_t)(s * CF::STAGE);
#pragma unroll
        for (int comp = 0; comp < 2; comp++) {        // A: MTILE rows x 32 k
            const bf16* src = comp ? Al : Ah;
            const uint32_t dst = sb + comp * CF::ASLOT;
#pragma unroll
            for (int i = 0; i < MTILE / 64; i++) {
                int e = t + i * 256;
                int row = e >> 2, c = e & 3;
                cp16(dst + row * 80 + c * 16,
                     src + (size_t)(m0 + row) * K + k0 + c * 8);
            }
        }
#pragma unroll
        for (int comp = 0; comp < 2; comp++) {        // B hi / lo
            const bf16* src = comp ? Bl : Bh;
            const uint32_t dst = sb + 2 * CF::ASLOT + comp * CF::BSLOT;
            if (!TRANSB) {                            // 32 k-rows x NTILE n
                constexpr int OPS = 32 * NTILE / 8;
#pragma unroll
                for (int i = 0; i < (OPS + 255) / 256; i++) {
                    int e = t + i * 256;
                    if (OPS >= 256 * (i + 1) || e < OPS) {
                        int row = e / (NTILE / 8), c = e % (NTILE / 8);
                        cp16(dst + row * CF::BPITCH + c * 16,
                             src + (size_t)(k0 + row) * N + n0 + c * 8);
                    }
                }
            } else {                                  // NTILE n-rows x 32 k
#pragma unroll
                for (int i = 0; i < NTILE / 64; i++) {
                    int e = t + i * 256;
                    int row = e >> 2, c = e & 3;
                    int nr = n0 + row;
                    if (nr >= N) nr = 0;
                    cp16(dst + row * 80 + c * 16,
                         src + (size_t)nr * K + k0 + c * 8);
                }
            }
        }
        cp_commit();
    };

    const uint32_t aoff =
        (uint32_t)((wm * 64 + (lane & 7) + ((lane >> 3) & 1) * 8) * 80 +
                   (lane >> 4) * 16);
    uint32_t boff;
    if (!TRANSB)
        boff = (uint32_t)(((lane & 7) + ((lane >> 3) & 1) * 8) * CF::BPITCH +
                          (wn * CF::WARP_N + (lane >> 4) * 8) * 2);
    else
        boff = (uint32_t)((wn * CF::WARP_N + (lane & 7) + (lane >> 4) * 8) * 80 +
                          ((lane >> 3) & 1) * 16);

    float acc[4][CF::NI][4] = {};
    const int KT = K / 32;
    load_tile(0, 0);

    for (int kc = 0; kc < KT; kc++) {
        if (kc + 1 < KT) { load_tile((kc + 1) & 1, kc + 1); cp_wait<1>(); }
        else             { cp_wait<0>(); }
        __syncthreads();
        const uint32_t sb = sU + (uint32_t)((kc & 1) * CF::STAGE);
        const uint32_t sAh = sb, sAl = sb + CF::ASLOT;
        const uint32_t sBh = sb + 2 * CF::ASLOT, sBl = sBh + CF::BSLOT;
#pragma unroll
        for (int ks = 0; ks < 2; ks++) {
            uint32_t ah[4][4], al[4][4], bh[CF::NB2][4], bl[CF::NB2][4];
#pragma unroll
            for (int mi = 0; mi < 4; mi++) {
                ldsm4(ah[mi], sAh + aoff + mi * (16 * 80) + ks * 32);
                ldsm4(al[mi], sAl + aoff + mi * (16 * 80) + ks * 32);
            }
#pragma unroll
            for (int n2 = 0; n2 < CF::NB2; n2++) {
                if (!TRANSB) {
                    ldsm4t(bh[n2], sBh + boff + n2 * 32 + ks * (16 * CF::BPITCH));
                    ldsm4t(bl[n2], sBl + boff + n2 * 32 + ks * (16 * CF::BPITCH));
                } else {
                    ldsm4(bh[n2], sBh + boff + n2 * (16 * 80) + ks * 32);
                    ldsm4(bl[n2], sBl + boff + n2 * (16 * 80) + ks * 32);
                }
            }
#pragma unroll
            for (int mi = 0; mi < 4; mi++)
#pragma unroll
                for (int ni = 0; ni < CF::NI; ni++) {
                    const uint32_t* bhp = &bh[ni >> 1][(ni & 1) * 2];
                    const uint32_t* blp = &bl[ni >> 1][(ni & 1) * 2];
                    mma16816(acc[mi][ni], ah[mi], bhp);
                    mma16816(acc[mi][ni], al[mi], bhp);
                    mma16816(acc[mi][ni], ah[mi], blp);
                }
        }
        __syncthreads();
    }

    // Epilogue
#pragma unroll
    for (int mi = 0; mi < 4; mi++) {
        const int r0 = m0 + wm * 64 + mi * 16 + (lane >> 2);
#pragma unroll
        for (int ni = 0; ni < CF::NI; ni++) {
            const int col = n0 + wn * CF::WARP_N + ni * 8 + (lane & 3) * 2;
            float v0 = acc[mi][ni][0], v1 = acc[mi][ni][1];
            float v2 = acc[mi][ni][2], v3 = acc[mi][ni][3];
            if (bias) {
                float b0 = (!TRANSB || col < N) ? bias[col] : 0.f;
                float b1 = (!TRANSB || col + 1 < N) ? bias[col + 1] : 0.f;
                v0 += b0; v1 += b1; v2 += b0; v3 += b1;
            }
            if (GELU) {
                v0 = 0.5f * v0 * (1.f + erff(v0 * 0.70710678118654752f));
                v1 = 0.5f * v1 * (1.f + erff(v1 * 0.70710678118654752f));
                v2 = 0.5f * v2 * (1.f + erff(v2 * 0.70710678118654752f));
                v3 = 0.5f * v3 * (1.f + erff(v3 * 0.70710678118654752f));
            }
            size_t o0 = (size_t)r0 * N + col;
            size_t o1 = o0 + (size_t)8 * N;
            if (SPLIT) {
                uint32_t hh, ll;
                split2(v0, v1, hh, ll);
                *(uint32_t*)(Oh + o0) = hh;
                *(uint32_t*)(Ol + o0) = ll;
                split2(v2, v3, hh, ll);
                *(uint32_t*)(Oh + o1) = hh;
                *(uint32_t*)(Ol + o1) = ll;
            } else if (!TRANSB) {
                if (resid) {
                    float2 rr0 = *(const float2*)(resid + o0);
                    float2 rr1 = *(const float2*)(resid + o1);
                    v0 += rr0.x; v1 += rr0.y; v2 += rr1.x; v3 += rr1.y;
                }
                *(float2*)(C + o0) = make_float2(v0, v1);
                *(float2*)(C + o1) = make_float2(v2, v3);
            } else {
                if (col < N)     { C[o0] = v0; C[o1] = v2; }
                if (col + 1 < N) { C[o0 + 1] = v1; C[o1 + 1] = v3; }
            }
        }
    }
}

// Wo / W2: 128x64 tiles, fp32 + residual
constexpr int SMEM_RES = GCfg<128, 64, false>::SMEM;
__global__ __launch_bounds__(256, 1)
void gemm_res_kernel(const bf16* __restrict__ Ah, const bf16* __restrict__ Al,
                     const bf16* __restrict__ Bh, const bf16* __restrict__ Bl,
                     const float* __restrict__ bias, const float* __restrict__ resid,
                     float* __restrict__ C, int N, int K) {
    extern __shared__ char sm[];
    bgemm_core<128, 64, false, false, false>(Ah, Al, Bh, Bl, bias, resid, C,
                                             nullptr, nullptr, N, K,
                                             blockIdx.y * 128, blockIdx.x * 64, sm);
}

// W1: 256x128 tiles, GELU + split-bf16 output
constexpr int SMEM_BIG = GCfg<256, 128, false>::SMEM;
__global__ __launch_bounds__(256, 1)
void gemm_gelu_kernel(const bf16* __restrict__ Ah, const bf16* __restrict__ Al,
                      const bf16* __restrict__ Bh, const bf16* __restrict__ Bl,
                      const float* __restrict__ bias,
                      bf16* __restrict__ Oh, bf16* __restrict__ Ol, int N, int K) {
    extern __shared__ char sm[];
    bgemm_core<256, 128, false, true, true>(Ah, Al, Bh, Bl, bias, nullptr, nullptr,
                                            Oh, Ol, N, K,
                                            blockIdx.y * 256, blockIdx.x * 128, sm);
}

// QKV fused: 256x128 tiles
__global__ __launch_bounds__(256, 1)
void qkv_kernel(const bf16* __restrict__ Ah, const bf16* __restrict__ Al,
                const bf16* __restrict__ Wh0, const bf16* __restrict__ Wl0,
                const bf16* __restrict__ Wh1, const bf16* __restrict__ Wl1,
                const bf16* __restrict__ Wh2, const bf16* __restrict__ Wl2,
                const float* __restrict__ c0, const float* __restrict__ c1,
                const float* __restrict__ c2,
                bf16* __restrict__ qh, bf16* __restrict__ ql,
                bf16* __restrict__ kh, bf16* __restrict__ kl,
                bf16* __restrict__ vh, bf16* __restrict__ vl) {
    extern __shared__ char sm[];
    int z = blockIdx.z;
    const bf16* Bh = (z == 0) ? Wh0 : (z == 1) ? Wh1 : Wh2;
    const bf16* Bl = (z == 0) ? Wl0 : (z == 1) ? Wl1 : Wl2;
    const float* bi = (z == 0) ? c0 : (z == 1) ? c1 : c2;
    bf16* oh = (z == 0) ? qh : (z == 1) ? kh : vh;
    bf16* ol = (z == 0) ? ql : (z == 1) ? kl : vl;
    bgemm_core<256, 128, false, false, true>(Ah, Al, Bh, Bl, bi, nullptr, nullptr,
                                             oh, ol, CD, CD,
                                             blockIdx.y * 256, blockIdx.x * 128, sm);
}

// lm_head: 256x128 tiles, m-fast grid
constexpr int SMEM_LMH = GCfg<256, 128, true>::SMEM;
__global__ __launch_bounds__(256, 1)
void lmhead_kernel(const bf16* __restrict__ Ah, const bf16* __restrict__ Al,
                   const bf16* __restrict__ Th, const bf16* __restrict__ Tl,
                   float* __restrict__ out) {
    extern __shared__ char sm[];
    bgemm_core<256, 128, true, false, false>(Ah, Al, Th, Tl, nullptr, nullptr, out,
                                             nullptr, nullptr, CV, CD,
                                             blockIdx.x * 256, blockIdx.y * 128, sm);
}

// ----------------------------------------------------------------------------
// HMMA flash attention, causal-folded: grid (16, B*H), 128 threads.
// ----------------------------------------------------------------------------
constexpr int AP = 72;
constexpr int TILEB = 64 * AP * 2;
constexpr int ATTN_SMEM = 10 * TILEB;

__global__ __launch_bounds__(128)
void attn_kernel(const bf16* __restrict__ Qh, const bf16* __restrict__ Ql,
                 const bf16* __restrict__ Kh, const bf16* __restrict__ Kl,
                 const bf16* __restrict__ Vh, const bf16* __restrict__ Vl,
                 bf16* __restrict__ Ath, bf16* __restrict__ Atl) {
    extern __shared__ char sm[];
    const uint32_t smU = smem_u32(sm);
    const uint32_t qU = smU;
    const uint32_t kvU = smU + 2 * TILEB;

    const int t = threadIdx.x;
    const int lane = t & 31, w = t >> 5;
    const int bh = blockIdx.y;
    const int b = bh >> 2, h = bh & 3;
    const size_t base = (size_t)b * CS * CD + (size_t)h * CHD;

    auto load_kv = [&](int buf, int kt) {
        const int k0 = kt * 64;
#pragma unroll
        for (int a = 0; a < 4; a++) {
            const bf16* src =
                ((a == 0) ? Kh : (a == 1) ? Kl : (a == 2) ? Vh : Vl) +
                base + (size_t)k0 * CD;
            const uint32_t dbase = kvU + (buf * 4 + a) * TILEB;
#pragma unroll
            for (int i = 0; i < 4; i++) {
                int e = t + i * 128;
                int row = e >> 3, c = e & 7;
                cp16(dbase + row * (AP * 2) + c * 16, src + (size_t)row * CD + c * 8);
            }
        }
        cp_commit();
    };

    for (int half = 0; half < 2; half++) {
        const int qt = half ? (31 - (int)blockIdx.x) : (int)blockIdx.x;
        const int q0 = qt * 64;
        __syncthreads();

        load_kv(0, 0);
#pragma unroll
        for (int a = 0; a < 2; a++) {
            const bf16* src = (a ? Ql : Qh) + base + (size_t)q0 * CD;
            char* dst = sm + a * TILEB;
#pragma unroll
            for (int i = 0; i < 4; i++) {
                int e = t + i * 128;
                int row = e >> 3, c = e & 7;
                *(uint4*)(dst + row * (AP * 2) + c * 16) =
                    *(const uint4*)(src + (size_t)row * CD + c * 8);
            }
        }
        __syncthreads();

        uint32_t qfh[4][4], qfl[4][4];
        {
            const uint32_t aoff =
                (uint32_t)((w * 16 + (lane & 7) + ((lane >> 3) & 1) * 8) * (AP * 2) +
                           (lane >> 4) * 16);
#pragma unroll
            for (int ks = 0; ks < 4; ks++) {
                ldsm4(qfh[ks], qU + aoff + ks * 32);
                ldsm4(qfl[ks], qU + TILEB + aoff + ks * 32);
            }
        }

        float acc[8][4] = {};
        float m_0 = -1e30f, m_1 = -1e30f, l_0 = 0.f, l_1 = 0.f;
        const int rl0 = w * 16 + (lane >> 2);

        for (int kt = 0; kt <= qt; kt++) {
            const int buf = kt & 1;
            const bool more = kt < qt;
            if (more) { load_kv(buf ^ 1, kt + 1); cp_wait<1>(); }
            else      { cp_wait<0>(); }
            __syncthreads();

            const uint32_t kBufH = kvU + (buf * 4 + 0) * TILEB;
            const uint32_t kBufL = kvU + (buf * 4 + 1) * TILEB;
            const uint32_t vBufH = kvU + (buf * 4 + 2) * TILEB;
            const uint32_t vBufL = kvU + (buf * 4 + 3) * TILEB;

            float st[8][4] = {};
#pragma unroll
            for (int ks = 0; ks < 4; ks++) {
                uint32_t kh4[4][4], kl4[4][4];
#pragma unroll
                for (int nt = 0; nt < 4; nt++) {
                    uint32_t ko =
                        (uint32_t)((nt * 16 + (lane & 7) + (lane >> 4) * 8) * (AP * 2) +
                                   ((lane >> 3) & 1) * 16 + ks * 32);
                    ldsm4(kh4[nt], kBufH + ko);
                    ldsm4(kl4[nt], kBufL + ko);
                }
#pragma unroll
                for (int ni = 0; ni < 8; ni++) {
                    const uint32_t* bhp = &kh4[ni >> 1][(ni & 1) * 2];
                    const uint32_t* blp = &kl4[ni >> 1][(ni & 1) * 2];
                    mma16816(st[ni], qfh[ks], bhp);
                    mma16816(st[ni], qfl[ks], bhp);
                    mma16816(st[ni], qfh[ks], blp);
                }
            }

#pragma unroll
            for (int ni = 0; ni < 8; ni++)
#pragma unroll
                for (int e = 0; e < 4; e++) st[ni][e] *= 0.125f;
            if (kt == qt) {
#pragma unroll
                for (int ni = 0; ni < 8; ni++) {
                    int cb = ni * 8 + (lane & 3) * 2;
                    if (cb > rl0)         st[ni][0] = -1e30f;
                    if (cb + 1 > rl0)     st[ni][1] = -1e30f;
                    if (cb > rl0 + 8)     st[ni][2] = -1e30f;
                    if (cb + 1 > rl0 + 8) st[ni][3] = -1e30f;
                }
            }

            float t0 = -1e30f, t1 = -1e30f;
#pragma unroll
            for (int ni = 0; ni < 8; ni++) {
                t0 = fmaxf(t0, fmaxf(st[ni][0], st[ni][1]));
                t1 = fmaxf(t1, fmaxf(st[ni][2], st[ni][3]));
            }
            t0 = fmaxf(t0, __shfl_xor_sync(0xffffffffu, t0, 1));
            t0 = fmaxf(t0, __shfl_xor_sync(0xffffffffu, t0, 2));
            t1 = fmaxf(t1, __shfl_xor_sync(0xffffffffu, t1, 1));
            t1 = fmaxf(t1, __shfl_xor_sync(0xffffffffu, t1, 2));
            float mn0 = fmaxf(m_0, t0), mn1 = fmaxf(m_1, t1);
            float fr0 = __expf(m_0 - mn0), fr1 = __expf(m_1 - mn1);
            m_0 = mn0; m_1 = mn1;
            float ps0 = 0.f, ps1 = 0.f;
#pragma unroll
            for (int ni = 0; ni < 8; ni++) {
                float p0 = __expf(st[ni][0] - mn0); st[ni][0] = p0; ps0 += p0;
                float p1 = __expf(st[ni][1] - mn0); st[ni][1] = p1; ps0 += p1;
                float p2 = __expf(st[ni][2] - mn1); st[ni][2] = p2; ps1 += p2;
                float p3 = __expf(st[ni][3] - mn1); st[ni][3] = p3; ps1 += p3;
            }
            ps0 += __shfl_xor_sync(0xffffffffu, ps0, 1);
            ps0 += __shfl_xor_sync(0xffffffffu, ps0, 2);
            ps1 += __shfl_xor_sync(0xffffffffu, ps1, 1);
            ps1 += __shfl_xor_sync(0xffffffffu, ps1, 2);
            l_0 = l_0 * fr0 + ps0;
            l_1 = l_1 * fr1 + ps1;
#pragma unroll
            for (int ni = 0; ni < 8; ni++) {
                acc[ni][0] *= fr0; acc[ni][1] *= fr0;
                acc[ni][2] *= fr1; acc[ni][3] *= fr1;
            }

#pragma unroll
            for (int ks = 0; ks < 4; ks++) {
                uint32_t pah[4], pal[4];
                split2(st[2 * ks][0],     st[2 * ks][1],     pah[0], pal[0]);
                split2(st[2 * ks][2],     st[2 * ks][3],     pah[1], pal[1]);
                split2(st[2 * ks + 1][0], st[2 * ks + 1][1], pah[2], pal[2]);
                split2(st[2 * ks + 1][2], st[2 * ks + 1][3], pah[3], pal[3]);
                uint32_t vh4[4][4], vl4[4][4];
#pragma unroll
                for (int vt = 0; vt < 4; vt++) {
                    uint32_t vo =
                        (uint32_t)(((lane & 7) + ((lane >> 3) & 1) * 8 + ks * 16) * (AP * 2) +
                                   (vt * 16 + (lane >> 4) * 8) * 2);
                    ldsm4t(vh4[vt], vBufH + vo);
                    ldsm4t(vl4[vt], vBufL + vo);
                }
#pragma unroll
                for (int ni = 0; ni < 8; ni++) {
                    const uint32_t* vhp = &vh4[ni >> 1][(ni & 1) * 2];
                    const uint32_t* vlp = &vl4[ni >> 1][(ni & 1) * 2];
                    mma16816(acc[ni], pah, vhp);
                    mma16816(acc[ni], pal, vhp);
                    mma16816(acc[ni], pah, vlp);
                }
            }
            __syncthreads();
        }

        float i0 = 1.f / l_0, i1 = 1.f / l_1;
        const int r0 = q0 + rl0;
#pragma unroll
        for (int ni = 0; ni < 8; ni++) {
            int col = ni * 8 + (lane & 3) * 2;
            size_t o = base + (size_t)r0 * CD + col;
            uint32_t hh, ll;
            split2(acc[ni][0] * i0, acc[ni][1] * i0, hh, ll);
            *(uint32_t*)(Ath + o) = hh;
            *(uint32_t*)(Atl + o) = ll;
            split2(acc[ni][2] * i1, acc[ni][3] * i1, hh, ll);
            *(uint32_t*)(Ath + o + (size_t)8 * CD) = hh;
            *(uint32_t*)(Atl + o + (size_t)8 * CD) = ll;
        }
    }
}

// ----------------------------------------------------------------------------
// Embedding / LayerNorm
// ----------------------------------------------------------------------------
__global__ void embed_kernel(const int* __restrict__ ids,
                             const float* __restrict__ tok,
                             const float* __restrict__ pos,
                             float* __restrict__ h) {
    int i = blockIdx.x;
    int d = threadIdx.x;
    int s = i & (CS - 1);
    h[(size_t)i * CD + d] = tok[(size_t)ids[i] * CD + d] + pos[(size_t)s * CD + d];
}

__global__ void ln_kernel(const float* __restrict__ x,
                          const float* __restrict__ sc,
                          const float* __restrict__ bi,
                          bf16* __restrict__ yh, bf16* __restrict__ yl) {
    int row = blockIdx.x * 8 + threadIdx.y;   // blockDim (32, 8)
    int lane = threadIdx.x;
    const float* xr = x + (size_t)row * CD;
    float v[8];
    float sum = 0.f, sq = 0.f;
#pragma unroll
    for (int j = 0; j < 8; j++) {
        v[j] = xr[lane * 8 + j];
        sum += v[j];
        sq += v[j] * v[j];
    }
#pragma unroll
    for (int o = 16; o > 0; o >>= 1) {
        sum += __shfl_xor_sync(0xffffffffu, sum, o);
        sq  += __shfl_xor_sync(0xffffffffu, sq, o);
    }
    float mean = sum * (1.f / CD);
    float var  = sq * (1.f / CD) - mean * mean;
    float inv  = rsqrtf(var + 1e-5f);
    size_t off = (size_t)row * CD + lane * 8;
    uint32_t hbuf[4], lbuf[4];
#pragma unroll
    for (int j = 0; j < 4; j++) {
        int c = lane * 8 + 2 * j;
        float y0 = (v[2 * j]     - mean) * inv * sc[c]     + bi[c];
        float y1 = (v[2 * j + 1] - mean) * inv * sc[c + 1] + bi[c + 1];
        split2(y0, y1, hbuf[j], lbuf[j]);
    }
    *(uint4*)(yh + off) = make_uint4(hbuf[0], hbuf[1], hbuf[2], hbuf[3]);
    *(uint4*)(yl + off) = make_uint4(lbuf[0], lbuf[1], lbuf[2], lbuf[3]);
}

// ----------------------------------------------------------------------------
// Orchestration
// ----------------------------------------------------------------------------
extern "C" void kernel_launch(void* const* d_in, const int* in_sizes, int n_in,
                              void* d_out, int out_size) {
    const int*   ids  = (const int*)d_in[0];
    const float* tok  = (const float*)d_in[1];
    const float* pos  = (const float*)d_in[2];
    const float* Wq   = (const float*)d_in[3];
    const float* bq   = (const float*)d_in[4];
    const float* Wk   = (const float*)d_in[5];
    const float* bk   = (const float*)d_in[6];
    const float* Wv   = (const float*)d_in[7];
    const float* bv   = (const float*)d_in[8];
    const float* Wo   = (const float*)d_in[9];
    const float* bo   = (const float*)d_in[10];
    const float* ln1s = (const float*)d_in[11];
    const float* ln1b = (const float*)d_in[12];
    const float* ln2s = (const float*)d_in[13];
    const float* ln2b = (const float*)d_in[14];
    const float* W1   = (const float*)d_in[15];
    const float* b1   = (const float*)d_in[16];
    const float* W2   = (const float*)d_in[17];
    const float* b2   = (const float*)d_in[18];
    const float* lnfs = (const float*)d_in[19];
    const float* lnfb = (const float*)d_in[20];
    float* out = (float*)d_out;

    float* h;
    bf16 *nh, *nl, *ath, *atl, *mh, *ml, *qh, *ql, *kh, *kl, *vh, *vl;
    bf16 *th, *tl, *wqh, *wql, *wkh, *wkl, *wvh, *wvl, *woh, *wol;
    bf16 *w1h, *w1l, *w2h, *w2l;
    cudaGetSymbolAddress((void**)&h,   g_h);
    cudaGetSymbolAddress((void**)&nh,  g_nh);   cudaGetSymbolAddress((void**)&nl,  g_nl);
    cudaGetSymbolAddress((void**)&ath, g_ath);  cudaGetSymbolAddress((void**)&atl, g_atl);
    cudaGetSymbolAddress((void**)&mh,  g_mh);   cudaGetSymbolAddress((void**)&ml,  g_ml);
    cudaGetSymbolAddress((void**)&qh,  g_qh);   cudaGetSymbolAddress((void**)&ql,  g_ql);
    cudaGetSymbolAddress((void**)&kh,  g_kh);   cudaGetSymbolAddress((void**)&kl,  g_kl);
    cudaGetSymbolAddress((void**)&vh,  g_vh);   cudaGetSymbolAddress((void**)&vl,  g_vl);
    cudaGetSymbolAddress((void**)&th,  g_th);   cudaGetSymbolAddress((void**)&tl,  g_tl);
    cudaGetSymbolAddress((void**)&wqh, g_wqh);  cudaGetSymbolAddress((void**)&wql, g_wql);
    cudaGetSymbolAddress((void**)&wkh, g_wkh);  cudaGetSymbolAddress((void**)&wkl, g_wkl);
    cudaGetSymbolAddress((void**)&wvh, g_wvh);  cudaGetSymbolAddress((void**)&wvl, g_wvl);
    cudaGetSymbolAddress((void**)&woh, g_woh);  cudaGetSymbolAddress((void**)&wol, g_wol);
    cudaGetSymbolAddress((void**)&w1h, g_w1h);  cudaGetSymbolAddress((void**)&w1l, g_w1l);
    cudaGetSymbolAddress((void**)&w2h, g_w2h);  cudaGetSymbolAddress((void**)&w2l, g_w2l);

    cudaFuncSetAttribute(attn_kernel,
                         cudaFuncAttributeMaxDynamicSharedMemorySize, ATTN_SMEM);
    cudaFuncSetAttribute(gemm_res_kernel,
                         cudaFuncAttributeMaxDynamicSharedMemorySize, SMEM_RES);
    cudaFuncSetAttribute(gemm_gelu_kernel,
                         cudaFuncAttributeMaxDynamicSharedMemorySize, SMEM_BIG);
    cudaFuncSetAttribute(qkv_kernel,
                         cudaFuncAttributeMaxDynamicSharedMemorySize, SMEM_BIG);
    cudaFuncSetAttribute(lmhead_kernel,
                         cudaFuncAttributeMaxDynamicSharedMemorySize, SMEM_LMH);

    split_all_kernel<<<(unsigned)((NP_TOT + 255) / 256), 256>>>(
        tok, Wq, Wk, Wv, Wo, W1, W2,
        th, tl, wqh, wql, wkh, wkl, wvh, wvl, woh, wol, w1h, w1l, w2h, w2l);

    dim3 lnb(32, 8);
    embed_kernel<<<CM, CD>>>(ids, tok, pos, h);

    for (int l = 0; l < CL; l++) {
        size_t wofs  = (size_t)l * CD * CD;
        size_t bofs  = (size_t)l * CD;
        size_t w1ofs = (size_t)l * CD * CFF;
        size_t b1ofs = (size_t)l * CFF;
        size_t w2ofs = (size_t)l * CFF * CD;

        ln_kernel<<<CM / 8, lnb>>>(h, ln1s + bofs, ln1b + bofs, nh, nl);
        qkv_kernel<<<dim3(CD / 128, CM / 256, 3), 256, SMEM_BIG>>>(
            nh, nl, wqh + wofs, wql + wofs, wkh + wofs, wkl + wofs,
            wvh + wofs, wvl + wofs, bq + bofs, bk + bofs, bv + bofs,
            qh, ql, kh, kl, vh, vl);

        attn_kernel<<<dim3(16, CB * CH), 128, ATTN_SMEM>>>(
            qh, ql, kh, kl, vh, vl, ath, atl);

        gemm_res_kernel<<<dim3(CD / 64, CM / 128), 256, SMEM_RES>>>(
            ath, atl, woh + wofs, wol + wofs, bo + bofs, h, h, CD, CD);

        ln_kernel<<<CM / 8, lnb>>>(h, ln2s + bofs, ln2b + bofs, nh, nl);
        gemm_gelu_kernel<<<dim3(CFF / 128, CM / 256), 256, SMEM_BIG>>>(
            nh, nl, w1h + w1ofs, w1l + w1ofs, b1 + b1ofs, mh, ml, CFF, CD);
        gemm_res_kernel<<<dim3(CD / 64, CM / 128), 256, SMEM_RES>>>(
            mh, ml, w2h + w2ofs, w2l + w2ofs, b2 + bofs, h, h, CD, CFF);
    }

    ln_kernel<<<CM / 8, lnb>>>(h, lnfs, lnfb, nh, nl);
    lmhead_kernel<<<dim3(CM / 256, (CV + 127) / 128), 256, SMEM_LMH>>>(
        nh, nl, th, tl, out);
}

// round 11
// speedup vs baseline: 3.9663x; 1.2289x over previous
#include <cuda_runtime.h>
#include <cuda_bf16.h>
#include <cuda_fp16.h>
#include <math.h>
#include <stdint.h>

typedef __nv_bfloat16 bf16;

// Problem constants
constexpr int CB = 2, CS = 2048, CD = 256, CH = 4, CL = 4, CV = 50257, CHD = 64;
constexpr int CM = CB * CS;      // 4096 rows
constexpr int CFF = 4 * CD;      // 1024

// ----------------------------------------------------------------------------
// Scratch (static device globals — no allocation inside kernel_launch)
// ----------------------------------------------------------------------------
__device__ float g_h[CM * CD];
__device__ bf16 g_nh[CM * CD],  g_nl[CM * CD];
__device__ __half g_nf[CM * CD];                      // final-LN fp16 (lm_head A)
__device__ bf16 g_ath[CM * CD], g_atl[CM * CD];
__device__ bf16 g_mh[CM * CFF], g_ml[CM * CFF];
__device__ bf16 g_qh[CM * CD], g_ql[CM * CD];
__device__ bf16 g_kh[CM * CD], g_kl[CM * CD];
__device__ bf16 g_vh[CM * CD], g_vl[CM * CD];
__device__ __half g_tf[(size_t)CV * CD];              // tok_emb fp16 (lm_head B)
__device__ bf16 g_wqh[CL * CD * CD],  g_wql[CL * CD * CD];
__device__ bf16 g_wkh[CL * CD * CD],  g_wkl[CL * CD * CD];
__device__ bf16 g_wvh[CL * CD * CD],  g_wvl[CL * CD * CD];
__device__ bf16 g_woh[CL * CD * CD],  g_wol[CL * CD * CD];
__device__ bf16 g_w1h[CL * CD * CFF], g_w1l[CL * CD * CFF];
__device__ bf16 g_w2h[CL * CD * CFF], g_w2l[CL * CD * CFF];

// ----------------------------------------------------------------------------
// Helpers
// ----------------------------------------------------------------------------
__device__ __forceinline__ uint32_t smem_u32(const void* p) {
    uint32_t a;
    asm("{ .reg .u64 t; cvta.to.shared.u64 t, %1; cvt.u32.u64 %0, t; }"
        : "=r"(a) : "l"(p));
    return a;
}
__device__ __forceinline__ void ldsm4(uint32_t* r, uint32_t addr) {
    asm volatile("ldmatrix.sync.aligned.m8n8.x4.shared.b16 {%0,%1,%2,%3}, [%4];"
                 : "=r"(r[0]), "=r"(r[1]), "=r"(r[2]), "=r"(r[3]) : "r"(addr));
}
__device__ __forceinline__ void ldsm4t(uint32_t* r, uint32_t addr) {
    asm volatile("ldmatrix.sync.aligned.m8n8.x4.trans.shared.b16 {%0,%1,%2,%3}, [%4];"
                 : "=r"(r[0]), "=r"(r[1]), "=r"(r[2]), "=r"(r[3]) : "r"(addr));
}
__device__ __forceinline__ void mma16816(float* c, const uint32_t* a, const uint32_t* b) {
    asm volatile("mma.sync.aligned.m16n8k16.row.col.f32.bf16.bf16.f32 "
                 "{%0,%1,%2,%3}, {%4,%5,%6,%7}, {%8,%9}, {%0,%1,%2,%3};"
                 : "+f"(c[0]), "+f"(c[1]), "+f"(c[2]), "+f"(c[3])
                 : "r"(a[0]), "r"(a[1]), "r"(a[2]), "r"(a[3]),
                   "r"(b[0]), "r"(b[1]));
}
__device__ __forceinline__ void mma16816h(float* c, const uint32_t* a, const uint32_t* b) {
    asm volatile("mma.sync.aligned.m16n8k16.row.col.f32.f16.f16.f32 "
                 "{%0,%1,%2,%3}, {%4,%5,%6,%7}, {%8,%9}, {%0,%1,%2,%3};"
                 : "+f"(c[0]), "+f"(c[1]), "+f"(c[2]), "+f"(c[3])
                 : "r"(a[0]), "r"(a[1]), "r"(a[2]), "r"(a[3]),
                   "r"(b[0]), "r"(b[1]));
}
__device__ __forceinline__ void split2(float x, float y, uint32_t& h, uint32_t& l) {
    asm("cvt.rn.bf16x2.f32 %0, %1, %2;" : "=r"(h) : "f"(y), "f"(x));
    float hx = __uint_as_float(h << 16);
    float hy = __uint_as_float(h & 0xFFFF0000u);
    float lx = x - hx, ly = y - hy;
    asm("cvt.rn.bf16x2.f32 %0, %1, %2;" : "=r"(l) : "f"(ly), "f"(lx));
}
__device__ __forceinline__ void cp16(uint32_t dst, const void* src) {
    asm volatile("cp.async.ca.shared.global [%0], [%1], 16;" :: "r"(dst), "l"(src));
}
__device__ __forceinline__ void cp_commit() {
    asm volatile("cp.async.commit_group;" ::: "memory");
}
template <int N>
__device__ __forceinline__ void cp_wait() {
    asm volatile("cp.async.wait_group %0;" :: "n"(N) : "memory");
}

// ----------------------------------------------------------------------------
// Merged one-launch weight splitter (tok -> fp16; weights -> bf16 hi/lo)
// ----------------------------------------------------------------------------
constexpr size_t NP_TOK = (size_t)CV * CD / 2;
constexpr size_t NP_W   = (size_t)CL * CD * CD / 2;
constexpr size_t NP_WF  = (size_t)CL * CD * CFF / 2;
constexpr size_t NP_TOT = NP_TOK + 4 * NP_W + 2 * NP_WF;

__global__ void split_all_kernel(
    const float* __restrict__ tok, const float* __restrict__ Wq,
    const float* __restrict__ Wk, const float* __restrict__ Wv,
    const float* __restrict__ Wo, const float* __restrict__ W1,
    const float* __restrict__ W2,
    __half* __restrict__ tf,
    bf16* __restrict__ wqh, bf16* __restrict__ wql,
    bf16* __restrict__ wkh, bf16* __restrict__ wkl,
    bf16* __restrict__ wvh, bf16* __restrict__ wvl,
    bf16* __restrict__ woh, bf16* __restrict__ wol,
    bf16* __restrict__ w1h, bf16* __restrict__ w1l,
    bf16* __restrict__ w2h, bf16* __restrict__ w2l) {
    size_t i = (size_t)blockIdx.x * blockDim.x + threadIdx.x;
    if (i >= NP_TOT) return;
    if (i < NP_TOK) {
        float2 x = *(const float2*)(tok + 2 * i);
        __half2 p = __floats2half2_rn(x.x, x.y);
        *(__half2*)(tf + 2 * i) = p;
        return;
    }
    i -= NP_TOK;
    const float* src; bf16 *hi, *lo;
    if (i < NP_W)          { src = Wq; hi = wqh; lo = wql; }
    else if (i < 2 * NP_W) { i -= NP_W;     src = Wk; hi = wkh; lo = wkl; }
    else if (i < 3 * NP_W) { i -= 2 * NP_W; src = Wv; hi = wvh; lo = wvl; }
    else if (i < 4 * NP_W) { i -= 3 * NP_W; src = Wo; hi = woh; lo = wol; }
    else if (i < 4 * NP_W + NP_WF) { i -= 4 * NP_W; src = W1; hi = w1h; lo = w1l; }
    else { i -= 4 * NP_W + NP_WF; src = W2; hi = w2h; lo = w2l; }
    float2 x = *(const float2*)(src + 2 * i);
    uint32_t h, l;
    split2(x.x, x.y, h, l);
    *(uint32_t*)(hi + 2 * i) = h;
    *(uint32_t*)(lo + 2 * i) = l;
}

// ----------------------------------------------------------------------------
// All-bf16 HMMA GEMM core (3-term split), parameterized MTILE x NTILE.
// ----------------------------------------------------------------------------
template <int MTILE, int NTILE, bool TRANSB>
struct GCfg {
    static constexpr int WM = MTILE / 64;
    static constexpr int WN = 8 / WM;
    static constexpr int WARP_N = NTILE / WN;
    static constexpr int NI = WARP_N / 8;
    static constexpr int NB2 = WARP_N / 16;
    static constexpr int BPITCH = NTILE * 2 + 16;
    static constexpr int ASLOT = MTILE * 80;
    static constexpr int BSLOT = TRANSB ? NTILE * 80 : 32 * BPITCH;
    static constexpr int STAGE = 2 * ASLOT + 2 * BSLOT;
    static constexpr int SMEM = 2 * STAGE;
};

template <int MTILE, int NTILE, bool TRANSB, bool GELU, bool SPLIT>
__device__ __forceinline__ void bgemm_core(
    const bf16* __restrict__ Ah, const bf16* __restrict__ Al,
    const bf16* __restrict__ Bh, const bf16* __restrict__ Bl,
    const float* __restrict__ bias, const float* __restrict__ resid,
    float* __restrict__ C, bf16* __restrict__ Oh, bf16* __restrict__ Ol,
    int N, int K, int m0, int n0, char* smbase) {
    using CF = GCfg<MTILE, NTILE, TRANSB>;
    const int t = threadIdx.x;
    const int lane = t & 31, wid = t >> 5;
    const int wm = wid % CF::WM, wn = wid / CF::WM;
    const uint32_t sU = smem_u32(smbase);

    auto load_tile = [&](int s, int kc) {
        const int k0 = kc * 32;
        const uint32_t sb = sU + (uint32_t)(s * CF::STAGE);
#pragma unroll
        for (int comp = 0; comp < 2; comp++) {
            const bf16* src = comp ? Al : Ah;
            const uint32_t dst = sb + comp * CF::ASLOT;
#pragma unroll
            for (int i = 0; i < MTILE / 64; i++) {
                int e = t + i * 256;
                int row = e >> 2, c = e & 3;
                cp16(dst + row * 80 + c * 16,
                     src + (size_t)(m0 + row) * K + k0 + c * 8);
            }
        }
#pragma unroll
        for (int comp = 0; comp < 2; comp++) {
            const bf16* src = comp ? Bl : Bh;
            const uint32_t dst = sb + 2 * CF::ASLOT + comp * CF::BSLOT;
            if (!TRANSB) {
                constexpr int OPS = 32 * NTILE / 8;
#pragma unroll
                for (int i = 0; i < (OPS + 255) / 256; i++) {
                    int e = t + i * 256;
                    if (OPS >= 256 * (i + 1) || e < OPS) {
                        int row = e / (NTILE / 8), c = e % (NTILE / 8);
                        cp16(dst + row * CF::BPITCH + c * 16,
                             src + (size_t)(k0 + row) * N + n0 + c * 8);
                    }
                }
            } else {
#pragma unroll
                for (int i = 0; i < NTILE / 64; i++) {
                    int e = t + i * 256;
                    int row = e >> 2, c = e & 3;
                    int nr = n0 + row;
                    if (nr >= N) nr = 0;
                    cp16(dst + row * 80 + c * 16,
                         src + (size_t)nr * K + k0 + c * 8);
                }
            }
        }
        cp_commit();
    };

    const uint32_t aoff =
        (uint32_t)((wm * 64 + (lane & 7) + ((lane >> 3) & 1) * 8) * 80 +
                   (lane >> 4) * 16);
    uint32_t boff;
    if (!TRANSB)
        boff = (uint32_t)(((lane & 7) + ((lane >> 3) & 1) * 8) * CF::BPITCH +
                          (wn * CF::WARP_N + (lane >> 4) * 8) * 2);
    else
        boff = (uint32_t)((wn * CF::WARP_N + (lane & 7) + (lane >> 4) * 8) * 80 +
                          ((lane >> 3) & 1) * 16);

    float acc[4][CF::NI][4] = {};
    const int KT = K / 32;
    load_tile(0, 0);

    for (int kc = 0; kc < KT; kc++) {
        if (kc + 1 < KT) { load_tile((kc + 1) & 1, kc + 1); cp_wait<1>(); }
        else             { cp_wait<0>(); }
        __syncthreads();
        const uint32_t sb = sU + (uint32_t)((kc & 1) * CF::STAGE);
        const uint32_t sAh = sb, sAl = sb + CF::ASLOT;
        const uint32_t sBh = sb + 2 * CF::ASLOT, sBl = sBh + CF::BSLOT;
#pragma unroll
        for (int ks = 0; ks < 2; ks++) {
            uint32_t ah[4][4], al[4][4], bh[CF::NB2][4], bl[CF::NB2][4];
#pragma unroll
            for (int mi = 0; mi < 4; mi++) {
                ldsm4(ah[mi], sAh + aoff + mi * (16 * 80) + ks * 32);
                ldsm4(al[mi], sAl + aoff + mi * (16 * 80) + ks * 32);
            }
#pragma unroll
            for (int n2 = 0; n2 < CF::NB2; n2++) {
                if (!TRANSB) {
                    ldsm4t(bh[n2], sBh + boff + n2 * 32 + ks * (16 * CF::BPITCH));
                    ldsm4t(bl[n2], sBl + boff + n2 * 32 + ks * (16 * CF::BPITCH));
                } else {
                    ldsm4(bh[n2], sBh + boff + n2 * (16 * 80) + ks * 32);
                    ldsm4(bl[n2], sBl + boff + n2 * (16 * 80) + ks * 32);
                }
            }
#pragma unroll
            for (int mi = 0; mi < 4; mi++)
#pragma unroll
                for (int ni = 0; ni < CF::NI; ni++) {
                    const uint32_t* bhp = &bh[ni >> 1][(ni & 1) * 2];
                    const uint32_t* blp = &bl[ni >> 1][(ni & 1) * 2];
                    mma16816(acc[mi][ni], ah[mi], bhp);
                    mma16816(acc[mi][ni], al[mi], bhp);
                    mma16816(acc[mi][ni], ah[mi], blp);
                }
        }
        __syncthreads();
    }

#pragma unroll
    for (int mi = 0; mi < 4; mi++) {
        const int r0 = m0 + wm * 64 + mi * 16 + (lane >> 2);
#pragma unroll
        for (int ni = 0; ni < CF::NI; ni++) {
            const int col = n0 + wn * CF::WARP_N + ni * 8 + (lane & 3) * 2;
            float v0 = acc[mi][ni][0], v1 = acc[mi][ni][1];
            float v2 = acc[mi][ni][2], v3 = acc[mi][ni][3];
            if (bias) {
                float b0 = (!TRANSB || col < N) ? bias[col] : 0.f;
                float b1 = (!TRANSB || col + 1 < N) ? bias[col + 1] : 0.f;
                v0 += b0; v1 += b1; v2 += b0; v3 += b1;
            }
            if (GELU) {
                v0 = 0.5f * v0 * (1.f + erff(v0 * 0.70710678118654752f));
                v1 = 0.5f * v1 * (1.f + erff(v1 * 0.70710678118654752f));
                v2 = 0.5f * v2 * (1.f + erff(v2 * 0.70710678118654752f));
                v3 = 0.5f * v3 * (1.f + erff(v3 * 0.70710678118654752f));
            }
            size_t o0 = (size_t)r0 * N + col;
            size_t o1 = o0 + (size_t)8 * N;
            if (SPLIT) {
                uint32_t hh, ll;
                split2(v0, v1, hh, ll);
                *(uint32_t*)(Oh + o0) = hh;
                *(uint32_t*)(Ol + o0) = ll;
                split2(v2, v3, hh, ll);
                *(uint32_t*)(Oh + o1) = hh;
                *(uint32_t*)(Ol + o1) = ll;
            } else if (!TRANSB) {
                if (resid) {
                    float2 rr0 = *(const float2*)(resid + o0);
                    float2 rr1 = *(const float2*)(resid + o1);
                    v0 += rr0.x; v1 += rr0.y; v2 += rr1.x; v3 += rr1.y;
                }
                *(float2*)(C + o0) = make_float2(v0, v1);
                *(float2*)(C + o1) = make_float2(v2, v3);
            } else {
                if (col < N)     { C[o0] = v0; C[o1] = v2; }
                if (col + 1 < N) { C[o0 + 1] = v1; C[o1 + 1] = v3; }
            }
        }
    }
}

// Wo / W2: 128x64 tiles, fp32 + residual
constexpr int SMEM_RES = GCfg<128, 64, false>::SMEM;
__global__ __launch_bounds__(256, 1)
void gemm_res_kernel(const bf16* __restrict__ Ah, const bf16* __restrict__ Al,
                     const bf16* __restrict__ Bh, const bf16* __restrict__ Bl,
                     const float* __restrict__ bias, const float* __restrict__ resid,
                     float* __restrict__ C, int N, int K) {
    extern __shared__ char sm[];
    bgemm_core<128, 64, false, false, false>(Ah, Al, Bh, Bl, bias, resid, C,
                                             nullptr, nullptr, N, K,
                                             blockIdx.y * 128, blockIdx.x * 64, sm);
}

// W1: 256x128 tiles, GELU + split-bf16 output
constexpr int SMEM_BIG = GCfg<256, 128, false>::SMEM;
__global__ __launch_bounds__(256, 1)
void gemm_gelu_kernel(const bf16* __restrict__ Ah, const bf16* __restrict__ Al,
                      const bf16* __restrict__ Bh, const bf16* __restrict__ Bl,
                      const float* __restrict__ bias,
                      bf16* __restrict__ Oh, bf16* __restrict__ Ol, int N, int K) {
    extern __shared__ char sm[];
    bgemm_core<256, 128, false, true, true>(Ah, Al, Bh, Bl, bias, nullptr, nullptr,
                                            Oh, Ol, N, K,
                                            blockIdx.y * 256, blockIdx.x * 128, sm);
}

// QKV fused: 256x128 tiles
__global__ __launch_bounds__(256, 1)
void qkv_kernel(const bf16* __restrict__ Ah, const bf16* __restrict__ Al,
                const bf16* __restrict__ Wh0, const bf16* __restrict__ Wl0,
                const bf16* __restrict__ Wh1, const bf16* __restrict__ Wl1,
                const bf16* __restrict__ Wh2, const bf16* __restrict__ Wl2,
                const float* __restrict__ c0, const float* __restrict__ c1,
                const float* __restrict__ c2,
                bf16* __restrict__ qh, bf16* __restrict__ ql,
                bf16* __restrict__ kh, bf16* __restrict__ kl,
                bf16* __restrict__ vh, bf16* __restrict__ vl) {
    extern __shared__ char sm[];
    int z = blockIdx.z;
    const bf16* Bh = (z == 0) ? Wh0 : (z == 1) ? Wh1 : Wh2;
    const bf16* Bl = (z == 0) ? Wl0 : (z == 1) ? Wl1 : Wl2;
    const float* bi = (z == 0) ? c0 : (z == 1) ? c1 : c2;
    bf16* oh = (z == 0) ? qh : (z == 1) ? kh : vh;
    bf16* ol = (z == 0) ? ql : (z == 1) ? kl : vl;
    bgemm_core<256, 128, false, false, true>(Ah, Al, Bh, Bl, bi, nullptr, nullptr,
                                             oh, ol, CD, CD,
                                             blockIdx.y * 256, blockIdx.x * 128, sm);
}

// ----------------------------------------------------------------------------
// lm_head: SINGLE-TERM fp16 HMMA. out[4096, 50257] = nf @ tf^T.
// 256x128 tile, 8 warps (4x2), warp 64x64. 2-stage cp.async. m-fast grid.
// ----------------------------------------------------------------------------
constexpr int LMH_ASLOT = 256 * 80;
constexpr int LMH_BSLOT = 128 * 80;
constexpr int LMH_STAGE = LMH_ASLOT + LMH_BSLOT;
constexpr int SMEM_LMH = 2 * LMH_STAGE;

__global__ __launch_bounds__(256, 1)
void lmhead_f16_kernel(const __half* __restrict__ Af, const __half* __restrict__ Bf,
                       float* __restrict__ out) {
    extern __shared__ char sm[];
    const int t = threadIdx.x;
    const int lane = t & 31, wid = t >> 5;
    const int wm = wid & 3, wn = wid >> 2;      // 4x2 warps
    const int m0 = blockIdx.x * 256;
    const int n0 = blockIdx.y * 128;
    const int N = CV, K = CD;
    const uint32_t sU = smem_u32(sm);

    auto load_tile = [&](int s, int kc) {
        const int k0 = kc * 32;
        const uint32_t sb = sU + (uint32_t)(s * LMH_STAGE);
        // A: 256 rows x 32 k (fp16)
#pragma unroll
        for (int i = 0; i < 4; i++) {
            int e = t + i * 256;
            int row = e >> 2, c = e & 3;
            cp16(sb + row * 80 + c * 16, Af + (size_t)(m0 + row) * K + k0 + c * 8);
        }
        // B: 128 n-rows x 32 k (fp16), clamped
#pragma unroll
        for (int i = 0; i < 2; i++) {
            int e = t + i * 256;
            int row = e >> 2, c = e & 3;
            int nr = n0 + row;
            if (nr >= N) nr = 0;
            cp16(sb + LMH_ASLOT + row * 80 + c * 16,
                 Bf + (size_t)nr * K + k0 + c * 8);
        }
        cp_commit();
    };

    const uint32_t aoff =
        (uint32_t)((wm * 64 + (lane & 7) + ((lane >> 3) & 1) * 8) * 80 +
                   (lane >> 4) * 16);
    const uint32_t boff =
        (uint32_t)((wn * 64 + (lane & 7) + (lane >> 4) * 8) * 80 +
                   ((lane >> 3) & 1) * 16);

    float acc[4][8][4] = {};
    load_tile(0, 0);

    for (int kc = 0; kc < K / 32; kc++) {
        if (kc + 1 < K / 32) { load_tile((kc + 1) & 1, kc + 1); cp_wait<1>(); }
        else                 { cp_wait<0>(); }
        __syncthreads();
        const uint32_t sb = sU + (uint32_t)((kc & 1) * LMH_STAGE);
#pragma unroll
        for (int ks = 0; ks < 2; ks++) {
            uint32_t ah[4][4], bh[4][4];
#pragma unroll
            for (int mi = 0; mi < 4; mi++)
                ldsm4(ah[mi], sb + aoff + mi * (16 * 80) + ks * 32);
#pragma unroll
            for (int n2 = 0; n2 < 4; n2++)
                ldsm4(bh[n2], sb + LMH_ASLOT + boff + n2 * (16 * 80) + ks * 32);
#pragma unroll
            for (int mi = 0; mi < 4; mi++)
#pragma unroll
                for (int ni = 0; ni < 8; ni++)
                    mma16816h(acc[mi][ni], ah[mi], &bh[ni >> 1][(ni & 1) * 2]);
        }
        __syncthreads();
    }

#pragma unroll
    for (int mi = 0; mi < 4; mi++) {
        const int r0 = m0 + wm * 64 + mi * 16 + (lane >> 2);
#pragma unroll
        for (int ni = 0; ni < 8; ni++) {
            const int col = n0 + wn * 64 + ni * 8 + (lane & 3) * 2;
            size_t o0 = (size_t)r0 * N + col;
            size_t o1 = o0 + (size_t)8 * N;
            if (col < N)     { out[o0] = acc[mi][ni][0]; out[o1] = acc[mi][ni][2]; }
            if (col + 1 < N) { out[o0 + 1] = acc[mi][ni][1]; out[o1 + 1] = acc[mi][ni][3]; }
        }
    }
}

// ----------------------------------------------------------------------------
// HMMA flash attention, causal-folded (unchanged)
// ----------------------------------------------------------------------------
constexpr int AP = 72;
constexpr int TILEB = 64 * AP * 2;
constexpr int ATTN_SMEM = 10 * TILEB;

__global__ __launch_bounds__(128)
void attn_kernel(const bf16* __restrict__ Qh, const bf16* __restrict__ Ql,
                 const bf16* __restrict__ Kh, const bf16* __restrict__ Kl,
                 const bf16* __restrict__ Vh, const bf16* __restrict__ Vl,
                 bf16* __restrict__ Ath, bf16* __restrict__ Atl) {
    extern __shared__ char sm[];
    const uint32_t smU = smem_u32(sm);
    const uint32_t qU = smU;
    const uint32_t kvU = smU + 2 * TILEB;

    const int t = threadIdx.x;
    const int lane = t & 31, w = t >> 5;
    const int bh = blockIdx.y;
    const int b = bh >> 2, h = bh & 3;
    const size_t base = (size_t)b * CS * CD + (size_t)h * CHD;

    auto load_kv = [&](int buf, int kt) {
        const int k0 = kt * 64;
#pragma unroll
        for (int a = 0; a < 4; a++) {
            const bf16* src =
                ((a == 0) ? Kh : (a == 1) ? Kl : (a == 2) ? Vh : Vl) +
                base + (size_t)k0 * CD;
            const uint32_t dbase = kvU + (buf * 4 + a) * TILEB;
#pragma unroll
            for (int i = 0; i < 4; i++) {
                int e = t + i * 128;
                int row = e >> 3, c = e & 7;
                cp16(dbase + row * (AP * 2) + c * 16, src + (size_t)row * CD + c * 8);
            }
        }
        cp_commit();
    };

    for (int half = 0; half < 2; half++) {
        const int qt = half ? (31 - (int)blockIdx.x) : (int)blockIdx.x;
        const int q0 = qt * 64;
        __syncthreads();

        load_kv(0, 0);
#pragma unroll
        for (int a = 0; a < 2; a++) {
            const bf16* src = (a ? Ql : Qh) + base + (size_t)q0 * CD;
            char* dst = sm + a * TILEB;
#pragma unroll
            for (int i = 0; i < 4; i++) {
                int e = t + i * 128;
                int row = e >> 3, c = e & 7;
                *(uint4*)(dst + row * (AP * 2) + c * 16) =
                    *(const uint4*)(src + (size_t)row * CD + c * 8);
            }
        }
        __syncthreads();

        uint32_t qfh[4][4], qfl[4][4];
        {
            const uint32_t aoff =
                (uint32_t)((w * 16 + (lane & 7) + ((lane >> 3) & 1) * 8) * (AP * 2) +
                           (lane >> 4) * 16);
#pragma unroll
            for (int ks = 0; ks < 4; ks++) {
                ldsm4(qfh[ks], qU + aoff + ks * 32);
                ldsm4(qfl[ks], qU + TILEB + aoff + ks * 32);
            }
        }

        float acc[8][4] = {};
        float m_0 = -1e30f, m_1 = -1e30f, l_0 = 0.f, l_1 = 0.f;
        const int rl0 = w * 16 + (lane >> 2);

        for (int kt = 0; kt <= qt; kt++) {
            const int buf = kt & 1;
            const bool more = kt < qt;
            if (more) { load_kv(buf ^ 1, kt + 1); cp_wait<1>(); }
            else      { cp_wait<0>(); }
            __syncthreads();

            const uint32_t kBufH = kvU + (buf * 4 + 0) * TILEB;
            const uint32_t kBufL = kvU + (buf * 4 + 1) * TILEB;
            const uint32_t vBufH = kvU + (buf * 4 + 2) * TILEB;
            const uint32_t vBufL = kvU + (buf * 4 + 3) * TILEB;

            float st[8][4] = {};
#pragma unroll
            for (int ks = 0; ks < 4; ks++) {
                uint32_t kh4[4][4], kl4[4][4];
#pragma unroll
                for (int nt = 0; nt < 4; nt++) {
                    uint32_t ko =
                        (uint32_t)((nt * 16 + (lane & 7) + (lane >> 4) * 8) * (AP * 2) +
                                   ((lane >> 3) & 1) * 16 + ks * 32);
                    ldsm4(kh4[nt], kBufH + ko);
                    ldsm4(kl4[nt], kBufL + ko);
                }
#pragma unroll
                for (int ni = 0; ni < 8; ni++) {
                    const uint32_t* bhp = &kh4[ni >> 1][(ni & 1) * 2];
                    const uint32_t* blp = &kl4[ni >> 1][(ni & 1) * 2];
                    mma16816(st[ni], qfh[ks], bhp);
                    mma16816(st[ni], qfl[ks], bhp);
                    mma16816(st[ni], qfh[ks], blp);
                }
            }

#pragma unroll
            for (int ni = 0; ni < 8; ni++)
#pragma unroll
                for (int e = 0; e < 4; e++) st[ni][e] *= 0.125f;
            if (kt == qt) {
#pragma unroll
                for (int ni = 0; ni < 8; ni++) {
                    int cb = ni * 8 + (lane & 3) * 2;
                    if (cb > rl0)         st[ni][0] = -1e30f;
                    if (cb + 1 > rl0)     st[ni][1] = -1e30f;
                    if (cb > rl0 + 8)     st[ni][2] = -1e30f;
                    if (cb + 1 > rl0 + 8) st[ni][3] = -1e30f;
                }
            }

            float t0 = -1e30f, t1 = -1e30f;
#pragma unroll
            for (int ni = 0; ni < 8; ni++) {
                t0 = fmaxf(t0, fmaxf(st[ni][0], st[ni][1]));
                t1 = fmaxf(t1, fmaxf(st[ni][2], st[ni][3]));
            }
            t0 = fmaxf(t0, __shfl_xor_sync(0xffffffffu, t0, 1));
            t0 = fmaxf(t0, __shfl_xor_sync(0xffffffffu, t0, 2));
            t1 = fmaxf(t1, __shfl_xor_sync(0xffffffffu, t1, 1));
            t1 = fmaxf(t1, __shfl_xor_sync(0xffffffffu, t1, 2));
            float mn0 = fmaxf(m_0, t0), mn1 = fmaxf(m_1, t1);
            float fr0 = __expf(m_0 - mn0), fr1 = __expf(m_1 - mn1);
            m_0 = mn0; m_1 = mn1;
            float ps0 = 0.f, ps1 = 0.f;
#pragma unroll
            for (int ni = 0; ni < 8; ni++) {
                float p0 = __expf(st[ni][0] - mn0); st[ni][0] = p0; ps0 += p0;
                float p1 = __expf(st[ni][1] - mn0); st[ni][1] = p1; ps0 += p1;
                float p2 = __expf(st[ni][2] - mn1); st[ni][2] = p2; ps1 += p2;
                float p3 = __expf(st[ni][3] - mn1); st[ni][3] = p3; ps1 += p3;
            }
            ps0 += __shfl_xor_sync(0xffffffffu, ps0, 1);
            ps0 += __shfl_xor_sync(0xffffffffu, ps0, 2);
            ps1 += __shfl_xor_sync(0xffffffffu, ps1, 1);
            ps1 += __shfl_xor_sync(0xffffffffu, ps1, 2);
            l_0 = l_0 * fr0 + ps0;
            l_1 = l_1 * fr1 + ps1;
#pragma unroll
            for (int ni = 0; ni < 8; ni++) {
                acc[ni][0] *= fr0; acc[ni][1] *= fr0;
                acc[ni][2] *= fr1; acc[ni][3] *= fr1;
            }

#pragma unroll
            for (int ks = 0; ks < 4; ks++) {
                uint32_t pah[4], pal[4];
                split2(st[2 * ks][0],     st[2 * ks][1],     pah[0], pal[0]);
                split2(st[2 * ks][2],     st[2 * ks][3],     pah[1], pal[1]);
                split2(st[2 * ks + 1][0], st[2 * ks + 1][1], pah[2], pal[2]);
                split2(st[2 * ks + 1][2], st[2 * ks + 1][3], pah[3], pal[3]);
                uint32_t vh4[4][4], vl4[4][4];
#pragma unroll
                for (int vt = 0; vt < 4; vt++) {
                    uint32_t vo =
                        (uint32_t)(((lane & 7) + ((lane >> 3) & 1) * 8 + ks * 16) * (AP * 2) +
                                   (vt * 16 + (lane >> 4) * 8) * 2);
                    ldsm4t(vh4[vt], vBufH + vo);
                    ldsm4t(vl4[vt], vBufL + vo);
                }
#pragma unroll
                for (int ni = 0; ni < 8; ni++) {
                    const uint32_t* vhp = &vh4[ni >> 1][(ni & 1) * 2];
                    const uint32_t* vlp = &vl4[ni >> 1][(ni & 1) * 2];
                    mma16816(acc[ni], pah, vhp);
                    mma16816(acc[ni], pal, vhp);
                    mma16816(acc[ni], pah, vlp);
                }
            }
            __syncthreads();
        }

        float i0 = 1.f / l_0, i1 = 1.f / l_1;
        const int r0 = q0 + rl0;
#pragma unroll
        for (int ni = 0; ni < 8; ni++) {
            int col = ni * 8 + (lane & 3) * 2;
            size_t o = base + (size_t)r0 * CD + col;
            uint32_t hh, ll;
            split2(acc[ni][0] * i0, acc[ni][1] * i0, hh, ll);
            *(uint32_t*)(Ath + o) = hh;
            *(uint32_t*)(Atl + o) = ll;
            split2(acc[ni][2] * i1, acc[ni][3] * i1, hh, ll);
            *(uint32_t*)(Ath + o + (size_t)8 * CD) = hh;
            *(uint32_t*)(Atl + o + (size_t)8 * CD) = ll;
        }
    }
}

// ----------------------------------------------------------------------------
// Embedding / LayerNorm
// ----------------------------------------------------------------------------
__global__ void embed_kernel(const int* __restrict__ ids,
                             const float* __restrict__ tok,
                             const float* __restrict__ pos,
                             float* __restrict__ h) {
    int i = blockIdx.x;
    int d = threadIdx.x;
    int s = i & (CS - 1);
    h[(size_t)i * CD + d] = tok[(size_t)ids[i] * CD + d] + pos[(size_t)s * CD + d];
}

__global__ void ln_kernel(const float* __restrict__ x,
                          const float* __restrict__ sc,
                          const float* __restrict__ bi,
                          bf16* __restrict__ yh, bf16* __restrict__ yl,
                          __half* __restrict__ yf) {
    int row = blockIdx.x * 8 + threadIdx.y;   // blockDim (32, 8)
    int lane = threadIdx.x;
    const float* xr = x + (size_t)row * CD;
    float v[8];
    float sum = 0.f, sq = 0.f;
#pragma unroll
    for (int j = 0; j < 8; j++) {
        v[j] = xr[lane * 8 + j];
        sum += v[j];
        sq += v[j] * v[j];
    }
#pragma unroll
    for (int o = 16; o > 0; o >>= 1) {
        sum += __shfl_xor_sync(0xffffffffu, sum, o);
        sq  += __shfl_xor_sync(0xffffffffu, sq, o);
    }
    float mean = sum * (1.f / CD);
    float var  = sq * (1.f / CD) - mean * mean;
    float inv  = rsqrtf(var + 1e-5f);
    size_t off = (size_t)row * CD + lane * 8;
    float y[8];
#pragma unroll
    for (int j = 0; j < 8; j++) {
        int c = lane * 8 + j;
        y[j] = (v[j] - mean) * inv * sc[c] + bi[c];
    }
    uint32_t hbuf[4], lbuf[4];
#pragma unroll
    for (int j = 0; j < 4; j++)
        split2(y[2 * j], y[2 * j + 1], hbuf[j], lbuf[j]);
    *(uint4*)(yh + off) = make_uint4(hbuf[0], hbuf[1], hbuf[2], hbuf[3]);
    *(uint4*)(yl + off) = make_uint4(lbuf[0], lbuf[1], lbuf[2], lbuf[3]);
    if (yf) {
        __half2 f[4];
#pragma unroll
        for (int j = 0; j < 4; j++)
            f[j] = __floats2half2_rn(y[2 * j], y[2 * j + 1]);
        *(uint4*)(yf + off) = *(uint4*)f;
    }
}

// ----------------------------------------------------------------------------
// Orchestration
// ----------------------------------------------------------------------------
extern "C" void kernel_launch(void* const* d_in, const int* in_sizes, int n_in,
                              void* d_out, int out_size) {
    const int*   ids  = (const int*)d_in[0];
    const float* tok  = (const float*)d_in[1];
    const float* pos  = (const float*)d_in[2];
    const float* Wq   = (const float*)d_in[3];
    const float* bq   = (const float*)d_in[4];
    const float* Wk   = (const float*)d_in[5];
    const float* bk   = (const float*)d_in[6];
    const float* Wv   = (const float*)d_in[7];
    const float* bv   = (const float*)d_in[8];
    const float* Wo   = (const float*)d_in[9];
    const float* bo   = (const float*)d_in[10];
    const float* ln1s = (const float*)d_in[11];
    const float* ln1b = (const float*)d_in[12];
    const float* ln2s = (const float*)d_in[13];
    const float* ln2b = (const float*)d_in[14];
    const float* W1   = (const float*)d_in[15];
    const float* b1   = (const float*)d_in[16];
    const float* W2   = (const float*)d_in[17];
    const float* b2   = (const float*)d_in[18];
    const float* lnfs = (const float*)d_in[19];
    const float* lnfb = (const float*)d_in[20];
    float* out = (float*)d_out;

    float* h;
    bf16 *nh, *nl, *ath, *atl, *mh, *ml, *qh, *ql, *kh, *kl, *vh, *vl;
    bf16 *wqh, *wql, *wkh, *wkl, *wvh, *wvl, *woh, *wol;
    bf16 *w1h, *w1l, *w2h, *w2l;
    __half *tf, *nf;
    cudaGetSymbolAddress((void**)&h,   g_h);
    cudaGetSymbolAddress((void**)&nh,  g_nh);   cudaGetSymbolAddress((void**)&nl,  g_nl);
    cudaGetSymbolAddress((void**)&nf,  g_nf);
    cudaGetSymbolAddress((void**)&ath, g_ath);  cudaGetSymbolAddress((void**)&atl, g_atl);
    cudaGetSymbolAddress((void**)&mh,  g_mh);   cudaGetSymbolAddress((void**)&ml,  g_ml);
    cudaGetSymbolAddress((void**)&qh,  g_qh);   cudaGetSymbolAddress((void**)&ql,  g_ql);
    cudaGetSymbolAddress((void**)&kh,  g_kh);   cudaGetSymbolAddress((void**)&kl,  g_kl);
    cudaGetSymbolAddress((void**)&vh,  g_vh);   cudaGetSymbolAddress((void**)&vl,  g_vl);
    cudaGetSymbolAddress((void**)&tf,  g_tf);
    cudaGetSymbolAddress((void**)&wqh, g_wqh);  cudaGetSymbolAddress((void**)&wql, g_wql);
    cudaGetSymbolAddress((void**)&wkh, g_wkh);  cudaGetSymbolAddress((void**)&wkl, g_wkl);
    cudaGetSymbolAddress((void**)&wvh, g_wvh);  cudaGetSymbolAddress((void**)&wvl, g_wvl);
    cudaGetSymbolAddress((void**)&woh, g_woh);  cudaGetSymbolAddress((void**)&wol, g_wol);
    cudaGetSymbolAddress((void**)&w1h, g_w1h);  cudaGetSymbolAddress((void**)&w1l, g_w1l);
    cudaGetSymbolAddress((void**)&w2h, g_w2h);  cudaGetSymbolAddress((void**)&w2l, g_w2l);

    cudaFuncSetAttribute(attn_kernel,
                         cudaFuncAttributeMaxDynamicSharedMemorySize, ATTN_SMEM);
    cudaFuncSetAttribute(gemm_res_kernel,
                         cudaFuncAttributeMaxDynamicSharedMemorySize, SMEM_RES);
    cudaFuncSetAttribute(gemm_gelu_kernel,
                         cudaFuncAttributeMaxDynamicSharedMemorySize, SMEM_BIG);
    cudaFuncSetAttribute(qkv_kernel,
                         cudaFuncAttributeMaxDynamicSharedMemorySize, SMEM_BIG);
    cudaFuncSetAttribute(lmhead_f16_kernel,
                         cudaFuncAttributeMaxDynamicSharedMemorySize, SMEM_LMH);

    split_all_kernel<<<(unsigned)((NP_TOT + 255) / 256), 256>>>(
        tok, Wq, Wk, Wv, Wo, W1, W2,
        tf, wqh, wql, wkh, wkl, wvh, wvl, woh, wol, w1h, w1l, w2h, w2l);

    dim3 lnb(32, 8);
    embed_kernel<<<CM, CD>>>(ids, tok, pos, h);

    for (int l = 0; l < CL; l++) {
        size_t wofs  = (size_t)l * CD * CD;
        size_t bofs  = (size_t)l * CD;
        size_t w1ofs = (size_t)l * CD * CFF;
        size_t b1ofs = (size_t)l * CFF;
        size_t w2ofs = (size_t)l * CFF * CD;

        ln_kernel<<<CM / 8, lnb>>>(h, ln1s + bofs, ln1b + bofs, nh, nl, nullptr);
        qkv_kernel<<<dim3(CD / 128, CM / 256, 3), 256, SMEM_BIG>>>(
            nh, nl, wqh + wofs, wql + wofs, wkh + wofs, wkl + wofs,
            wvh + wofs, wvl + wofs, bq + bofs, bk + bofs, bv + bofs,
            qh, ql, kh, kl, vh, vl);

        attn_kernel<<<dim3(16, CB * CH), 128, ATTN_SMEM>>>(
            qh, ql, kh, kl, vh, vl, ath, atl);

        gemm_res_kernel<<<dim3(CD / 64, CM / 128), 256, SMEM_RES>>>(
            ath, atl, woh + wofs, wol + wofs, bo + bofs, h, h, CD, CD);

        ln_kernel<<<CM / 8, lnb>>>(h, ln2s + bofs, ln2b + bofs, nh, nl, nullptr);
        gemm_gelu_kernel<<<dim3(CFF / 128, CM / 256), 256, SMEM_BIG>>>(
            nh, nl, w1h + w1ofs, w1l + w1ofs, b1 + b1ofs, mh, ml, CFF, CD);
        gemm_res_kernel<<<dim3(CD / 64, CM / 128), 256, SMEM_RES>>>(
            mh, ml, w2h + w2ofs, w2l + w2ofs, b2 + bofs, h, h, CD, CFF);
    }

    ln_kernel<<<CM / 8, lnb>>>(h, lnfs, lnfb, nh, nl, nf);
    lmhead_f16_kernel<<<dim3(CM / 256, (CV + 127) / 128), 256, SMEM_LMH>>>(
        nf, tf, out);
}

// round 12
// speedup vs baseline: 5.0426x; 1.2714x over previous
#include <cuda_runtime.h>
#include <cuda_bf16.h>
#include <cuda_fp16.h>
#include <math.h>
#include <stdint.h>

// Problem constants
constexpr int CB = 2, CS = 2048, CD = 256, CH = 4, CL = 4, CV = 50257, CHD = 64;
constexpr int CM = CB * CS;      // 4096 rows
constexpr int CFF = 4 * CD;      // 1024

// ----------------------------------------------------------------------------
// Scratch (static device globals — no allocation inside kernel_launch)
// ----------------------------------------------------------------------------
__device__ float  g_h[CM * CD];
__device__ __half g_n[CM * CD];
__device__ __half g_q[CM * CD], g_k[CM * CD], g_v[CM * CD];
__device__ __half g_att[CM * CD];
__device__ __half g_m[CM * CFF];
__device__ __half g_tf[(size_t)CV * CD];
__device__ __half g_wq[CL * CD * CD], g_wk[CL * CD * CD];
__device__ __half g_wv[CL * CD * CD], g_wo[CL * CD * CD];
__device__ __half g_w1[CL * CD * CFF], g_w2[CL * CD * CFF];

// ----------------------------------------------------------------------------
// Helpers
// ----------------------------------------------------------------------------
__device__ __forceinline__ uint32_t smem_u32(const void* p) {
    uint32_t a;
    asm("{ .reg .u64 t; cvta.to.shared.u64 t, %1; cvt.u32.u64 %0, t; }"
        : "=r"(a) : "l"(p));
    return a;
}
__device__ __forceinline__ void ldsm4(uint32_t* r, uint32_t addr) {
    asm volatile("ldmatrix.sync.aligned.m8n8.x4.shared.b16 {%0,%1,%2,%3}, [%4];"
                 : "=r"(r[0]), "=r"(r[1]), "=r"(r[2]), "=r"(r[3]) : "r"(addr));
}
__device__ __forceinline__ void ldsm4t(uint32_t* r, uint32_t addr) {
    asm volatile("ldmatrix.sync.aligned.m8n8.x4.trans.shared.b16 {%0,%1,%2,%3}, [%4];"
                 : "=r"(r[0]), "=r"(r[1]), "=r"(r[2]), "=r"(r[3]) : "r"(addr));
}
__device__ __forceinline__ void mma16816h(float* c, const uint32_t* a, const uint32_t* b) {
    asm volatile("mma.sync.aligned.m16n8k16.row.col.f32.f16.f16.f32 "
                 "{%0,%1,%2,%3}, {%4,%5,%6,%7}, {%8,%9}, {%0,%1,%2,%3};"
                 : "+f"(c[0]), "+f"(c[1]), "+f"(c[2]), "+f"(c[3])
                 : "r"(a[0]), "r"(a[1]), "r"(a[2]), "r"(a[3]),
                   "r"(b[0]), "r"(b[1]));
}
__device__ __forceinline__ uint32_t pack_h2(float x, float y) {
    __half2 p = __floats2half2_rn(x, y);
    return *(uint32_t*)&p;
}
__device__ __forceinline__ void cp16(uint32_t dst, const void* src) {
    asm volatile("cp.async.ca.shared.global [%0], [%1], 16;" :: "r"(dst), "l"(src));
}
__device__ __forceinline__ void cp_commit() {
    asm volatile("cp.async.commit_group;" ::: "memory");
}
template <int N>
__device__ __forceinline__ void cp_wait() {
    asm volatile("cp.async.wait_group %0;" :: "n"(N) : "memory");
}

// ----------------------------------------------------------------------------
// One-launch fp32 -> fp16 converter for tok_emb + all weights
// ----------------------------------------------------------------------------
constexpr size_t NP_TOK = (size_t)CV * CD / 2;
constexpr size_t NP_W   = (size_t)CL * CD * CD / 2;
constexpr size_t NP_WF  = (size_t)CL * CD * CFF / 2;
constexpr size_t NP_TOT = NP_TOK + 4 * NP_W + 2 * NP_WF;

__global__ void convert_all_kernel(
    const float* __restrict__ tok, const float* __restrict__ Wq,
    const float* __restrict__ Wk, const float* __restrict__ Wv,
    const float* __restrict__ Wo, const float* __restrict__ W1,
    const float* __restrict__ W2,
    __half* __restrict__ tf, __half* __restrict__ wq, __half* __restrict__ wk,
    __half* __restrict__ wv, __half* __restrict__ wo, __half* __restrict__ w1,
    __half* __restrict__ w2) {
    size_t i = (size_t)blockIdx.x * blockDim.x + threadIdx.x;
    if (i >= NP_TOT) return;
    const float* src; __half* dst;
    if (i < NP_TOK) { src = tok; dst = tf; }
    else {
        i -= NP_TOK;
        if (i < NP_W)          { src = Wq; dst = wq; }
        else if (i < 2 * NP_W) { i -= NP_W;     src = Wk; dst = wk; }
        else if (i < 3 * NP_W) { i -= 2 * NP_W; src = Wv; dst = wv; }
        else if (i < 4 * NP_W) { i -= 3 * NP_W; src = Wo; dst = wo; }
        else if (i < 4 * NP_W + NP_WF) { i -= 4 * NP_W; src = W1; dst = w1; }
        else { i -= 4 * NP_W + NP_WF; src = W2; dst = w2; }
    }
    float2 x = *(const float2*)(src + 2 * i);
    *(__half2*)(dst + 2 * i) = __floats2half2_rn(x.x, x.y);
}

// ----------------------------------------------------------------------------
// Single-term fp16 HMMA GEMM core, MTILE x NTILE, BK=32, 256 thr, 2-stage.
// ----------------------------------------------------------------------------
template <int MTILE, int NTILE, bool TRANSB>
struct GCfg {
    static constexpr int WM = MTILE / 64;
    static constexpr int WN = 8 / WM;
    static constexpr int WARP_N = NTILE / WN;
    static constexpr int NI = WARP_N / 8;
    static constexpr int NB2 = WARP_N / 16;
    static constexpr int BPITCH = NTILE * 2 + 16;
    static constexpr int ASLOT = MTILE * 80;
    static constexpr int BSLOT = TRANSB ? NTILE * 80 : 32 * BPITCH;
    static constexpr int STAGE = ASLOT + BSLOT;
    static constexpr int SMEM = 2 * STAGE;
};

template <int MTILE, int NTILE, bool TRANSB, bool GELU, bool F16OUT>
__device__ __forceinline__ void hgemm_core(
    const __half* __restrict__ A, const __half* __restrict__ B,
    const float* __restrict__ bias, const float* __restrict__ resid,
    float* __restrict__ C, __half* __restrict__ Of,
    int N, int K, int m0, int n0, char* smbase) {
    using CF = GCfg<MTILE, NTILE, TRANSB>;
    const int t = threadIdx.x;
    const int lane = t & 31, wid = t >> 5;
    const int wm = wid % CF::WM, wn = wid / CF::WM;
    const uint32_t sU = smem_u32(smbase);

    auto load_tile = [&](int s, int kc) {
        const int k0 = kc * 32;
        const uint32_t sb = sU + (uint32_t)(s * CF::STAGE);
        // A: MTILE rows x 32 k
#pragma unroll
        for (int i = 0; i < MTILE / 64; i++) {
            int e = t + i * 256;
            int row = e >> 2, c = e & 3;
            cp16(sb + row * 80 + c * 16, A + (size_t)(m0 + row) * K + k0 + c * 8);
        }
        // B
        if (!TRANSB) {
            constexpr int OPS = 32 * NTILE / 8;
#pragma unroll
            for (int i = 0; i < (OPS + 255) / 256; i++) {
                int e = t + i * 256;
                if (OPS >= 256 * (i + 1) || e < OPS) {
                    int row = e / (NTILE / 8), c = e % (NTILE / 8);
                    cp16(sb + CF::ASLOT + row * CF::BPITCH + c * 16,
                         B + (size_t)(k0 + row) * N + n0 + c * 8);
                }
            }
        } else {
#pragma unroll
            for (int i = 0; i < NTILE / 64; i++) {
                int e = t + i * 256;
                int row = e >> 2, c = e & 3;
                int nr = n0 + row;
                if (nr >= N) nr = 0;
                cp16(sb + CF::ASLOT + row * 80 + c * 16,
                     B + (size_t)nr * K + k0 + c * 8);
            }
        }
        cp_commit();
    };

    const uint32_t aoff =
        (uint32_t)((wm * 64 + (lane & 7) + ((lane >> 3) & 1) * 8) * 80 +
                   (lane >> 4) * 16);
    uint32_t boff;
    if (!TRANSB)
        boff = (uint32_t)(((lane & 7) + ((lane >> 3) & 1) * 8) * CF::BPITCH +
                          (wn * CF::WARP_N + (lane >> 4) * 8) * 2);
    else
        boff = (uint32_t)((wn * CF::WARP_N + (lane & 7) + (lane >> 4) * 8) * 80 +
                          ((lane >> 3) & 1) * 16);

    float acc[4][CF::NI][4] = {};
    const int KT = K / 32;
    load_tile(0, 0);

    for (int kc = 0; kc < KT; kc++) {
        if (kc + 1 < KT) { load_tile((kc + 1) & 1, kc + 1); cp_wait<1>(); }
        else             { cp_wait<0>(); }
        __syncthreads();
        const uint32_t sb = sU + (uint32_t)((kc & 1) * CF::STAGE);
#pragma unroll
        for (int ks = 0; ks < 2; ks++) {
            uint32_t ah[4][4], bh[CF::NB2][4];
#pragma unroll
            for (int mi = 0; mi < 4; mi++)
                ldsm4(ah[mi], sb + aoff + mi * (16 * 80) + ks * 32);
#pragma unroll
            for (int n2 = 0; n2 < CF::NB2; n2++) {
                if (!TRANSB)
                    ldsm4t(bh[n2], sb + CF::ASLOT + boff + n2 * 32 + ks * (16 * CF::BPITCH));
                else
                    ldsm4(bh[n2], sb + CF::ASLOT + boff + n2 * (16 * 80) + ks * 32);
            }
#pragma unroll
            for (int mi = 0; mi < 4; mi++)
#pragma unroll
                for (int ni = 0; ni < CF::NI; ni++)
                    mma16816h(acc[mi][ni], ah[mi], &bh[ni >> 1][(ni & 1) * 2]);
        }
        __syncthreads();
    }

    // Epilogue
#pragma unroll
    for (int mi = 0; mi < 4; mi++) {
        const int r0 = m0 + wm * 64 + mi * 16 + (lane >> 2);
#pragma unroll
        for (int ni = 0; ni < CF::NI; ni++) {
            const int col = n0 + wn * CF::WARP_N + ni * 8 + (lane & 3) * 2;
            float v0 = acc[mi][ni][0], v1 = acc[mi][ni][1];
            float v2 = acc[mi][ni][2], v3 = acc[mi][ni][3];
            if (bias) {
                float b0 = (!TRANSB || col < N) ? bias[col] : 0.f;
                float b1 = (!TRANSB || col + 1 < N) ? bias[col + 1] : 0.f;
                v0 += b0; v1 += b1; v2 += b0; v3 += b1;
            }
            if (GELU) {
                v0 = 0.5f * v0 * (1.f + erff(v0 * 0.70710678118654752f));
                v1 = 0.5f * v1 * (1.f + erff(v1 * 0.70710678118654752f));
                v2 = 0.5f * v2 * (1.f + erff(v2 * 0.70710678118654752f));
                v3 = 0.5f * v3 * (1.f + erff(v3 * 0.70710678118654752f));
            }
            size_t o0 = (size_t)r0 * N + col;
            size_t o1 = o0 + (size_t)8 * N;
            if (F16OUT) {
                *(uint32_t*)(Of + o0) = pack_h2(v0, v1);
                *(uint32_t*)(Of + o1) = pack_h2(v2, v3);
            } else if (!TRANSB) {
                if (resid) {
                    float2 rr0 = *(const float2*)(resid + o0);
                    float2 rr1 = *(const float2*)(resid + o1);
                    v0 += rr0.x; v1 += rr0.y; v2 += rr1.x; v3 += rr1.y;
                }
                *(float2*)(C + o0) = make_float2(v0, v1);
                *(float2*)(C + o1) = make_float2(v2, v3);
            } else {
                if (col < N)     { C[o0] = v0; C[o1] = v2; }
                if (col + 1 < N) { C[o0 + 1] = v1; C[o1 + 1] = v3; }
            }
        }
    }
}

// Wo / W2: 128x64 tiles, fp32 + residual
constexpr int SMEM_RES = GCfg<128, 64, false>::SMEM;
__global__ __launch_bounds__(256, 1)
void gemm_res_kernel(const __half* __restrict__ A, const __half* __restrict__ B,
                     const float* __restrict__ bias, const float* __restrict__ resid,
                     float* __restrict__ C, int N, int K) {
    extern __shared__ char sm[];
    hgemm_core<128, 64, false, false, false>(A, B, bias, resid, C, nullptr,
                                             N, K, blockIdx.y * 128,
                                             blockIdx.x * 64, sm);
}

// W1: 256x128 tiles, GELU + fp16 out
constexpr int SMEM_BIG = GCfg<256, 128, false>::SMEM;
__global__ __launch_bounds__(256, 1)
void gemm_gelu_kernel(const __half* __restrict__ A, const __half* __restrict__ B,
                      const float* __restrict__ bias, __half* __restrict__ Of,
                      int N, int K) {
    extern __shared__ char sm[];
    hgemm_core<256, 128, false, true, true>(A, B, bias, nullptr, nullptr, Of,
                                            N, K, blockIdx.y * 256,
                                            blockIdx.x * 128, sm);
}

// QKV fused: 256x128, fp16 out
__global__ __launch_bounds__(256, 1)
void qkv_kernel(const __half* __restrict__ A,
                const __half* __restrict__ W0, const __half* __restrict__ W1_,
                const __half* __restrict__ W2_,
                const float* __restrict__ c0, const float* __restrict__ c1,
                const float* __restrict__ c2,
                __half* __restrict__ q, __half* __restrict__ k,
                __half* __restrict__ v) {
    extern __shared__ char sm[];
    int z = blockIdx.z;
    const __half* B = (z == 0) ? W0 : (z == 1) ? W1_ : W2_;
    const float* bi = (z == 0) ? c0 : (z == 1) ? c1 : c2;
    __half* Of = (z == 0) ? q : (z == 1) ? k : v;
    hgemm_core<256, 128, false, false, true>(A, B, bi, nullptr, nullptr, Of,
                                             CD, CD, blockIdx.y * 256,
                                             blockIdx.x * 128, sm);
}

// lm_head: 256x128, TRANSB, fp32 out, m-fast grid
constexpr int SMEM_LMH = GCfg<256, 128, true>::SMEM;
__global__ __launch_bounds__(256, 1)
void lmhead_kernel(const __half* __restrict__ A, const __half* __restrict__ T,
                   float* __restrict__ out) {
    extern __shared__ char sm[];
    hgemm_core<256, 128, true, false, false>(A, T, nullptr, nullptr, out, nullptr,
                                             CV, CD, blockIdx.x * 256,
                                             blockIdx.y * 128, sm);
}

// ----------------------------------------------------------------------------
// Single-fp16 HMMA flash attention, causal-folded: grid (16, B*H), 128 threads.
// ----------------------------------------------------------------------------
constexpr int AP = 72;
constexpr int TILEB = 64 * AP * 2;          // 9216 B per 64x64 fp16 tile
constexpr int ATTN_SMEM = 5 * TILEB;        // Q + 2 bufs x (K, V)

__global__ __launch_bounds__(128)
void attn_kernel(const __half* __restrict__ Q, const __half* __restrict__ Km,
                 const __half* __restrict__ Vm, __half* __restrict__ At) {
    extern __shared__ char sm[];
    const uint32_t smU = smem_u32(sm);
    const uint32_t qU = smU;
    const uint32_t kvU = smU + TILEB;       // [buf][K, V]

    const int t = threadIdx.x;
    const int lane = t & 31, w = t >> 5;
    const int bh = blockIdx.y;
    const int b = bh >> 2, h = bh & 3;
    const size_t base = (size_t)b * CS * CD + (size_t)h * CHD;

    auto load_kv = [&](int buf, int kt) {
        const int k0 = kt * 64;
#pragma unroll
        for (int a = 0; a < 2; a++) {
            const __half* src = (a ? Vm : Km) + base + (size_t)k0 * CD;
            const uint32_t dbase = kvU + (buf * 2 + a) * TILEB;
#pragma unroll
            for (int i = 0; i < 4; i++) {
                int e = t + i * 128;
                int row = e >> 3, c = e & 7;
                cp16(dbase + row * (AP * 2) + c * 16, src + (size_t)row * CD + c * 8);
            }
        }
        cp_commit();
    };

    for (int half = 0; half < 2; half++) {
        const int qt = half ? (31 - (int)blockIdx.x) : (int)blockIdx.x;
        const int q0 = qt * 64;
        __syncthreads();

        load_kv(0, 0);
        {   // stage Q
            const __half* src = Q + base + (size_t)q0 * CD;
#pragma unroll
            for (int i = 0; i < 4; i++) {
                int e = t + i * 128;
                int row = e >> 3, c = e & 7;
                *(uint4*)(sm + row * (AP * 2) + c * 16) =
                    *(const uint4*)(src + (size_t)row * CD + c * 8);
            }
        }
        __syncthreads();

        uint32_t qf[4][4];
        {
            const uint32_t aoff =
                (uint32_t)((w * 16 + (lane & 7) + ((lane >> 3) & 1) * 8) * (AP * 2) +
                           (lane >> 4) * 16);
#pragma unroll
            for (int ks = 0; ks < 4; ks++)
                ldsm4(qf[ks], qU + aoff + ks * 32);
        }

        float acc[8][4] = {};
        float m_0 = -1e30f, m_1 = -1e30f, l_0 = 0.f, l_1 = 0.f;
        const int rl0 = w * 16 + (lane >> 2);

        for (int kt = 0; kt <= qt; kt++) {
            const int buf = kt & 1;
            const bool more = kt < qt;
            if (more) { load_kv(buf ^ 1, kt + 1); cp_wait<1>(); }
            else      { cp_wait<0>(); }
            __syncthreads();

            const uint32_t kBuf = kvU + (buf * 2 + 0) * TILEB;
            const uint32_t vBuf = kvU + (buf * 2 + 1) * TILEB;

            float st[8][4] = {};
#pragma unroll
            for (int ks = 0; ks < 4; ks++) {
                uint32_t kf[4][4];
#pragma unroll
                for (int nt = 0; nt < 4; nt++) {
                    uint32_t ko =
                        (uint32_t)((nt * 16 + (lane & 7) + (lane >> 4) * 8) * (AP * 2) +
                                   ((lane >> 3) & 1) * 16 + ks * 32);
                    ldsm4(kf[nt], kBuf + ko);
                }
#pragma unroll
                for (int ni = 0; ni < 8; ni++)
                    mma16816h(st[ni], qf[ks], &kf[ni >> 1][(ni & 1) * 2]);
            }

#pragma unroll
            for (int ni = 0; ni < 8; ni++)
#pragma unroll
                for (int e = 0; e < 4; e++) st[ni][e] *= 0.125f;
            if (kt == qt) {
#pragma unroll
                for (int ni = 0; ni < 8; ni++) {
                    int cb = ni * 8 + (lane & 3) * 2;
                    if (cb > rl0)         st[ni][0] = -1e30f;
                    if (cb + 1 > rl0)     st[ni][1] = -1e30f;
                    if (cb > rl0 + 8)     st[ni][2] = -1e30f;
                    if (cb + 1 > rl0 + 8) st[ni][3] = -1e30f;
                }
            }

            float t0 = -1e30f, t1 = -1e30f;
#pragma unroll
            for (int ni = 0; ni < 8; ni++) {
                t0 = fmaxf(t0, fmaxf(st[ni][0], st[ni][1]));
                t1 = fmaxf(t1, fmaxf(st[ni][2], st[ni][3]));
            }
            t0 = fmaxf(t0, __shfl_xor_sync(0xffffffffu, t0, 1));
            t0 = fmaxf(t0, __shfl_xor_sync(0xffffffffu, t0, 2));
            t1 = fmaxf(t1, __shfl_xor_sync(0xffffffffu, t1, 1));
            t1 = fmaxf(t1, __shfl_xor_sync(0xffffffffu, t1, 2));
            float mn0 = fmaxf(m_0, t0), mn1 = fmaxf(m_1, t1);
            float fr0 = __expf(m_0 - mn0), fr1 = __expf(m_1 - mn1);
            m_0 = mn0; m_1 = mn1;
            float ps0 = 0.f, ps1 = 0.f;
#pragma unroll
            for (int ni = 0; ni < 8; ni++) {
                float p0 = __expf(st[ni][0] - mn0); st[ni][0] = p0; ps0 += p0;
                float p1 = __expf(st[ni][1] - mn0); st[ni][1] = p1; ps0 += p1;
                float p2 = __expf(st[ni][2] - mn1); st[ni][2] = p2; ps1 += p2;
                float p3 = __expf(st[ni][3] - mn1); st[ni][3] = p3; ps1 += p3;
            }
            ps0 += __shfl_xor_sync(0xffffffffu, ps0, 1);
            ps0 += __shfl_xor_sync(0xffffffffu, ps0, 2);
            ps1 += __shfl_xor_sync(0xffffffffu, ps1, 1);
            ps1 += __shfl_xor_sync(0xffffffffu, ps1, 2);
            l_0 = l_0 * fr0 + ps0;
            l_1 = l_1 * fr1 + ps1;
#pragma unroll
            for (int ni = 0; ni < 8; ni++) {
                acc[ni][0] *= fr0; acc[ni][1] *= fr0;
                acc[ni][2] *= fr1; acc[ni][3] *= fr1;
            }

            // O += P @ V (single fp16)
#pragma unroll
            for (int ks = 0; ks < 4; ks++) {
                uint32_t pa[4];
                pa[0] = pack_h2(st[2 * ks][0],     st[2 * ks][1]);
                pa[1] = pack_h2(st[2 * ks][2],     st[2 * ks][3]);
                pa[2] = pack_h2(st[2 * ks + 1][0], st[2 * ks + 1][1]);
                pa[3] = pack_h2(st[2 * ks + 1][2], st[2 * ks + 1][3]);
                uint32_t vf[4][4];
#pragma unroll
                for (int vt = 0; vt < 4; vt++) {
                    uint32_t vo =
                        (uint32_t)(((lane & 7) + ((lane >> 3) & 1) * 8 + ks * 16) * (AP * 2) +
                                   (vt * 16 + (lane >> 4) * 8) * 2);
                    ldsm4t(vf[vt], vBuf + vo);
                }
#pragma unroll
                for (int ni = 0; ni < 8; ni++)
                    mma16816h(acc[ni], pa, &vf[ni >> 1][(ni & 1) * 2]);
            }
            __syncthreads();
        }

        float i0 = 1.f / l_0, i1 = 1.f / l_1;
        const int r0 = q0 + rl0;
#pragma unroll
        for (int ni = 0; ni < 8; ni++) {
            int col = ni * 8 + (lane & 3) * 2;
            size_t o = base + (size_t)r0 * CD + col;
            *(uint32_t*)(At + o) = pack_h2(acc[ni][0] * i0, acc[ni][1] * i0);
            *(uint32_t*)(At + o + (size_t)8 * CD) =
                pack_h2(acc[ni][2] * i1, acc[ni][3] * i1);
        }
    }
}

// ----------------------------------------------------------------------------
// Embedding / LayerNorm
// ----------------------------------------------------------------------------
__global__ void embed_kernel(const int* __restrict__ ids,
                             const float* __restrict__ tok,
                             const float* __restrict__ pos,
                             float* __restrict__ h) {
    int i = blockIdx.x;
    int d = threadIdx.x;
    int s = i & (CS - 1);
    h[(size_t)i * CD + d] = tok[(size_t)ids[i] * CD + d] + pos[(size_t)s * CD + d];
}

__global__ void ln_kernel(const float* __restrict__ x,
                          const float* __restrict__ sc,
                          const float* __restrict__ bi,
                          __half* __restrict__ yf) {
    int row = blockIdx.x * 8 + threadIdx.y;   // blockDim (32, 8)
    int lane = threadIdx.x;
    const float* xr = x + (size_t)row * CD;
    float v[8];
    float sum = 0.f, sq = 0.f;
#pragma unroll
    for (int j = 0; j < 8; j++) {
        v[j] = xr[lane * 8 + j];
        sum += v[j];
        sq += v[j] * v[j];
    }
#pragma unroll
    for (int o = 16; o > 0; o >>= 1) {
        sum += __shfl_xor_sync(0xffffffffu, sum, o);
        sq  += __shfl_xor_sync(0xffffffffu, sq, o);
    }
    float mean = sum * (1.f / CD);
    float var  = sq * (1.f / CD) - mean * mean;
    float inv  = rsqrtf(var + 1e-5f);
    size_t off = (size_t)row * CD + lane * 8;
    __half2 f[4];
#pragma unroll
    for (int j = 0; j < 4; j++) {
        int c = lane * 8 + 2 * j;
        float y0 = (v[2 * j]     - mean) * inv * sc[c]     + bi[c];
        float y1 = (v[2 * j + 1] - mean) * inv * sc[c + 1] + bi[c + 1];
        f[j] = __floats2half2_rn(y0, y1);
    }
    *(uint4*)(yf + off) = *(uint4*)f;
}

// ----------------------------------------------------------------------------
// Orchestration
// ----------------------------------------------------------------------------
extern "C" void kernel_launch(void* const* d_in, const int* in_sizes, int n_in,
                              void* d_out, int out_size) {
    const int*   ids  = (const int*)d_in[0];
    const float* tok  = (const float*)d_in[1];
    const float* pos  = (const float*)d_in[2];
    const float* Wq   = (const float*)d_in[3];
    const float* bq   = (const float*)d_in[4];
    const float* Wk   = (const float*)d_in[5];
    const float* bk   = (const float*)d_in[6];
    const float* Wv   = (const float*)d_in[7];
    const float* bv   = (const float*)d_in[8];
    const float* Wo   = (const float*)d_in[9];
    const float* bo   = (const float*)d_in[10];
    const float* ln1s = (const float*)d_in[11];
    const float* ln1b = (const float*)d_in[12];
    const float* ln2s = (const float*)d_in[13];
    const float* ln2b = (const float*)d_in[14];
    const float* W1   = (const float*)d_in[15];
    const float* b1   = (const float*)d_in[16];
    const float* W2   = (const float*)d_in[17];
    const float* b2   = (const float*)d_in[18];
    const float* lnfs = (const float*)d_in[19];
    const float* lnfb = (const float*)d_in[20];
    float* out = (float*)d_out;

    float* h;
    __half *n, *q, *k, *v, *att, *m, *tf, *wq, *wk, *wv, *wo, *w1, *w2;
    cudaGetSymbolAddress((void**)&h,   g_h);
    cudaGetSymbolAddress((void**)&n,   g_n);
    cudaGetSymbolAddress((void**)&q,   g_q);
    cudaGetSymbolAddress((void**)&k,   g_k);
    cudaGetSymbolAddress((void**)&v,   g_v);
    cudaGetSymbolAddress((void**)&att, g_att);
    cudaGetSymbolAddress((void**)&m,   g_m);
    cudaGetSymbolAddress((void**)&tf,  g_tf);
    cudaGetSymbolAddress((void**)&wq,  g_wq);
    cudaGetSymbolAddress((void**)&wk,  g_wk);
    cudaGetSymbolAddress((void**)&wv,  g_wv);
    cudaGetSymbolAddress((void**)&wo,  g_wo);
    cudaGetSymbolAddress((void**)&w1,  g_w1);
    cudaGetSymbolAddress((void**)&w2,  g_w2);

    cudaFuncSetAttribute(attn_kernel,
                         cudaFuncAttributeMaxDynamicSharedMemorySize, ATTN_SMEM);
    cudaFuncSetAttribute(gemm_res_kernel,
                         cudaFuncAttributeMaxDynamicSharedMemorySize, SMEM_RES);
    cudaFuncSetAttribute(gemm_gelu_kernel,
                         cudaFuncAttributeMaxDynamicSharedMemorySize, SMEM_BIG);
    cudaFuncSetAttribute(qkv_kernel,
                         cudaFuncAttributeMaxDynamicSharedMemorySize, SMEM_BIG);
    cudaFuncSetAttribute(lmhead_kernel,
                         cudaFuncAttributeMaxDynamicSharedMemorySize, SMEM_LMH);

    convert_all_kernel<<<(unsigned)((NP_TOT + 255) / 256), 256>>>(
        tok, Wq, Wk, Wv, Wo, W1, W2, tf, wq, wk, wv, wo, w1, w2);

    dim3 lnb(32, 8);
    embed_kernel<<<CM, CD>>>(ids, tok, pos, h);

    for (int l = 0; l < CL; l++) {
        size_t wofs  = (size_t)l * CD * CD;
        size_t bofs  = (size_t)l * CD;
        size_t w1ofs = (size_t)l * CD * CFF;
        size_t b1ofs = (size_t)l * CFF;
        size_t w2ofs = (size_t)l * CFF * CD;

        ln_kernel<<<CM / 8, lnb>>>(h, ln1s + bofs, ln1b + bofs, n);
        qkv_kernel<<<dim3(CD / 128, CM / 256, 3), 256, SMEM_BIG>>>(
            n, wq + wofs, wk + wofs, wv + wofs,
            bq + bofs, bk + bofs, bv + bofs, q, k, v);

        attn_kernel<<<dim3(16, CB * CH), 128, ATTN_SMEM>>>(q, k, v, att);

        gemm_res_kernel<<<dim3(CD / 64, CM / 128), 256, SMEM_RES>>>(
            att, wo + wofs, bo + bofs, h, h, CD, CD);

        ln_kernel<<<CM / 8, lnb>>>(h, ln2s + bofs, ln2b + bofs, n);
        gemm_gelu_kernel<<<dim3(CFF / 128, CM / 256), 256, SMEM_BIG>>>(
            n, w1 + w1ofs, b1 + b1ofs, m, CFF, CD);
        gemm_res_kernel<<<dim3(CD / 64, CM / 128), 256, SMEM_RES>>>(
            m, w2 + w2ofs, b2 + bofs, h, h, CD, CFF);
    }

    ln_kernel<<<CM / 8, lnb>>>(h, lnfs, lnfb, n);
    lmhead_kernel<<<dim3(CM / 256, (CV + 127) / 128), 256, SMEM_LMH>>>(
        n, tf, out);
}

// round 13
// speedup vs baseline: 5.2630x; 1.0437x over previous
#include <cuda_runtime.h>
#include <cuda_bf16.h>
#include <cuda_fp16.h>
#include <math.h>
#include <stdint.h>

// Problem constants
constexpr int CB = 2, CS = 2048, CD = 256, CH = 4, CL = 4, CV = 50257, CHD = 64;
constexpr int CM = CB * CS;      // 4096 rows
constexpr int CFF = 4 * CD;      // 1024

// ----------------------------------------------------------------------------
// Scratch (static device globals — no allocation inside kernel_launch)
// ----------------------------------------------------------------------------
__device__ float  g_h[CM * CD];
__device__ __half g_n[CM * CD];
__device__ __half g_q[CM * CD], g_k[CM * CD], g_v[CM * CD];
__device__ __half g_att[CM * CD];
__device__ __half g_m[CM * CFF];
__device__ __half g_tf[(size_t)CV * CD];
__device__ __half g_wq[CL * CD * CD], g_wk[CL * CD * CD];
__device__ __half g_wv[CL * CD * CD], g_wo[CL * CD * CD];
__device__ __half g_w1[CL * CD * CFF], g_w2[CL * CD * CFF];

// ----------------------------------------------------------------------------
// Helpers
// ----------------------------------------------------------------------------
__device__ __forceinline__ uint32_t smem_u32(const void* p) {
    uint32_t a;
    asm("{ .reg .u64 t; cvta.to.shared.u64 t, %1; cvt.u32.u64 %0, t; }"
        : "=r"(a) : "l"(p));
    return a;
}
__device__ __forceinline__ void ldsm4(uint32_t* r, uint32_t addr) {
    asm volatile("ldmatrix.sync.aligned.m8n8.x4.shared.b16 {%0,%1,%2,%3}, [%4];"
                 : "=r"(r[0]), "=r"(r[1]), "=r"(r[2]), "=r"(r[3]) : "r"(addr));
}
__device__ __forceinline__ void ldsm4t(uint32_t* r, uint32_t addr) {
    asm volatile("ldmatrix.sync.aligned.m8n8.x4.trans.shared.b16 {%0,%1,%2,%3}, [%4];"
                 : "=r"(r[0]), "=r"(r[1]), "=r"(r[2]), "=r"(r[3]) : "r"(addr));
}
__device__ __forceinline__ void mma16816h(float* c, const uint32_t* a, const uint32_t* b) {
    asm volatile("mma.sync.aligned.m16n8k16.row.col.f32.f16.f16.f32 "
                 "{%0,%1,%2,%3}, {%4,%5,%6,%7}, {%8,%9}, {%0,%1,%2,%3};"
                 : "+f"(c[0]), "+f"(c[1]), "+f"(c[2]), "+f"(c[3])
                 : "r"(a[0]), "r"(a[1]), "r"(a[2]), "r"(a[3]),
                   "r"(b[0]), "r"(b[1]));
}
__device__ __forceinline__ uint32_t pack_h2(float x, float y) {
    __half2 p = __floats2half2_rn(x, y);
    return *(uint32_t*)&p;
}
__device__ __forceinline__ void cp16(uint32_t dst, const void* src) {
    asm volatile("cp.async.ca.shared.global [%0], [%1], 16;" :: "r"(dst), "l"(src));
}
__device__ __forceinline__ void cp_commit() {
    asm volatile("cp.async.commit_group;" ::: "memory");
}
template <int N>
__device__ __forceinline__ void cp_wait() {
    asm volatile("cp.async.wait_group %0;" :: "n"(N) : "memory");
}

// ----------------------------------------------------------------------------
// One-launch fp32 -> fp16 converter for tok_emb + all weights
// ----------------------------------------------------------------------------
constexpr size_t NP_TOK = (size_t)CV * CD / 2;
constexpr size_t NP_W   = (size_t)CL * CD * CD / 2;
constexpr size_t NP_WF  = (size_t)CL * CD * CFF / 2;
constexpr size_t NP_TOT = NP_TOK + 4 * NP_W + 2 * NP_WF;

__global__ void convert_all_kernel(
    const float* __restrict__ tok, const float* __restrict__ Wq,
    const float* __restrict__ Wk, const float* __restrict__ Wv,
    const float* __restrict__ Wo, const float* __restrict__ W1,
    const float* __restrict__ W2,
    __half* __restrict__ tf, __half* __restrict__ wq, __half* __restrict__ wk,
    __half* __restrict__ wv, __half* __restrict__ wo, __half* __restrict__ w1,
    __half* __restrict__ w2) {
    size_t i = (size_t)blockIdx.x * blockDim.x + threadIdx.x;
    if (i >= NP_TOT) return;
    const float* src; __half* dst;
    if (i < NP_TOK) { src = tok; dst = tf; }
    else {
        i -= NP_TOK;
        if (i < NP_W)          { src = Wq; dst = wq; }
        else if (i < 2 * NP_W) { i -= NP_W;     src = Wk; dst = wk; }
        else if (i < 3 * NP_W) { i -= 2 * NP_W; src = Wv; dst = wv; }
        else if (i < 4 * NP_W) { i -= 3 * NP_W; src = Wo; dst = wo; }
        else if (i < 4 * NP_W + NP_WF) { i -= 4 * NP_W; src = W1; dst = w1; }
        else { i -= 4 * NP_W + NP_WF; src = W2; dst = w2; }
    }
    float2 x = *(const float2*)(src + 2 * i);
    *(__half2*)(dst + 2 * i) = __floats2half2_rn(x.x, x.y);
}

// ----------------------------------------------------------------------------
// Single-term fp16 HMMA GEMM core, MTILE x NTILE, BK=32, 256 thr.
// 3-stage cp.async ring, ONE __syncthreads per k-chunk:
//   iter kc: wait(L_kc done) -> barrier -> issue L_{kc+2} -> compute S_{kc%3}
// The buffer written by L_{kc+2} is the one read at kc-1, protected by barrier.
// ----------------------------------------------------------------------------
template <int MTILE, int NTILE, bool TRANSB>
struct GCfg {
    static constexpr int WM = MTILE / 64;
    static constexpr int WN = 8 / WM;
    static constexpr int WARP_N = NTILE / WN;
    static constexpr int NI = WARP_N / 8;
    static constexpr int NB2 = WARP_N / 16;
    static constexpr int BPITCH = NTILE * 2 + 16;
    static constexpr int ASLOT = MTILE * 80;
    static constexpr int BSLOT = TRANSB ? NTILE * 80 : 32 * BPITCH;
    static constexpr int STAGE = ASLOT + BSLOT;
    static constexpr int SMEM = 3 * STAGE;
};

template <int MTILE, int NTILE, bool TRANSB, bool GELU, bool F16OUT>
__device__ __forceinline__ void hgemm_core(
    const __half* __restrict__ A, const __half* __restrict__ B,
    const float* __restrict__ bias, const float* __restrict__ resid,
    float* __restrict__ C, __half* __restrict__ Of,
    int N, int K, int m0, int n0, char* smbase) {
    using CF = GCfg<MTILE, NTILE, TRANSB>;
    const int t = threadIdx.x;
    const int lane = t & 31, wid = t >> 5;
    const int wm = wid % CF::WM, wn = wid / CF::WM;
    const uint32_t sU = smem_u32(smbase);

    auto load_tile = [&](int s, int kc) {
        const int k0 = kc * 32;
        const uint32_t sb = sU + (uint32_t)(s * CF::STAGE);
        // A: MTILE rows x 32 k
#pragma unroll
        for (int i = 0; i < MTILE / 64; i++) {
            int e = t + i * 256;
            int row = e >> 2, c = e & 3;
            cp16(sb + row * 80 + c * 16, A + (size_t)(m0 + row) * K + k0 + c * 8);
        }
        // B
        if (!TRANSB) {
            constexpr int OPS = 32 * NTILE / 8;
#pragma unroll
            for (int i = 0; i < (OPS + 255) / 256; i++) {
                int e = t + i * 256;
                if (OPS >= 256 * (i + 1) || e < OPS) {
                    int row = e / (NTILE / 8), c = e % (NTILE / 8);
                    cp16(sb + CF::ASLOT + row * CF::BPITCH + c * 16,
                         B + (size_t)(k0 + row) * N + n0 + c * 8);
                }
            }
        } else {
#pragma unroll
            for (int i = 0; i < NTILE / 64; i++) {
                int e = t + i * 256;
                int row = e >> 2, c = e & 3;
                int nr = n0 + row;
                if (nr >= N) nr = 0;
                cp16(sb + CF::ASLOT + row * 80 + c * 16,
                     B + (size_t)nr * K + k0 + c * 8);
            }
        }
        cp_commit();
    };

    const uint32_t aoff =
        (uint32_t)((wm * 64 + (lane & 7) + ((lane >> 3) & 1) * 8) * 80 +
                   (lane >> 4) * 16);
    uint32_t boff;
    if (!TRANSB)
        boff = (uint32_t)(((lane & 7) + ((lane >> 3) & 1) * 8) * CF::BPITCH +
                          (wn * CF::WARP_N + (lane >> 4) * 8) * 2);
    else
        boff = (uint32_t)((wn * CF::WARP_N + (lane & 7) + (lane >> 4) * 8) * 80 +
                          ((lane >> 3) & 1) * 16);

    float acc[4][CF::NI][4] = {};
    const int KT = K / 32;

    load_tile(0, 0);
    if (KT > 1) load_tile(1, 1);

    int stage = 0;
    for (int kc = 0; kc < KT; kc++) {
        // Need L_kc complete. Most recent issued group is L_{kc+1} (if any).
        if (kc + 1 < KT) cp_wait<1>(); else cp_wait<0>();
        __syncthreads();
        if (kc + 2 < KT) {
            int s2 = stage + 2; if (s2 >= 3) s2 -= 3;
            load_tile(s2, kc + 2);
        }
        const uint32_t sb = sU + (uint32_t)(stage * CF::STAGE);
#pragma unroll
        for (int ks = 0; ks < 2; ks++) {
            uint32_t ah[4][4], bh[CF::NB2][4];
#pragma unroll
            for (int mi = 0; mi < 4; mi++)
                ldsm4(ah[mi], sb + aoff + mi * (16 * 80) + ks * 32);
#pragma unroll
            for (int n2 = 0; n2 < CF::NB2; n2++) {
                if (!TRANSB)
                    ldsm4t(bh[n2], sb + CF::ASLOT + boff + n2 * 32 + ks * (16 * CF::BPITCH));
                else
                    ldsm4(bh[n2], sb + CF::ASLOT + boff + n2 * (16 * 80) + ks * 32);
            }
#pragma unroll
            for (int mi = 0; mi < 4; mi++)
#pragma unroll
                for (int ni = 0; ni < CF::NI; ni++)
                    mma16816h(acc[mi][ni], ah[mi], &bh[ni >> 1][(ni & 1) * 2]);
        }
        if (++stage == 3) stage = 0;
    }

    // Epilogue
#pragma unroll
    for (int mi = 0; mi < 4; mi++) {
        const int r0 = m0 + wm * 64 + mi * 16 + (lane >> 2);
#pragma unroll
        for (int ni = 0; ni < CF::NI; ni++) {
            const int col = n0 + wn * CF::WARP_N + ni * 8 + (lane & 3) * 2;
            float v0 = acc[mi][ni][0], v1 = acc[mi][ni][1];
            float v2 = acc[mi][ni][2], v3 = acc[mi][ni][3];
            if (bias) {
                float b0 = (!TRANSB || col < N) ? bias[col] : 0.f;
                float b1 = (!TRANSB || col + 1 < N) ? bias[col + 1] : 0.f;
                v0 += b0; v1 += b1; v2 += b0; v3 += b1;
            }
            if (GELU) {
                v0 = 0.5f * v0 * (1.f + erff(v0 * 0.70710678118654752f));
                v1 = 0.5f * v1 * (1.f + erff(v1 * 0.70710678118654752f));
                v2 = 0.5f * v2 * (1.f + erff(v2 * 0.70710678118654752f));
                v3 = 0.5f * v3 * (1.f + erff(v3 * 0.70710678118654752f));
            }
            size_t o0 = (size_t)r0 * N + col;
            size_t o1 = o0 + (size_t)8 * N;
            if (F16OUT) {
                *(uint32_t*)(Of + o0) = pack_h2(v0, v1);
                *(uint32_t*)(Of + o1) = pack_h2(v2, v3);
            } else if (!TRANSB) {
                if (resid) {
                    float2 rr0 = *(const float2*)(resid + o0);
                    float2 rr1 = *(const float2*)(resid + o1);
                    v0 += rr0.x; v1 += rr0.y; v2 += rr1.x; v3 += rr1.y;
                }
                *(float2*)(C + o0) = make_float2(v0, v1);
                *(float2*)(C + o1) = make_float2(v2, v3);
            } else {
                if (col < N)     { C[o0] = v0; C[o1] = v2; }
                if (col + 1 < N) { C[o0 + 1] = v1; C[o1 + 1] = v3; }
            }
        }
    }
}

// Wo / W2: 128x64 tiles, fp32 + residual
constexpr int SMEM_RES = GCfg<128, 64, false>::SMEM;
__global__ __launch_bounds__(256, 1)
void gemm_res_kernel(const __half* __restrict__ A, const __half* __restrict__ B,
                     const float* __restrict__ bias, const float* __restrict__ resid,
                     float* __restrict__ C, int N, int K) {
    extern __shared__ char sm[];
    hgemm_core<128, 64, false, false, false>(A, B, bias, resid, C, nullptr,
                                             N, K, blockIdx.y * 128,
                                             blockIdx.x * 64, sm);
}

// W1: 256x128 tiles, GELU + fp16 out
constexpr int SMEM_BIG = GCfg<256, 128, false>::SMEM;
__global__ __launch_bounds__(256, 1)
void gemm_gelu_kernel(const __half* __restrict__ A, const __half* __restrict__ B,
                      const float* __restrict__ bias, __half* __restrict__ Of,
                      int N, int K) {
    extern __shared__ char sm[];
    hgemm_core<256, 128, false, true, true>(A, B, bias, nullptr, nullptr, Of,
                                            N, K, blockIdx.y * 256,
                                            blockIdx.x * 128, sm);
}

// QKV fused: 256x128, fp16 out
__global__ __launch_bounds__(256, 1)
void qkv_kernel(const __half* __restrict__ A,
                const __half* __restrict__ W0, const __half* __restrict__ W1_,
                const __half* __restrict__ W2_,
                const float* __restrict__ c0, const float* __restrict__ c1,
                const float* __restrict__ c2,
                __half* __restrict__ q, __half* __restrict__ k,
                __half* __restrict__ v) {
    extern __shared__ char sm[];
    int z = blockIdx.z;
    const __half* B = (z == 0) ? W0 : (z == 1) ? W1_ : W2_;
    const float* bi = (z == 0) ? c0 : (z == 1) ? c1 : c2;
    __half* Of = (z == 0) ? q : (z == 1) ? k : v;
    hgemm_core<256, 128, false, false, true>(A, B, bi, nullptr, nullptr, Of,
                                             CD, CD, blockIdx.y * 256,
                                             blockIdx.x * 128, sm);
}

// lm_head: 256x128, TRANSB, fp32 out, m-fast grid
constexpr int SMEM_LMH = GCfg<256, 128, true>::SMEM;
__global__ __launch_bounds__(256, 1)
void lmhead_kernel(const __half* __restrict__ A, const __half* __restrict__ T,
                   float* __restrict__ out) {
    extern __shared__ char sm[];
    hgemm_core<256, 128, true, false, false>(A, T, nullptr, nullptr, out, nullptr,
                                             CV, CD, blockIdx.x * 256,
                                             blockIdx.y * 128, sm);
}

// ----------------------------------------------------------------------------
// Single-fp16 HMMA flash attention, causal-folded: grid (16, B*H), 128 threads.
// ----------------------------------------------------------------------------
constexpr int AP = 72;
constexpr int TILEB = 64 * AP * 2;          // 9216 B per 64x64 fp16 tile
constexpr int ATTN_SMEM = 5 * TILEB;        // Q + 2 bufs x (K, V)

__global__ __launch_bounds__(128)
void attn_kernel(const __half* __restrict__ Q, const __half* __restrict__ Km,
                 const __half* __restrict__ Vm, __half* __restrict__ At) {
    extern __shared__ char sm[];
    const uint32_t smU = smem_u32(sm);
    const uint32_t qU = smU;
    const uint32_t kvU = smU + TILEB;       // [buf][K, V]

    const int t = threadIdx.x;
    const int lane = t & 31, w = t >> 5;
    const int bh = blockIdx.y;
    const int b = bh >> 2, h = bh & 3;
    const size_t base = (size_t)b * CS * CD + (size_t)h * CHD;

    auto load_kv = [&](int buf, int kt) {
        const int k0 = kt * 64;
#pragma unroll
        for (int a = 0; a < 2; a++) {
            const __half* src = (a ? Vm : Km) + base + (size_t)k0 * CD;
            const uint32_t dbase = kvU + (buf * 2 + a) * TILEB;
#pragma unroll
            for (int i = 0; i < 4; i++) {
                int e = t + i * 128;
                int row = e >> 3, c = e & 7;
                cp16(dbase + row * (AP * 2) + c * 16, src + (size_t)row * CD + c * 8);
            }
        }
        cp_commit();
    };

    for (int half = 0; half < 2; half++) {
        const int qt = half ? (31 - (int)blockIdx.x) : (int)blockIdx.x;
        const int q0 = qt * 64;
        __syncthreads();

        load_kv(0, 0);
        {   // stage Q
            const __half* src = Q + base + (size_t)q0 * CD;
#pragma unroll
            for (int i = 0; i < 4; i++) {
                int e = t + i * 128;
                int row = e >> 3, c = e & 7;
                *(uint4*)(sm + row * (AP * 2) + c * 16) =
                    *(const uint4*)(src + (size_t)row * CD + c * 8);
            }
        }
        __syncthreads();

        uint32_t qf[4][4];
        {
            const uint32_t aoff =
                (uint32_t)((w * 16 + (lane & 7) + ((lane >> 3) & 1) * 8) * (AP * 2) +
                           (lane >> 4) * 16);
#pragma unroll
            for (int ks = 0; ks < 4; ks++)
                ldsm4(qf[ks], qU + aoff + ks * 32);
        }

        float acc[8][4] = {};
        float m_0 = -1e30f, m_1 = -1e30f, l_0 = 0.f, l_1 = 0.f;
        const int rl0 = w * 16 + (lane >> 2);

        for (int kt = 0; kt <= qt; kt++) {
            const int buf = kt & 1;
            const bool more = kt < qt;
            if (more) { load_kv(buf ^ 1, kt + 1); cp_wait<1>(); }
            else      { cp_wait<0>(); }
            __syncthreads();

            const uint32_t kBuf = kvU + (buf * 2 + 0) * TILEB;
            const uint32_t vBuf = kvU + (buf * 2 + 1) * TILEB;

            float st[8][4] = {};
#pragma unroll
            for (int ks = 0; ks < 4; ks++) {
                uint32_t kf[4][4];
#pragma unroll
                for (int nt = 0; nt < 4; nt++) {
                    uint32_t ko =
                        (uint32_t)((nt * 16 + (lane & 7) + (lane >> 4) * 8) * (AP * 2) +
                                   ((lane >> 3) & 1) * 16 + ks * 32);
                    ldsm4(kf[nt], kBuf + ko);
                }
#pragma unroll
                for (int ni = 0; ni < 8; ni++)
                    mma16816h(st[ni], qf[ks], &kf[ni >> 1][(ni & 1) * 2]);
            }

#pragma unroll
            for (int ni = 0; ni < 8; ni++)
#pragma unroll
                for (int e = 0; e < 4; e++) st[ni][e] *= 0.125f;
            if (kt == qt) {
#pragma unroll
                for (int ni = 0; ni < 8; ni++) {
                    int cb = ni * 8 + (lane & 3) * 2;
                    if (cb > rl0)         st[ni][0] = -1e30f;
                    if (cb + 1 > rl0)     st[ni][1] = -1e30f;
                    if (cb > rl0 + 8)     st[ni][2] = -1e30f;
                    if (cb + 1 > rl0 + 8) st[ni][3] = -1e30f;
                }
            }

            float t0 = -1e30f, t1 = -1e30f;
#pragma unroll
            for (int ni = 0; ni < 8; ni++) {
                t0 = fmaxf(t0, fmaxf(st[ni][0], st[ni][1]));
                t1 = fmaxf(t1, fmaxf(st[ni][2], st[ni][3]));
            }
            t0 = fmaxf(t0, __shfl_xor_sync(0xffffffffu, t0, 1));
            t0 = fmaxf(t0, __shfl_xor_sync(0xffffffffu, t0, 2));
            t1 = fmaxf(t1, __shfl_xor_sync(0xffffffffu, t1, 1));
            t1 = fmaxf(t1, __shfl_xor_sync(0xffffffffu, t1, 2));
            float mn0 = fmaxf(m_0, t0), mn1 = fmaxf(m_1, t1);
            float fr0 = __expf(m_0 - mn0), fr1 = __expf(m_1 - mn1);
            m_0 = mn0; m_1 = mn1;
            float ps0 = 0.f, ps1 = 0.f;
#pragma unroll
            for (int ni = 0; ni < 8; ni++) {
                float p0 = __expf(st[ni][0] - mn0); st[ni][0] = p0; ps0 += p0;
                float p1 = __expf(st[ni][1] - mn0); st[ni][1] = p1; ps0 += p1;
                float p2 = __expf(st[ni][2] - mn1); st[ni][2] = p2; ps1 += p2;
                float p3 = __expf(st[ni][3] - mn1); st[ni][3] = p3; ps1 += p3;
            }
            ps0 += __shfl_xor_sync(0xffffffffu, ps0, 1);
            ps0 += __shfl_xor_sync(0xffffffffu, ps0, 2);
            ps1 += __shfl_xor_sync(0xffffffffu, ps1, 1);
            ps1 += __shfl_xor_sync(0xffffffffu, ps1, 2);
            l_0 = l_0 * fr0 + ps0;
            l_1 = l_1 * fr1 + ps1;
#pragma unroll
            for (int ni = 0; ni < 8; ni++) {
                acc[ni][0] *= fr0; acc[ni][1] *= fr0;
                acc[ni][2] *= fr1; acc[ni][3] *= fr1;
            }

            // O += P @ V (single fp16)
#pragma unroll
            for (int ks = 0; ks < 4; ks++) {
                uint32_t pa[4];
                pa[0] = pack_h2(st[2 * ks][0],     st[2 * ks][1]);
                pa[1] = pack_h2(st[2 * ks][2],     st[2 * ks][3]);
                pa[2] = pack_h2(st[2 * ks + 1][0], st[2 * ks + 1][1]);
                pa[3] = pack_h2(st[2 * ks + 1][2], st[2 * ks + 1][3]);
                uint32_t vf[4][4];
#pragma unroll
                for (int vt = 0; vt < 4; vt++) {
                    uint32_t vo =
                        (uint32_t)(((lane & 7) + ((lane >> 3) & 1) * 8 + ks * 16) * (AP * 2) +
                                   (vt * 16 + (lane >> 4) * 8) * 2);
                    ldsm4t(vf[vt], vBuf + vo);
                }
#pragma unroll
                for (int ni = 0; ni < 8; ni++)
                    mma16816h(acc[ni], pa, &vf[ni >> 1][(ni & 1) * 2]);
            }
            __syncthreads();
        }

        float i0 = 1.f / l_0, i1 = 1.f / l_1;
        const int r0 = q0 + rl0;
#pragma unroll
        for (int ni = 0; ni < 8; ni++) {
            int col = ni * 8 + (lane & 3) * 2;
            size_t o = base + (size_t)r0 * CD + col;
            *(uint32_t*)(At + o) = pack_h2(acc[ni][0] * i0, acc[ni][1] * i0);
            *(uint32_t*)(At + o + (size_t)8 * CD) =
                pack_h2(acc[ni][2] * i1, acc[ni][3] * i1);
        }
    }
}

// ----------------------------------------------------------------------------
// Embedding / LayerNorm
// ----------------------------------------------------------------------------
__global__ void embed_kernel(const int* __restrict__ ids,
                             const float* __restrict__ tok,
                             const float* __restrict__ pos,
                             float* __restrict__ h) {
    int i = blockIdx.x;
    int d = threadIdx.x;
    int s = i & (CS - 1);
    h[(size_t)i * CD + d] = tok[(size_t)ids[i] * CD + d] + pos[(size_t)s * CD + d];
}

__global__ void ln_kernel(const float* __restrict__ x,
                          const float* __restrict__ sc,
                          const float* __restrict__ bi,
                          __half* __restrict__ yf) {
    int row = blockIdx.x * 8 + threadIdx.y;   // blockDim (32, 8)
    int lane = threadIdx.x;
    const float* xr = x + (size_t)row * CD;
    float v[8];
    float sum = 0.f, sq = 0.f;
#pragma unroll
    for (int j = 0; j < 8; j++) {
        v[j] = xr[lane * 8 + j];
        sum += v[j];
        sq += v[j] * v[j];
    }
#pragma unroll
    for (int o = 16; o > 0; o >>= 1) {
        sum += __shfl_xor_sync(0xffffffffu, sum, o);
        sq  += __shfl_xor_sync(0xffffffffu, sq, o);
    }
    float mean = sum * (1.f / CD);
    float var  = sq * (1.f / CD) - mean * mean;
    float inv  = rsqrtf(var + 1e-5f);
    size_t off = (size_t)row * CD + lane * 8;
    __half2 f[4];
#pragma unroll
    for (int j = 0; j < 4; j++) {
        int c = lane * 8 + 2 * j;
        float y0 = (v[2 * j]     - mean) * inv * sc[c]     + bi[c];
        float y1 = (v[2 * j + 1] - mean) * inv * sc[c + 1] + bi[c + 1];
        f[j] = __floats2half2_rn(y0, y1);
    }
    *(uint4*)(yf + off) = *(uint4*)f;
}

// ----------------------------------------------------------------------------
// Orchestration
// ----------------------------------------------------------------------------
extern "C" void kernel_launch(void* const* d_in, const int* in_sizes, int n_in,
                              void* d_out, int out_size) {
    const int*   ids  = (const int*)d_in[0];
    const float* tok  = (const float*)d_in[1];
    const float* pos  = (const float*)d_in[2];
    const float* Wq   = (const float*)d_in[3];
    const float* bq   = (const float*)d_in[4];
    const float* Wk   = (const float*)d_in[5];
    const float* bk   = (const float*)d_in[6];
    const float* Wv   = (const float*)d_in[7];
    const float* bv   = (const float*)d_in[8];
    const float* Wo   = (const float*)d_in[9];
    const float* bo   = (const float*)d_in[10];
    const float* ln1s = (const float*)d_in[11];
    const float* ln1b = (const float*)d_in[12];
    const float* ln2s = (const float*)d_in[13];
    const float* ln2b = (const float*)d_in[14];
    const float* W1   = (const float*)d_in[15];
    const float* b1   = (const float*)d_in[16];
    const float* W2   = (const float*)d_in[17];
    const float* b2   = (const float*)d_in[18];
    const float* lnfs = (const float*)d_in[19];
    const float* lnfb = (const float*)d_in[20];
    float* out = (float*)d_out;

    float* h;
    __half *n, *q, *k, *v, *att, *m, *tf, *wq, *wk, *wv, *wo, *w1, *w2;
    cudaGetSymbolAddress((void**)&h,   g_h);
    cudaGetSymbolAddress((void**)&n,   g_n);
    cudaGetSymbolAddress((void**)&q,   g_q);
    cudaGetSymbolAddress((void**)&k,   g_k);
    cudaGetSymbolAddress((void**)&v,   g_v);
    cudaGetSymbolAddress((void**)&att, g_att);
    cudaGetSymbolAddress((void**)&m,   g_m);
    cudaGetSymbolAddress((void**)&tf,  g_tf);
    cudaGetSymbolAddress((void**)&wq,  g_wq);
    cudaGetSymbolAddress((void**)&wk,  g_wk);
    cudaGetSymbolAddress((void**)&wv,  g_wv);
    cudaGetSymbolAddress((void**)&wo,  g_wo);
    cudaGetSymbolAddress((void**)&w1,  g_w1);
    cudaGetSymbolAddress((void**)&w2,  g_w2);

    cudaFuncSetAttribute(attn_kernel,
                         cudaFuncAttributeMaxDynamicSharedMemorySize, ATTN_SMEM);
    cudaFuncSetAttribute(gemm_res_kernel,
                         cudaFuncAttributeMaxDynamicSharedMemorySize, SMEM_RES);
    cudaFuncSetAttribute(gemm_gelu_kernel,
                         cudaFuncAttributeMaxDynamicSharedMemorySize, SMEM_BIG);
    cudaFuncSetAttribute(qkv_kernel,
                         cudaFuncAttributeMaxDynamicSharedMemorySize, SMEM_BIG);
    cudaFuncSetAttribute(lmhead_kernel,
                         cudaFuncAttributeMaxDynamicSharedMemorySize, SMEM_LMH);

    convert_all_kernel<<<(unsigned)((NP_TOT + 255) / 256), 256>>>(
        tok, Wq, Wk, Wv, Wo, W1, W2, tf, wq, wk, wv, wo, w1, w2);

    dim3 lnb(32, 8);
    embed_kernel<<<CM, CD>>>(ids, tok, pos, h);

    for (int l = 0; l < CL; l++) {
        size_t wofs  = (size_t)l * CD * CD;
        size_t bofs  = (size_t)l * CD;
        size_t w1ofs = (size_t)l * CD * CFF;
        size_t b1ofs = (size_t)l * CFF;
        size_t w2ofs = (size_t)l * CFF * CD;

        ln_kernel<<<CM / 8, lnb>>>(h, ln1s + bofs, ln1b + bofs, n);
        qkv_kernel<<<dim3(CD / 128, CM / 256, 3), 256, SMEM_BIG>>>(
            n, wq + wofs, wk + wofs, wv + wofs,
            bq + bofs, bk + bofs, bv + bofs, q, k, v);

        attn_kernel<<<dim3(16, CB * CH), 128, ATTN_SMEM>>>(q, k, v, att);

        gemm_res_kernel<<<dim3(CD / 64, CM / 128), 256, SMEM_RES>>>(
            att, wo + wofs, bo + bofs, h, h, CD, CD);

        ln_kernel<<<CM / 8, lnb>>>(h, ln2s + bofs, ln2b + bofs, n);
        gemm_gelu_kernel<<<dim3(CFF / 128, CM / 256), 256, SMEM_BIG>>>(
            n, w1 + w1ofs, b1 + b1ofs, m, CFF, CD);
        gemm_res_kernel<<<dim3(CD / 64, CM / 128), 256, SMEM_RES>>>(
            m, w2 + w2ofs, b2 + bofs, h, h, CD, CFF);
    }

    ln_kernel<<<CM / 8, lnb>>>(h, lnfs, lnfb, n);
    lmhead_kernel<<<dim3(CM / 256, (CV + 127) / 128), 256, SMEM_LMH>>>(
        n, tf, out);
}

// round 14
// speedup vs baseline: 6.1351x; 1.1657x over previous
#include <cuda_runtime.h>
#include <cuda_bf16.h>
#include <cuda_fp16.h>
#include <math.h>
#include <stdint.h>

// Problem constants
constexpr int CB = 2, CS = 2048, CD = 256, CH = 4, CL = 4, CV = 50257, CHD = 64;
constexpr int CM = CB * CS;      // 4096 rows
constexpr int CFF = 4 * CD;      // 1024

// ----------------------------------------------------------------------------
// Scratch (static device globals — no allocation inside kernel_launch)
// ----------------------------------------------------------------------------
__device__ float  g_h[CM * CD];
__device__ __half g_n[CM * CD];
__device__ __half g_q[CM * CD], g_k[CM * CD], g_v[CM * CD];
__device__ __half g_att[CM * CD];
__device__ __half g_m[CM * CFF];
__device__ __half g_tf[(size_t)CV * CD];
__device__ __half g_wq[CL * CD * CD], g_wk[CL * CD * CD];
__device__ __half g_wv[CL * CD * CD], g_wo[CL * CD * CD];
__device__ __half g_w1[CL * CD * CFF], g_w2[CL * CD * CFF];

// ----------------------------------------------------------------------------
// Helpers
// ----------------------------------------------------------------------------
__device__ __forceinline__ uint32_t smem_u32(const void* p) {
    uint32_t a;
    asm("{ .reg .u64 t; cvta.to.shared.u64 t, %1; cvt.u32.u64 %0, t; }"
        : "=r"(a) : "l"(p));
    return a;
}
__device__ __forceinline__ void ldsm4(uint32_t* r, uint32_t addr) {
    asm volatile("ldmatrix.sync.aligned.m8n8.x4.shared.b16 {%0,%1,%2,%3}, [%4];"
                 : "=r"(r[0]), "=r"(r[1]), "=r"(r[2]), "=r"(r[3]) : "r"(addr));
}
__device__ __forceinline__ void ldsm4t(uint32_t* r, uint32_t addr) {
    asm volatile("ldmatrix.sync.aligned.m8n8.x4.trans.shared.b16 {%0,%1,%2,%3}, [%4];"
                 : "=r"(r[0]), "=r"(r[1]), "=r"(r[2]), "=r"(r[3]) : "r"(addr));
}
__device__ __forceinline__ void mma16816h(float* c, const uint32_t* a, const uint32_t* b) {
    asm volatile("mma.sync.aligned.m16n8k16.row.col.f32.f16.f16.f32 "
                 "{%0,%1,%2,%3}, {%4,%5,%6,%7}, {%8,%9}, {%0,%1,%2,%3};"
                 : "+f"(c[0]), "+f"(c[1]), "+f"(c[2]), "+f"(c[3])
                 : "r"(a[0]), "r"(a[1]), "r"(a[2]), "r"(a[3]),
                   "r"(b[0]), "r"(b[1]));
}
__device__ __forceinline__ uint32_t pack_h2(float x, float y) {
    __half2 p = __floats2half2_rn(x, y);
    return *(uint32_t*)&p;
}
__device__ __forceinline__ void cp16(uint32_t dst, const void* src) {
    asm volatile("cp.async.ca.shared.global [%0], [%1], 16;" :: "r"(dst), "l"(src));
}
__device__ __forceinline__ void cp_commit() {
    asm volatile("cp.async.commit_group;" ::: "memory");
}
template <int N>
__device__ __forceinline__ void cp_wait() {
    asm volatile("cp.async.wait_group %0;" :: "n"(N) : "memory");
}
__device__ __forceinline__ void barx(int id) {   // named barrier, 128 threads
    asm volatile("bar.sync %0, 128;" :: "r"(id) : "memory");
}

// ----------------------------------------------------------------------------
// One-launch fp32 -> fp16 converter for tok_emb + all weights
// ----------------------------------------------------------------------------
constexpr size_t NP_TOK = (size_t)CV * CD / 2;
constexpr size_t NP_W   = (size_t)CL * CD * CD / 2;
constexpr size_t NP_WF  = (size_t)CL * CD * CFF / 2;
constexpr size_t NP_TOT = NP_TOK + 4 * NP_W + 2 * NP_WF;

__global__ void convert_all_kernel(
    const float* __restrict__ tok, const float* __restrict__ Wq,
    const float* __restrict__ Wk, const float* __restrict__ Wv,
    const float* __restrict__ Wo, const float* __restrict__ W1,
    const float* __restrict__ W2,
    __half* __restrict__ tf, __half* __restrict__ wq, __half* __restrict__ wk,
    __half* __restrict__ wv, __half* __restrict__ wo, __half* __restrict__ w1,
    __half* __restrict__ w2) {
    size_t i = (size_t)blockIdx.x * blockDim.x + threadIdx.x;
    if (i >= NP_TOT) return;
    const float* src; __half* dst;
    if (i < NP_TOK) { src = tok; dst = tf; }
    else {
        i -= NP_TOK;
        if (i < NP_W)          { src = Wq; dst = wq; }
        else if (i < 2 * NP_W) { i -= NP_W;     src = Wk; dst = wk; }
        else if (i < 3 * NP_W) { i -= 2 * NP_W; src = Wv; dst = wv; }
        else if (i < 4 * NP_W) { i -= 3 * NP_W; src = Wo; dst = wo; }
        else if (i < 4 * NP_W + NP_WF) { i -= 4 * NP_W; src = W1; dst = w1; }
        else { i -= 4 * NP_W + NP_WF; src = W2; dst = w2; }
    }
    float2 x = *(const float2*)(src + 2 * i);
    *(__half2*)(dst + 2 * i) = __floats2half2_rn(x.x, x.y);
}

// ----------------------------------------------------------------------------
// Single-term fp16 HMMA GEMM core, MTILE x NTILE, BK=32, 256 thr.
// 3-stage cp.async ring, one __syncthreads per k-chunk. 2 CTAs/SM.
// ----------------------------------------------------------------------------
template <int MTILE, int NTILE, bool TRANSB>
struct GCfg {
    static constexpr int WM = MTILE / 64;
    static constexpr int WN = 8 / WM;
    static constexpr int WARP_N = NTILE / WN;
    static constexpr int NI = WARP_N / 8;
    static constexpr int NB2 = WARP_N / 16;
    static constexpr int BPITCH = NTILE * 2 + 16;
    static constexpr int ASLOT = MTILE * 80;
    static constexpr int BSLOT = TRANSB ? NTILE * 80 : 32 * BPITCH;
    static constexpr int STAGE = ASLOT + BSLOT;
    static constexpr int SMEM = 3 * STAGE;
};

template <int MTILE, int NTILE, bool TRANSB, bool GELU, bool F16OUT>
__device__ __forceinline__ void hgemm_core(
    const __half* __restrict__ A, const __half* __restrict__ B,
    const float* __restrict__ bias, const float* __restrict__ resid,
    float* __restrict__ C, __half* __restrict__ Of,
    int N, int K, int m0, int n0, char* smbase) {
    using CF = GCfg<MTILE, NTILE, TRANSB>;
    const int t = threadIdx.x;
    const int lane = t & 31, wid = t >> 5;
    const int wm = wid % CF::WM, wn = wid / CF::WM;
    const uint32_t sU = smem_u32(smbase);

    auto load_tile = [&](int s, int kc) {
        const int k0 = kc * 32;
        const uint32_t sb = sU + (uint32_t)(s * CF::STAGE);
        // A: MTILE rows x 32 k
#pragma unroll
        for (int i = 0; i < MTILE / 64; i++) {
            int e = t + i * 256;
            int row = e >> 2, c = e & 3;
            cp16(sb + row * 80 + c * 16, A + (size_t)(m0 + row) * K + k0 + c * 8);
        }
        // B
        if (!TRANSB) {
            constexpr int OPS = 32 * NTILE / 8;
#pragma unroll
            for (int i = 0; i < (OPS + 255) / 256; i++) {
                int e = t + i * 256;
                if (OPS >= 256 * (i + 1) || e < OPS) {
                    int row = e / (NTILE / 8), c = e % (NTILE / 8);
                    cp16(sb + CF::ASLOT + row * CF::BPITCH + c * 16,
                         B + (size_t)(k0 + row) * N + n0 + c * 8);
                }
            }
        } else {
#pragma unroll
            for (int i = 0; i < NTILE / 64; i++) {
                int e = t + i * 256;
                int row = e >> 2, c = e & 3;
                int nr = n0 + row;
                if (nr >= N) nr = 0;
                cp16(sb + CF::ASLOT + row * 80 + c * 16,
                     B + (size_t)nr * K + k0 + c * 8);
            }
        }
        cp_commit();
    };

    const uint32_t aoff =
        (uint32_t)((wm * 64 + (lane & 7) + ((lane >> 3) & 1) * 8) * 80 +
                   (lane >> 4) * 16);
    uint32_t boff;
    if (!TRANSB)
        boff = (uint32_t)(((lane & 7) + ((lane >> 3) & 1) * 8) * CF::BPITCH +
                          (wn * CF::WARP_N + (lane >> 4) * 8) * 2);
    else
        boff = (uint32_t)((wn * CF::WARP_N + (lane & 7) + (lane >> 4) * 8) * 80 +
                          ((lane >> 3) & 1) * 16);

    float acc[4][CF::NI][4] = {};
    const int KT = K / 32;

    load_tile(0, 0);
    if (KT > 1) load_tile(1, 1);

    int stage = 0;
    for (int kc = 0; kc < KT; kc++) {
        if (kc + 1 < KT) cp_wait<1>(); else cp_wait<0>();
        __syncthreads();
        if (kc + 2 < KT) {
            int s2 = stage + 2; if (s2 >= 3) s2 -= 3;
            load_tile(s2, kc + 2);
        }
        const uint32_t sb = sU + (uint32_t)(stage * CF::STAGE);
#pragma unroll
        for (int ks = 0; ks < 2; ks++) {
            uint32_t ah[4][4], bh[CF::NB2][4];
#pragma unroll
            for (int mi = 0; mi < 4; mi++)
                ldsm4(ah[mi], sb + aoff + mi * (16 * 80) + ks * 32);
#pragma unroll
            for (int n2 = 0; n2 < CF::NB2; n2++) {
                if (!TRANSB)
                    ldsm4t(bh[n2], sb + CF::ASLOT + boff + n2 * 32 + ks * (16 * CF::BPITCH));
                else
                    ldsm4(bh[n2], sb + CF::ASLOT + boff + n2 * (16 * 80) + ks * 32);
            }
#pragma unroll
            for (int mi = 0; mi < 4; mi++)
#pragma unroll
                for (int ni = 0; ni < CF::NI; ni++)
                    mma16816h(acc[mi][ni], ah[mi], &bh[ni >> 1][(ni & 1) * 2]);
        }
        if (++stage == 3) stage = 0;
    }

    // Epilogue
#pragma unroll
    for (int mi = 0; mi < 4; mi++) {
        const int r0 = m0 + wm * 64 + mi * 16 + (lane >> 2);
#pragma unroll
        for (int ni = 0; ni < CF::NI; ni++) {
            const int col = n0 + wn * CF::WARP_N + ni * 8 + (lane & 3) * 2;
            float v0 = acc[mi][ni][0], v1 = acc[mi][ni][1];
            float v2 = acc[mi][ni][2], v3 = acc[mi][ni][3];
            if (bias) {
                float b0 = (!TRANSB || col < N) ? bias[col] : 0.f;
                float b1 = (!TRANSB || col + 1 < N) ? bias[col + 1] : 0.f;
                v0 += b0; v1 += b1; v2 += b0; v3 += b1;
            }
            if (GELU) {
                v0 = 0.5f * v0 * (1.f + erff(v0 * 0.70710678118654752f));
                v1 = 0.5f * v1 * (1.f + erff(v1 * 0.70710678118654752f));
                v2 = 0.5f * v2 * (1.f + erff(v2 * 0.70710678118654752f));
                v3 = 0.5f * v3 * (1.f + erff(v3 * 0.70710678118654752f));
            }
            size_t o0 = (size_t)r0 * N + col;
            size_t o1 = o0 + (size_t)8 * N;
            if (F16OUT) {
                *(uint32_t*)(Of + o0) = pack_h2(v0, v1);
                *(uint32_t*)(Of + o1) = pack_h2(v2, v3);
            } else if (!TRANSB) {
                if (resid) {
                    float2 rr0 = *(const float2*)(resid + o0);
                    float2 rr1 = *(const float2*)(resid + o1);
                    v0 += rr0.x; v1 += rr0.y; v2 += rr1.x; v3 += rr1.y;
                }
                *(float2*)(C + o0) = make_float2(v0, v1);
                *(float2*)(C + o1) = make_float2(v2, v3);
            } else {
                if (col < N)     { C[o0] = v0; C[o1] = v2; }
                if (col + 1 < N) { C[o0 + 1] = v1; C[o1 + 1] = v3; }
            }
        }
    }
}

// Wo / W2: 128x64 tiles, fp32 + residual, 2 CTAs/SM
constexpr int SMEM_RES = GCfg<128, 64, false>::SMEM;
__global__ __launch_bounds__(256, 2)
void gemm_res_kernel(const __half* __restrict__ A, const __half* __restrict__ B,
                     const float* __restrict__ bias, const float* __restrict__ resid,
                     float* __restrict__ C, int N, int K) {
    extern __shared__ char sm[];
    hgemm_core<128, 64, false, false, false>(A, B, bias, resid, C, nullptr,
                                             N, K, blockIdx.y * 128,
                                             blockIdx.x * 64, sm);
}

// W1: 128x128 tiles, GELU + fp16 out, 2 CTAs/SM
constexpr int SMEM_BIG = GCfg<128, 128, false>::SMEM;
__global__ __launch_bounds__(256, 2)
void gemm_gelu_kernel(const __half* __restrict__ A, const __half* __restrict__ B,
                      const float* __restrict__ bias, __half* __restrict__ Of,
                      int N, int K) {
    extern __shared__ char sm[];
    hgemm_core<128, 128, false, true, true>(A, B, bias, nullptr, nullptr, Of,
                                            N, K, blockIdx.y * 128,
                                            blockIdx.x * 128, sm);
}

// QKV fused: 128x128, fp16 out, 2 CTAs/SM
__global__ __launch_bounds__(256, 2)
void qkv_kernel(const __half* __restrict__ A,
                const __half* __restrict__ W0, const __half* __restrict__ W1_,
                const __half* __restrict__ W2_,
                const float* __restrict__ c0, const float* __restrict__ c1,
                const float* __restrict__ c2,
                __half* __restrict__ q, __half* __restrict__ k,
                __half* __restrict__ v) {
    extern __shared__ char sm[];
    int z = blockIdx.z;
    const __half* B = (z == 0) ? W0 : (z == 1) ? W1_ : W2_;
    const float* bi = (z == 0) ? c0 : (z == 1) ? c1 : c2;
    __half* Of = (z == 0) ? q : (z == 1) ? k : v;
    hgemm_core<128, 128, false, false, true>(A, B, bi, nullptr, nullptr, Of,
                                             CD, CD, blockIdx.y * 128,
                                             blockIdx.x * 128, sm);
}

// lm_head: 128x128, TRANSB, fp32 out, m-fast grid, 2 CTAs/SM
constexpr int SMEM_LMH = GCfg<128, 128, true>::SMEM;
__global__ __launch_bounds__(256, 2)
void lmhead_kernel(const __half* __restrict__ A, const __half* __restrict__ T,
                   float* __restrict__ out) {
    extern __shared__ char sm[];
    hgemm_core<128, 128, true, false, false>(A, T, nullptr, nullptr, out, nullptr,
                                             CV, CD, blockIdx.x * 128,
                                             blockIdx.y * 128, sm);
}

// ----------------------------------------------------------------------------
// fp16 HMMA flash attention, causal-folded, BOTH halves concurrent:
// 256 threads; warps 0-3 do q-tile bx, warps 4-7 do q-tile 31-bx.
// Each half has its own smem region + named barrier. Grid (16, B*H).
// ----------------------------------------------------------------------------
constexpr int AP = 72;
constexpr int TILEB = 64 * AP * 2;              // 9216 B per 64x64 fp16 tile
constexpr int ATTN_SMEM = 2 * 5 * TILEB;        // 2 halves x (Q + 2x(K,V))

__global__ __launch_bounds__(256)
void attn_kernel(const __half* __restrict__ Q, const __half* __restrict__ Km,
                 const __half* __restrict__ Vm, __half* __restrict__ At) {
    extern __shared__ char sm[];
    const int t = threadIdx.x;
    const int lane = t & 31;
    const int wid = t >> 5;
    const int half = wid >> 2;                  // 0 or 1
    const int w = wid & 3;
    const int t128 = t & 127;
    const int barid = 1 + half;

    char* smh = sm + half * 5 * TILEB;
    const uint32_t hU = smem_u32(smh);
    const uint32_t qU = hU;
    const uint32_t kvU = hU + TILEB;            // [buf][K, V]

    const int bh = blockIdx.y;
    const int b = bh >> 2, h = bh & 3;
    const size_t base = (size_t)b * CS * CD + (size_t)h * CHD;
    const int qt = half ? (31 - (int)blockIdx.x) : (int)blockIdx.x;
    const int q0 = qt * 64;

    auto load_kv = [&](int buf, int kt) {
        const int k0 = kt * 64;
#pragma unroll
        for (int a = 0; a < 2; a++) {
            const __half* src = (a ? Vm : Km) + base + (size_t)k0 * CD;
            const uint32_t dbase = kvU + (buf * 2 + a) * TILEB;
#pragma unroll
            for (int i = 0; i < 4; i++) {
                int e = t128 + i * 128;
                int row = e >> 3, c = e & 7;
                cp16(dbase + row * (AP * 2) + c * 16, src + (size_t)row * CD + c * 8);
            }
        }
        cp_commit();
    };

    load_kv(0, 0);
    {   // stage Q
        const __half* src = Q + base + (size_t)q0 * CD;
#pragma unroll
        for (int i = 0; i < 4; i++) {
            int e = t128 + i * 128;
            int row = e >> 3, c = e & 7;
            *(uint4*)(smh + row * (AP * 2) + c * 16) =
                *(const uint4*)(src + (size_t)row * CD + c * 8);
        }
    }
    barx(barid);

    uint32_t qf[4][4];
    {
        const uint32_t aoff =
            (uint32_t)((w * 16 + (lane & 7) + ((lane >> 3) & 1) * 8) * (AP * 2) +
                       (lane >> 4) * 16);
#pragma unroll
        for (int ks = 0; ks < 4; ks++)
            ldsm4(qf[ks], qU + aoff + ks * 32);
    }

    float acc[8][4] = {};
    float m_0 = -1e30f, m_1 = -1e30f, l_0 = 0.f, l_1 = 0.f;
    const int rl0 = w * 16 + (lane >> 2);

    for (int kt = 0; kt <= qt; kt++) {
        const int buf = kt & 1;
        const bool more = kt < qt;
        if (more) { load_kv(buf ^ 1, kt + 1); cp_wait<1>(); }
        else      { cp_wait<0>(); }
        barx(barid);

        const uint32_t kBuf = kvU + (buf * 2 + 0) * TILEB;
        const uint32_t vBuf = kvU + (buf * 2 + 1) * TILEB;

        float st[8][4] = {};
#pragma unroll
        for (int ks = 0; ks < 4; ks++) {
            uint32_t kf[4][4];
#pragma unroll
            for (int nt = 0; nt < 4; nt++) {
                uint32_t ko =
                    (uint32_t)((nt * 16 + (lane & 7) + (lane >> 4) * 8) * (AP * 2) +
                               ((lane >> 3) & 1) * 16 + ks * 32);
                ldsm4(kf[nt], kBuf + ko);
            }
#pragma unroll
            for (int ni = 0; ni < 8; ni++)
                mma16816h(st[ni], qf[ks], &kf[ni >> 1][(ni & 1) * 2]);
        }

#pragma unroll
        for (int ni = 0; ni < 8; ni++)
#pragma unroll
            for (int e = 0; e < 4; e++) st[ni][e] *= 0.125f;
        if (kt == qt) {
#pragma unroll
            for (int ni = 0; ni < 8; ni++) {
                int cb = ni * 8 + (lane & 3) * 2;
                if (cb > rl0)         st[ni][0] = -1e30f;
                if (cb + 1 > rl0)     st[ni][1] = -1e30f;
                if (cb > rl0 + 8)     st[ni][2] = -1e30f;
                if (cb + 1 > rl0 + 8) st[ni][3] = -1e30f;
            }
        }

        float t0 = -1e30f, t1 = -1e30f;
#pragma unroll
        for (int ni = 0; ni < 8; ni++) {
            t0 = fmaxf(t0, fmaxf(st[ni][0], st[ni][1]));
            t1 = fmaxf(t1, fmaxf(st[ni][2], st[ni][3]));
        }
        t0 = fmaxf(t0, __shfl_xor_sync(0xffffffffu, t0, 1));
        t0 = fmaxf(t0, __shfl_xor_sync(0xffffffffu, t0, 2));
        t1 = fmaxf(t1, __shfl_xor_sync(0xffffffffu, t1, 1));
        t1 = fmaxf(t1, __shfl_xor_sync(0xffffffffu, t1, 2));
        float mn0 = fmaxf(m_0, t0), mn1 = fmaxf(m_1, t1);
        float fr0 = __expf(m_0 - mn0), fr1 = __expf(m_1 - mn1);
        m_0 = mn0; m_1 = mn1;
        float ps0 = 0.f, ps1 = 0.f;
#pragma unroll
        for (int ni = 0; ni < 8; ni++) {
            float p0 = __expf(st[ni][0] - mn0); st[ni][0] = p0; ps0 += p0;
            float p1 = __expf(st[ni][1] - mn0); st[ni][1] = p1; ps0 += p1;
            float p2 = __expf(st[ni][2] - mn1); st[ni][2] = p2; ps1 += p2;
            float p3 = __expf(st[ni][3] - mn1); st[ni][3] = p3; ps1 += p3;
        }
        ps0 += __shfl_xor_sync(0xffffffffu, ps0, 1);
        ps0 += __shfl_xor_sync(0xffffffffu, ps0, 2);
        ps1 += __shfl_xor_sync(0xffffffffu, ps1, 1);
        ps1 += __shfl_xor_sync(0xffffffffu, ps1, 2);
        l_0 = l_0 * fr0 + ps0;
        l_1 = l_1 * fr1 + ps1;
#pragma unroll
        for (int ni = 0; ni < 8; ni++) {
            acc[ni][0] *= fr0; acc[ni][1] *= fr0;
            acc[ni][2] *= fr1; acc[ni][3] *= fr1;
        }

        // O += P @ V
#pragma unroll
        for (int ks = 0; ks < 4; ks++) {
            uint32_t pa[4];
            pa[0] = pack_h2(st[2 * ks][0],     st[2 * ks][1]);
            pa[1] = pack_h2(st[2 * ks][2],     st[2 * ks][3]);
            pa[2] = pack_h2(st[2 * ks + 1][0], st[2 * ks + 1][1]);
            pa[3] = pack_h2(st[2 * ks + 1][2], st[2 * ks + 1][3]);
            uint32_t vf[4][4];
#pragma unroll
            for (int vt = 0; vt < 4; vt++) {
                uint32_t vo =
                    (uint32_t)(((lane & 7) + ((lane >> 3) & 1) * 8 + ks * 16) * (AP * 2) +
                               (vt * 16 + (lane >> 4) * 8) * 2);
                ldsm4t(vf[vt], vBuf + vo);
            }
#pragma unroll
            for (int ni = 0; ni < 8; ni++)
                mma16816h(acc[ni], pa, &vf[ni >> 1][(ni & 1) * 2]);
        }
        barx(barid);
    }

    float i0 = 1.f / l_0, i1 = 1.f / l_1;
    const int r0 = q0 + rl0;
#pragma unroll
    for (int ni = 0; ni < 8; ni++) {
        int col = ni * 8 + (lane & 3) * 2;
        size_t o = base + (size_t)r0 * CD + col;
        *(uint32_t*)(At + o) = pack_h2(acc[ni][0] * i0, acc[ni][1] * i0);
        *(uint32_t*)(At + o + (size_t)8 * CD) =
            pack_h2(acc[ni][2] * i1, acc[ni][3] * i1);
    }
}

// ----------------------------------------------------------------------------
// Embedding / LayerNorm
// ----------------------------------------------------------------------------
__global__ void embed_kernel(const int* __restrict__ ids,
                             const float* __restrict__ tok,
                             const float* __restrict__ pos,
                             float* __restrict__ h) {
    int i = blockIdx.x;
    int d = threadIdx.x;
    int s = i & (CS - 1);
    h[(size_t)i * CD + d] = tok[(size_t)ids[i] * CD + d] + pos[(size_t)s * CD + d];
}

__global__ void ln_kernel(const float* __restrict__ x,
                          const float* __restrict__ sc,
                          const float* __restrict__ bi,
                          __half* __restrict__ yf) {
    int row = blockIdx.x * 8 + threadIdx.y;   // blockDim (32, 8)
    int lane = threadIdx.x;
    const float* xr = x + (size_t)row * CD;
    float v[8];
    float sum = 0.f, sq = 0.f;
#pragma unroll
    for (int j = 0; j < 8; j++) {
        v[j] = xr[lane * 8 + j];
        sum += v[j];
        sq += v[j] * v[j];
    }
#pragma unroll
    for (int o = 16; o > 0; o >>= 1) {
        sum += __shfl_xor_sync(0xffffffffu, sum, o);
        sq  += __shfl_xor_sync(0xffffffffu, sq, o);
    }
    float mean = sum * (1.f / CD);
    float var  = sq * (1.f / CD) - mean * mean;
    float inv  = rsqrtf(var + 1e-5f);
    size_t off = (size_t)row * CD + lane * 8;
    __half2 f[4];
#pragma unroll
    for (int j = 0; j < 4; j++) {
        int c = lane * 8 + 2 * j;
        float y0 = (v[2 * j]     - mean) * inv * sc[c]     + bi[c];
        float y1 = (v[2 * j + 1] - mean) * inv * sc[c + 1] + bi[c + 1];
        f[j] = __floats2half2_rn(y0, y1);
    }
    *(uint4*)(yf + off) = *(uint4*)f;
}

// ----------------------------------------------------------------------------
// Orchestration
// ----------------------------------------------------------------------------
extern "C" void kernel_launch(void* const* d_in, const int* in_sizes, int n_in,
                              void* d_out, int out_size) {
    const int*   ids  = (const int*)d_in[0];
    const float* tok  = (const float*)d_in[1];
    const float* pos  = (const float*)d_in[2];
    const float* Wq   = (const float*)d_in[3];
    const float* bq   = (const float*)d_in[4];
    const float* Wk   = (const float*)d_in[5];
    const float* bk   = (const float*)d_in[6];
    const float* Wv   = (const float*)d_in[7];
    const float* bv   = (const float*)d_in[8];
    const float* Wo   = (const float*)d_in[9];
    const float* bo   = (const float*)d_in[10];
    const float* ln1s = (const float*)d_in[11];
    const float* ln1b = (const float*)d_in[12];
    const float* ln2s = (const float*)d_in[13];
    const float* ln2b = (const float*)d_in[14];
    const float* W1   = (const float*)d_in[15];
    const float* b1   = (const float*)d_in[16];
    const float* W2   = (const float*)d_in[17];
    const float* b2   = (const float*)d_in[18];
    const float* lnfs = (const float*)d_in[19];
    const float* lnfb = (const float*)d_in[20];
    float* out = (float*)d_out;

    float* h;
    __half *n, *q, *k, *v, *att, *m, *tf, *wq, *wk, *wv, *wo, *w1, *w2;
    cudaGetSymbolAddress((void**)&h,   g_h);
    cudaGetSymbolAddress((void**)&n,   g_n);
    cudaGetSymbolAddress((void**)&q,   g_q);
    cudaGetSymbolAddress((void**)&k,   g_k);
    cudaGetSymbolAddress((void**)&v,   g_v);
    cudaGetSymbolAddress((void**)&att, g_att);
    cudaGetSymbolAddress((void**)&m,   g_m);
    cudaGetSymbolAddress((void**)&tf,  g_tf);
    cudaGetSymbolAddress((void**)&wq,  g_wq);
    cudaGetSymbolAddress((void**)&wk,  g_wk);
    cudaGetSymbolAddress((void**)&wv,  g_wv);
    cudaGetSymbolAddress((void**)&wo,  g_wo);
    cudaGetSymbolAddress((void**)&w1,  g_w1);
    cudaGetSymbolAddress((void**)&w2,  g_w2);

    cudaFuncSetAttribute(attn_kernel,
                         cudaFuncAttributeMaxDynamicSharedMemorySize, ATTN_SMEM);
    cudaFuncSetAttribute(gemm_res_kernel,
                         cudaFuncAttributeMaxDynamicSharedMemorySize, SMEM_RES);
    cudaFuncSetAttribute(gemm_gelu_kernel,
                         cudaFuncAttributeMaxDynamicSharedMemorySize, SMEM_BIG);
    cudaFuncSetAttribute(qkv_kernel,
                         cudaFuncAttributeMaxDynamicSharedMemorySize, SMEM_BIG);
    cudaFuncSetAttribute(lmhead_kernel,
                         cudaFuncAttributeMaxDynamicSharedMemorySize, SMEM_LMH);

    convert_all_kernel<<<(unsigned)((NP_TOT + 255) / 256), 256>>>(
        tok, Wq, Wk, Wv, Wo, W1, W2, tf, wq, wk, wv, wo, w1, w2);

    dim3 lnb(32, 8);
    embed_kernel<<<CM, CD>>>(ids, tok, pos, h);

    for (int l = 0; l < CL; l++) {
        size_t wofs  = (size_t)l * CD * CD;
        size_t bofs  = (size_t)l * CD;
        size_t w1ofs = (size_t)l * CD * CFF;
        size_t b1ofs = (size_t)l * CFF;
        size_t w2ofs = (size_t)l * CFF * CD;

        ln_kernel<<<CM / 8, lnb>>>(h, ln1s + bofs, ln1b + bofs, n);
        qkv_kernel<<<dim3(CD / 128, CM / 128, 3), 256, SMEM_BIG>>>(
            n, wq + wofs, wk + wofs, wv + wofs,
            bq + bofs, bk + bofs, bv + bofs, q, k, v);

        attn_kernel<<<dim3(16, CB * CH), 256, ATTN_SMEM>>>(q, k, v, att);

        gemm_res_kernel<<<dim3(CD / 64, CM / 128), 256, SMEM_RES>>>(
            att, wo + wofs, bo + bofs, h, h, CD, CD);

        ln_kernel<<<CM / 8, lnb>>>(h, ln2s + bofs, ln2b + bofs, n);
        gemm_gelu_kernel<<<dim3(CFF / 128, CM / 128), 256, SMEM_BIG>>>(
            n, w1 + w1ofs, b1 + b1ofs, m, CFF, CD);
        gemm_res_kernel<<<dim3(CD / 64, CM / 128), 256, SMEM_RES>>>(
            m, w2 + w2ofs, b2 + bofs, h, h, CD, CFF);
    }

    ln_kernel<<<CM / 8, lnb>>>(h, lnfs, lnfb, n);
    lmhead_kernel<<<dim3(CM / 128, (CV + 127) / 128), 256, SMEM_LMH>>>(
        n, tf, out);
}

// round 15
// speedup vs baseline: 8.1577x; 1.3297x over previous
#include <cuda_runtime.h>
#include <cuda_bf16.h>
#include <cuda_fp16.h>
#include <math.h>
#include <stdint.h>

// Problem constants
constexpr int CB = 2, CS = 2048, CD = 256, CH = 4, CL = 4, CV = 50257, CHD = 64;
constexpr int CM = CB * CS;      // 4096 rows
constexpr int CFF = 4 * CD;      // 1024

// ----------------------------------------------------------------------------
// Scratch (static device globals — no allocation inside kernel_launch)
// ----------------------------------------------------------------------------
__device__ float  g_h[CM * CD];
__device__ __half g_n[CM * CD];
__device__ __half g_q[CM * CD], g_k[CM * CD], g_v[CM * CD];
__device__ __half g_att[CM * CD];
__device__ __half g_m[CM * CFF];
__device__ __half g_tf[(size_t)CV * CD];
__device__ __half g_wq[CL * CD * CD], g_wk[CL * CD * CD];
__device__ __half g_wv[CL * CD * CD], g_wo[CL * CD * CD];
__device__ __half g_w1[CL * CD * CFF], g_w2[CL * CD * CFF];

// ----------------------------------------------------------------------------
// Helpers
// ----------------------------------------------------------------------------
__device__ __forceinline__ uint32_t smem_u32(const void* p) {
    uint32_t a;
    asm("{ .reg .u64 t; cvta.to.shared.u64 t, %1; cvt.u32.u64 %0, t; }"
        : "=r"(a) : "l"(p));
    return a;
}
__device__ __forceinline__ void ldsm4(uint32_t* r, uint32_t addr) {
    asm volatile("ldmatrix.sync.aligned.m8n8.x4.shared.b16 {%0,%1,%2,%3}, [%4];"
                 : "=r"(r[0]), "=r"(r[1]), "=r"(r[2]), "=r"(r[3]) : "r"(addr));
}
__device__ __forceinline__ void ldsm4t(uint32_t* r, uint32_t addr) {
    asm volatile("ldmatrix.sync.aligned.m8n8.x4.trans.shared.b16 {%0,%1,%2,%3}, [%4];"
                 : "=r"(r[0]), "=r"(r[1]), "=r"(r[2]), "=r"(r[3]) : "r"(addr));
}
__device__ __forceinline__ void mma16816h(float* c, const uint32_t* a, const uint32_t* b) {
    asm volatile("mma.sync.aligned.m16n8k16.row.col.f32.f16.f16.f32 "
                 "{%0,%1,%2,%3}, {%4,%5,%6,%7}, {%8,%9}, {%0,%1,%2,%3};"
                 : "+f"(c[0]), "+f"(c[1]), "+f"(c[2]), "+f"(c[3])
                 : "r"(a[0]), "r"(a[1]), "r"(a[2]), "r"(a[3]),
                   "r"(b[0]), "r"(b[1]));
}
__device__ __forceinline__ uint32_t pack_h2(float x, float y) {
    __half2 p = __floats2half2_rn(x, y);
    return *(uint32_t*)&p;
}
__device__ __forceinline__ void cp16(uint32_t dst, const void* src) {
    asm volatile("cp.async.ca.shared.global [%0], [%1], 16;" :: "r"(dst), "l"(src));
}
__device__ __forceinline__ void cp_commit() {
    asm volatile("cp.async.commit_group;" ::: "memory");
}
template <int N>
__device__ __forceinline__ void cp_wait() {
    asm volatile("cp.async.wait_group %0;" :: "n"(N) : "memory");
}
__device__ __forceinline__ void barx(int id) {   // named barrier, 128 threads
    asm volatile("bar.sync %0, 128;" :: "r"(id) : "memory");
}

// ----------------------------------------------------------------------------
// One-launch fp32 -> fp16 converter for tok_emb + all weights
// ----------------------------------------------------------------------------
constexpr size_t NP_TOK = (size_t)CV * CD / 2;
constexpr size_t NP_W   = (size_t)CL * CD * CD / 2;
constexpr size_t NP_WF  = (size_t)CL * CD * CFF / 2;
constexpr size_t NP_TOT = NP_TOK + 4 * NP_W + 2 * NP_WF;

__global__ void convert_all_kernel(
    const float* __restrict__ tok, const float* __restrict__ Wq,
    const float* __restrict__ Wk, const float* __restrict__ Wv,
    const float* __restrict__ Wo, const float* __restrict__ W1,
    const float* __restrict__ W2,
    __half* __restrict__ tf, __half* __restrict__ wq, __half* __restrict__ wk,
    __half* __restrict__ wv, __half* __restrict__ wo, __half* __restrict__ w1,
    __half* __restrict__ w2) {
    size_t i = (size_t)blockIdx.x * blockDim.x + threadIdx.x;
    if (i >= NP_TOT) return;
    const float* src; __half* dst;
    if (i < NP_TOK) { src = tok; dst = tf; }
    else {
        i -= NP_TOK;
        if (i < NP_W)          { src = Wq; dst = wq; }
        else if (i < 2 * NP_W) { i -= NP_W;     src = Wk; dst = wk; }
        else if (i < 3 * NP_W) { i -= 2 * NP_W; src = Wv; dst = wv; }
        else if (i < 4 * NP_W) { i -= 3 * NP_W; src = Wo; dst = wo; }
        else if (i < 4 * NP_W + NP_WF) { i -= 4 * NP_W; src = W1; dst = w1; }
        else { i -= 4 * NP_W + NP_WF; src = W2; dst = w2; }
    }
    float2 x = *(const float2*)(src + 2 * i);
    *(__half2*)(dst + 2 * i) = __floats2half2_rn(x.x, x.y);
}

// ----------------------------------------------------------------------------
// Single-term fp16 HMMA GEMM core, MTILE x NTILE, BK=64, 256 thr.
// 3-stage cp.async ring, one __syncthreads per k-chunk. 2 CTAs/SM.
// TRANSB epilogue: smem-staged, coalesced fp32 stores (N odd).
// ----------------------------------------------------------------------------
template <int MTILE, int NTILE, bool TRANSB>
struct GCfg {
    static constexpr int WM = MTILE / 64;
    static constexpr int WN = 8 / WM;
    static constexpr int WARP_N = NTILE / WN;
    static constexpr int NI = WARP_N / 8;
    static constexpr int NB2 = WARP_N / 16;
    static constexpr int BPITCH = NTILE * 2 + 16;   // !TRANSB B row pitch (bytes)
    static constexpr int APITCH = 144;              // 64 fp16 + 16B pad
    static constexpr int ASLOT = MTILE * APITCH;
    static constexpr int BSLOT = TRANSB ? NTILE * APITCH : 64 * BPITCH;
    static constexpr int STAGE = ASLOT + BSLOT;
    static constexpr int SMEM = 3 * STAGE;
};

template <int MTILE, int NTILE, bool TRANSB, bool GELU, bool F16OUT>
__device__ __forceinline__ void hgemm_core(
    const __half* __restrict__ A, const __half* __restrict__ B,
    const float* __restrict__ bias, const float* __restrict__ resid,
    float* __restrict__ C, __half* __restrict__ Of,
    int N, int K, int m0, int n0, char* smbase) {
    using CF = GCfg<MTILE, NTILE, TRANSB>;
    const int t = threadIdx.x;
    const int lane = t & 31, wid = t >> 5;
    const int wm = wid % CF::WM, wn = wid / CF::WM;
    const uint32_t sU = smem_u32(smbase);

    auto load_tile = [&](int s, int kc) {
        const int k0 = kc * 64;
        const uint32_t sb = sU + (uint32_t)(s * CF::STAGE);
        // A: MTILE rows x 64 k
#pragma unroll
        for (int i = 0; i < MTILE / 32; i++) {
            int e = t + i * 256;
            int row = e >> 3, c = e & 7;
            cp16(sb + row * CF::APITCH + c * 16,
                 A + (size_t)(m0 + row) * K + k0 + c * 8);
        }
        // B
        if (!TRANSB) {                    // 64 k-rows x NTILE
            constexpr int OPS = 64 * NTILE / 8;
#pragma unroll
            for (int i = 0; i < OPS / 256; i++) {
                int e = t + i * 256;
                int row = e / (NTILE / 8), c = e % (NTILE / 8);
                cp16(sb + CF::ASLOT + row * CF::BPITCH + c * 16,
                     B + (size_t)(k0 + row) * N + n0 + c * 8);
            }
        } else {                          // NTILE n-rows x 64 k
#pragma unroll
            for (int i = 0; i < NTILE / 32; i++) {
                int e = t + i * 256;
                int row = e >> 3, c = e & 7;
                int nr = n0 + row;
                if (nr >= N) nr = 0;
                cp16(sb + CF::ASLOT + row * CF::APITCH + c * 16,
                     B + (size_t)nr * K + k0 + c * 8);
            }
        }
        cp_commit();
    };

    const uint32_t aoff =
        (uint32_t)((wm * 64 + (lane & 7) + ((lane >> 3) & 1) * 8) * CF::APITCH +
                   (lane >> 4) * 16);
    uint32_t boff;
    if (!TRANSB)
        boff = (uint32_t)(((lane & 7) + ((lane >> 3) & 1) * 8) * CF::BPITCH +
                          (wn * CF::WARP_N + (lane >> 4) * 8) * 2);
    else
        boff = (uint32_t)((wn * CF::WARP_N + (lane & 7) + (lane >> 4) * 8) * CF::APITCH +
                          ((lane >> 3) & 1) * 16);

    float acc[4][CF::NI][4] = {};
    const int KT = K / 64;

    load_tile(0, 0);
    if (KT > 1) load_tile(1, 1);

    int stage = 0;
    for (int kc = 0; kc < KT; kc++) {
        if (kc + 1 < KT) cp_wait<1>(); else cp_wait<0>();
        __syncthreads();
        if (kc + 2 < KT) {
            int s2 = stage + 2; if (s2 >= 3) s2 -= 3;
            load_tile(s2, kc + 2);
        }
        const uint32_t sb = sU + (uint32_t)(stage * CF::STAGE);
#pragma unroll
        for (int ks = 0; ks < 4; ks++) {
            uint32_t ah[4][4], bh[CF::NB2][4];
#pragma unroll
            for (int mi = 0; mi < 4; mi++)
                ldsm4(ah[mi], sb + aoff + mi * (16 * CF::APITCH) + ks * 32);
#pragma unroll
            for (int n2 = 0; n2 < CF::NB2; n2++) {
                if (!TRANSB)
                    ldsm4t(bh[n2], sb + CF::ASLOT + boff + n2 * 32 + ks * (16 * CF::BPITCH));
                else
                    ldsm4(bh[n2], sb + CF::ASLOT + boff + n2 * (16 * CF::APITCH) + ks * 32);
            }
#pragma unroll
            for (int mi = 0; mi < 4; mi++)
#pragma unroll
                for (int ni = 0; ni < CF::NI; ni++)
                    mma16816h(acc[mi][ni], ah[mi], &bh[ni >> 1][(ni & 1) * 2]);
        }
        if (++stage == 3) stage = 0;
    }

    if (TRANSB) {
        // Staged, coalesced fp32 epilogue (lm_head; MTILE=128, NTILE=128)
        constexpr int PIT = 132;              // fp32 pitch
        float* stg = (float*)smbase;          // 128*132*4 = 67584 B <= SMEM
        __syncthreads();                      // pipeline buffers done
#pragma unroll
        for (int mi = 0; mi < 4; mi++) {
            int lr = wm * 64 + mi * 16 + (lane >> 2);
#pragma unroll
            for (int ni = 0; ni < CF::NI; ni++) {
                int lc = wn * CF::WARP_N + ni * 8 + (lane & 3) * 2;
                stg[lr * PIT + lc]           = acc[mi][ni][0];
                stg[lr * PIT + lc + 1]       = acc[mi][ni][1];
                stg[(lr + 8) * PIT + lc]     = acc[mi][ni][2];
                stg[(lr + 8) * PIT + lc + 1] = acc[mi][ni][3];
            }
        }
        __syncthreads();
#pragma unroll 4
        for (int i = 0; i < (MTILE * NTILE) / 256; i++) {
            int e = t + i * 256;
            int row = e / NTILE, col = e % NTILE;
            int gn = n0 + col;
            if (gn < N)
                C[(size_t)(m0 + row) * N + gn] = stg[row * PIT + col];
        }
        return;
    }

    // Direct epilogue (non-TRANSB)
#pragma unroll
    for (int mi = 0; mi < 4; mi++) {
        const int r0 = m0 + wm * 64 + mi * 16 + (lane >> 2);
#pragma unroll
        for (int ni = 0; ni < CF::NI; ni++) {
            const int col = n0 + wn * CF::WARP_N + ni * 8 + (lane & 3) * 2;
            float v0 = acc[mi][ni][0], v1 = acc[mi][ni][1];
            float v2 = acc[mi][ni][2], v3 = acc[mi][ni][3];
            if (bias) {
                float b0 = bias[col], b1 = bias[col + 1];
                v0 += b0; v1 += b1; v2 += b0; v3 += b1;
            }
            if (GELU) {
                v0 = 0.5f * v0 * (1.f + erff(v0 * 0.70710678118654752f));
                v1 = 0.5f * v1 * (1.f + erff(v1 * 0.70710678118654752f));
                v2 = 0.5f * v2 * (1.f + erff(v2 * 0.70710678118654752f));
                v3 = 0.5f * v3 * (1.f + erff(v3 * 0.70710678118654752f));
            }
            size_t o0 = (size_t)r0 * N + col;
            size_t o1 = o0 + (size_t)8 * N;
            if (F16OUT) {
                *(uint32_t*)(Of + o0) = pack_h2(v0, v1);
                *(uint32_t*)(Of + o1) = pack_h2(v2, v3);
            } else {
                if (resid) {
                    float2 rr0 = *(const float2*)(resid + o0);
                    float2 rr1 = *(const float2*)(resid + o1);
                    v0 += rr0.x; v1 += rr0.y; v2 += rr1.x; v3 += rr1.y;
                }
                *(float2*)(C + o0) = make_float2(v0, v1);
                *(float2*)(C + o1) = make_float2(v2, v3);
            }
        }
    }
}

// Wo / W2: 128x64 tiles, fp32 + residual, 2 CTAs/SM
constexpr int SMEM_RES = GCfg<128, 64, false>::SMEM;
__global__ __launch_bounds__(256, 2)
void gemm_res_kernel(const __half* __restrict__ A, const __half* __restrict__ B,
                     const float* __restrict__ bias, const float* __restrict__ resid,
                     float* __restrict__ C, int N, int K) {
    extern __shared__ char sm[];
    hgemm_core<128, 64, false, false, false>(A, B, bias, resid, C, nullptr,
                                             N, K, blockIdx.y * 128,
                                             blockIdx.x * 64, sm);
}

// W1: 128x128 tiles, GELU + fp16 out, 2 CTAs/SM
constexpr int SMEM_BIG = GCfg<128, 128, false>::SMEM;
__global__ __launch_bounds__(256, 2)
void gemm_gelu_kernel(const __half* __restrict__ A, const __half* __restrict__ B,
                      const float* __restrict__ bias, __half* __restrict__ Of,
                      int N, int K) {
    extern __shared__ char sm[];
    hgemm_core<128, 128, false, true, true>(A, B, bias, nullptr, nullptr, Of,
                                            N, K, blockIdx.y * 128,
                                            blockIdx.x * 128, sm);
}

// QKV fused: 128x128, fp16 out, 2 CTAs/SM
__global__ __launch_bounds__(256, 2)
void qkv_kernel(const __half* __restrict__ A,
                const __half* __restrict__ W0, const __half* __restrict__ W1_,
                const __half* __restrict__ W2_,
                const float* __restrict__ c0, const float* __restrict__ c1,
                const float* __restrict__ c2,
                __half* __restrict__ q, __half* __restrict__ k,
                __half* __restrict__ v) {
    extern __shared__ char sm[];
    int z = blockIdx.z;
    const __half* B = (z == 0) ? W0 : (z == 1) ? W1_ : W2_;
    const float* bi = (z == 0) ? c0 : (z == 1) ? c1 : c2;
    __half* Of = (z == 0) ? q : (z == 1) ? k : v;
    hgemm_core<128, 128, false, false, true>(A, B, bi, nullptr, nullptr, Of,
                                             CD, CD, blockIdx.y * 128,
                                             blockIdx.x * 128, sm);
}

// lm_head: 128x128, TRANSB, fp32 out staged+coalesced, m-fast grid, 2 CTAs/SM
constexpr int SMEM_LMH = GCfg<128, 128, true>::SMEM;
__global__ __launch_bounds__(256, 2)
void lmhead_kernel(const __half* __restrict__ A, const __half* __restrict__ T,
                   float* __restrict__ out) {
    extern __shared__ char sm[];
    hgemm_core<128, 128, true, false, false>(A, T, nullptr, nullptr, out, nullptr,
                                             CV, CD, blockIdx.x * 128,
                                             blockIdx.y * 128, sm);
}

// ----------------------------------------------------------------------------
// fp16 HMMA flash attention, causal-folded, both halves concurrent (256 thr).
// ----------------------------------------------------------------------------
constexpr int AP = 72;
constexpr int TILEB = 64 * AP * 2;
constexpr int ATTN_SMEM = 2 * 5 * TILEB;

__global__ __launch_bounds__(256)
void attn_kernel(const __half* __restrict__ Q, const __half* __restrict__ Km,
                 const __half* __restrict__ Vm, __half* __restrict__ At) {
    extern __shared__ char sm[];
    const int t = threadIdx.x;
    const int lane = t & 31;
    const int wid = t >> 5;
    const int half = wid >> 2;
    const int w = wid & 3;
    const int t128 = t & 127;
    const int barid = 1 + half;

    char* smh = sm + half * 5 * TILEB;
    const uint32_t hU = smem_u32(smh);
    const uint32_t qU = hU;
    const uint32_t kvU = hU + TILEB;

    const int bh = blockIdx.y;
    const int b = bh >> 2, h = bh & 3;
    const size_t base = (size_t)b * CS * CD + (size_t)h * CHD;
    const int qt = half ? (31 - (int)blockIdx.x) : (int)blockIdx.x;
    const int q0 = qt * 64;

    auto load_kv = [&](int buf, int kt) {
        const int k0 = kt * 64;
#pragma unroll
        for (int a = 0; a < 2; a++) {
            const __half* src = (a ? Vm : Km) + base + (size_t)k0 * CD;
            const uint32_t dbase = kvU + (buf * 2 + a) * TILEB;
#pragma unroll
            for (int i = 0; i < 4; i++) {
                int e = t128 + i * 128;
                int row = e >> 3, c = e & 7;
                cp16(dbase + row * (AP * 2) + c * 16, src + (size_t)row * CD + c * 8);
            }
        }
        cp_commit();
    };

    load_kv(0, 0);
    {
        const __half* src = Q + base + (size_t)q0 * CD;
#pragma unroll
        for (int i = 0; i < 4; i++) {
            int e = t128 + i * 128;
            int row = e >> 3, c = e & 7;
            *(uint4*)(smh + row * (AP * 2) + c * 16) =
                *(const uint4*)(src + (size_t)row * CD + c * 8);
        }
    }
    barx(barid);

    uint32_t qf[4][4];
    {
        const uint32_t aoff =
            (uint32_t)((w * 16 + (lane & 7) + ((lane >> 3) & 1) * 8) * (AP * 2) +
                       (lane >> 4) * 16);
#pragma unroll
        for (int ks = 0; ks < 4; ks++)
            ldsm4(qf[ks], qU + aoff + ks * 32);
    }

    float acc[8][4] = {};
    float m_0 = -1e30f, m_1 = -1e30f, l_0 = 0.f, l_1 = 0.f;
    const int rl0 = w * 16 + (lane >> 2);

    for (int kt = 0; kt <= qt; kt++) {
        const int buf = kt & 1;
        const bool more = kt < qt;
        if (more) { load_kv(buf ^ 1, kt + 1); cp_wait<1>(); }
        else      { cp_wait<0>(); }
        barx(barid);

        const uint32_t kBuf = kvU + (buf * 2 + 0) * TILEB;
        const uint32_t vBuf = kvU + (buf * 2 + 1) * TILEB;

        float st[8][4] = {};
#pragma unroll
        for (int ks = 0; ks < 4; ks++) {
            uint32_t kf[4][4];
#pragma unroll
            for (int nt = 0; nt < 4; nt++) {
                uint32_t ko =
                    (uint32_t)((nt * 16 + (lane & 7) + (lane >> 4) * 8) * (AP * 2) +
                               ((lane >> 3) & 1) * 16 + ks * 32);
                ldsm4(kf[nt], kBuf + ko);
            }
#pragma unroll
            for (int ni = 0; ni < 8; ni++)
                mma16816h(st[ni], qf[ks], &kf[ni >> 1][(ni & 1) * 2]);
        }

#pragma unroll
        for (int ni = 0; ni < 8; ni++)
#pragma unroll
            for (int e = 0; e < 4; e++) st[ni][e] *= 0.125f;
        if (kt == qt) {
#pragma unroll
            for (int ni = 0; ni < 8; ni++) {
                int cb = ni * 8 + (lane & 3) * 2;
                if (cb > rl0)         st[ni][0] = -1e30f;
                if (cb + 1 > rl0)     st[ni][1] = -1e30f;
                if (cb > rl0 + 8)     st[ni][2] = -1e30f;
                if (cb + 1 > rl0 + 8) st[ni][3] = -1e30f;
            }
        }

        float t0 = -1e30f, t1 = -1e30f;
#pragma unroll
        for (int ni = 0; ni < 8; ni++) {
            t0 = fmaxf(t0, fmaxf(st[ni][0], st[ni][1]));
            t1 = fmaxf(t1, fmaxf(st[ni][2], st[ni][3]));
        }
        t0 = fmaxf(t0, __shfl_xor_sync(0xffffffffu, t0, 1));
        t0 = fmaxf(t0, __shfl_xor_sync(0xffffffffu, t0, 2));
        t1 = fmaxf(t1, __shfl_xor_sync(0xffffffffu, t1, 1));
        t1 = fmaxf(t1, __shfl_xor_sync(0xffffffffu, t1, 2));
        float mn0 = fmaxf(m_0, t0), mn1 = fmaxf(m_1, t1);
        float fr0 = __expf(m_0 - mn0), fr1 = __expf(m_1 - mn1);
        m_0 = mn0; m_1 = mn1;
        float ps0 = 0.f, ps1 = 0.f;
#pragma unroll
        for (int ni = 0; ni < 8; ni++) {
            float p0 = __expf(st[ni][0] - mn0); st[ni][0] = p0; ps0 += p0;
            float p1 = __expf(st[ni][1] - mn0); st[ni][1] = p1; ps0 += p1;
            float p2 = __expf(st[ni][2] - mn1); st[ni][2] = p2; ps1 += p2;
            float p3 = __expf(st[ni][3] - mn1); st[ni][3] = p3; ps1 += p3;
        }
        ps0 += __shfl_xor_sync(0xffffffffu, ps0, 1);
        ps0 += __shfl_xor_sync(0xffffffffu, ps0, 2);
        ps1 += __shfl_xor_sync(0xffffffffu, ps1, 1);
        ps1 += __shfl_xor_sync(0xffffffffu, ps1, 2);
        l_0 = l_0 * fr0 + ps0;
        l_1 = l_1 * fr1 + ps1;
#pragma unroll
        for (int ni = 0; ni < 8; ni++) {
            acc[ni][0] *= fr0; acc[ni][1] *= fr0;
            acc[ni][2] *= fr1; acc[ni][3] *= fr1;
        }

#pragma unroll
        for (int ks = 0; ks < 4; ks++) {
            uint32_t pa[4];
            pa[0] = pack_h2(st[2 * ks][0],     st[2 * ks][1]);
            pa[1] = pack_h2(st[2 * ks][2],     st[2 * ks][3]);
            pa[2] = pack_h2(st[2 * ks + 1][0], st[2 * ks + 1][1]);
            pa[3] = pack_h2(st[2 * ks + 1][2], st[2 * ks + 1][3]);
            uint32_t vf[4][4];
#pragma unroll
            for (int vt = 0; vt < 4; vt++) {
                uint32_t vo =
                    (uint32_t)(((lane & 7) + ((lane >> 3) & 1) * 8 + ks * 16) * (AP * 2) +
                               (vt * 16 + (lane >> 4) * 8) * 2);
                ldsm4t(vf[vt], vBuf + vo);
            }
#pragma unroll
            for (int ni = 0; ni < 8; ni++)
                mma16816h(acc[ni], pa, &vf[ni >> 1][(ni & 1) * 2]);
        }
        barx(barid);
    }

    float i0 = 1.f / l_0, i1 = 1.f / l_1;
    const int r0 = q0 + rl0;
#pragma unroll
    for (int ni = 0; ni < 8; ni++) {
        int col = ni * 8 + (lane & 3) * 2;
        size_t o = base + (size_t)r0 * CD + col;
        *(uint32_t*)(At + o) = pack_h2(acc[ni][0] * i0, acc[ni][1] * i0);
        *(uint32_t*)(At + o + (size_t)8 * CD) =
            pack_h2(acc[ni][2] * i1, acc[ni][3] * i1);
    }
}

// ----------------------------------------------------------------------------
// Embedding / LayerNorm
// ----------------------------------------------------------------------------
__global__ void embed_kernel(const int* __restrict__ ids,
                             const float* __restrict__ tok,
                             const float* __restrict__ pos,
                             float* __restrict__ h) {
    int i = blockIdx.x;
    int d = threadIdx.x;
    int s = i & (CS - 1);
    h[(size_t)i * CD + d] = tok[(size_t)ids[i] * CD + d] + pos[(size_t)s * CD + d];
}

__global__ void ln_kernel(const float* __restrict__ x,
                          const float* __restrict__ sc,
                          const float* __restrict__ bi,
                          __half* __restrict__ yf) {
    int row = blockIdx.x * 8 + threadIdx.y;   // blockDim (32, 8)
    int lane = threadIdx.x;
    const float* xr = x + (size_t)row * CD;
    float v[8];
    float sum = 0.f, sq = 0.f;
#pragma unroll
    for (int j = 0; j < 8; j++) {
        v[j] = xr[lane * 8 + j];
        sum += v[j];
        sq += v[j] * v[j];
    }
#pragma unroll
    for (int o = 16; o > 0; o >>= 1) {
        sum += __shfl_xor_sync(0xffffffffu, sum, o);
        sq  += __shfl_xor_sync(0xffffffffu, sq, o);
    }
    float mean = sum * (1.f / CD);
    float var  = sq * (1.f / CD) - mean * mean;
    float inv  = rsqrtf(var + 1e-5f);
    size_t off = (size_t)row * CD + lane * 8;
    __half2 f[4];
#pragma unroll
    for (int j = 0; j < 4; j++) {
        int c = lane * 8 + 2 * j;
        float y0 = (v[2 * j]     - mean) * inv * sc[c]     + bi[c];
        float y1 = (v[2 * j + 1] - mean) * inv * sc[c + 1] + bi[c + 1];
        f[j] = __floats2half2_rn(y0, y1);
    }
    *(uint4*)(yf + off) = *(uint4*)f;
}

// ----------------------------------------------------------------------------
// Orchestration
// ----------------------------------------------------------------------------
extern "C" void kernel_launch(void* const* d_in, const int* in_sizes, int n_in,
                              void* d_out, int out_size) {
    const int*   ids  = (const int*)d_in[0];
    const float* tok  = (const float*)d_in[1];
    const float* pos  = (const float*)d_in[2];
    const float* Wq   = (const float*)d_in[3];
    const float* bq   = (const float*)d_in[4];
    const float* Wk   = (const float*)d_in[5];
    const float* bk   = (const float*)d_in[6];
    const float* Wv   = (const float*)d_in[7];
    const float* bv   = (const float*)d_in[8];
    const float* Wo   = (const float*)d_in[9];
    const float* bo   = (const float*)d_in[10];
    const float* ln1s = (const float*)d_in[11];
    const float* ln1b = (const float*)d_in[12];
    const float* ln2s = (const float*)d_in[13];
    const float* ln2b = (const float*)d_in[14];
    const float* W1   = (const float*)d_in[15];
    const float* b1   = (const float*)d_in[16];
    const float* W2   = (const float*)d_in[17];
    const float* b2   = (const float*)d_in[18];
    const float* lnfs = (const float*)d_in[19];
    const float* lnfb = (const float*)d_in[20];
    float* out = (float*)d_out;

    float* h;
    __half *n, *q, *k, *v, *att, *m, *tf, *wq, *wk, *wv, *wo, *w1, *w2;
    cudaGetSymbolAddress((void**)&h,   g_h);
    cudaGetSymbolAddress((void**)&n,   g_n);
    cudaGetSymbolAddress((void**)&q,   g_q);
    cudaGetSymbolAddress((void**)&k,   g_k);
    cudaGetSymbolAddress((void**)&v,   g_v);
    cudaGetSymbolAddress((void**)&att, g_att);
    cudaGetSymbolAddress((void**)&m,   g_m);
    cudaGetSymbolAddress((void**)&tf,  g_tf);
    cudaGetSymbolAddress((void**)&wq,  g_wq);
    cudaGetSymbolAddress((void**)&wk,  g_wk);
    cudaGetSymbolAddress((void**)&wv,  g_wv);
    cudaGetSymbolAddress((void**)&wo,  g_wo);
    cudaGetSymbolAddress((void**)&w1,  g_w1);
    cudaGetSymbolAddress((void**)&w2,  g_w2);

    cudaFuncSetAttribute(attn_kernel,
                         cudaFuncAttributeMaxDynamicSharedMemorySize, ATTN_SMEM);
    cudaFuncSetAttribute(gemm_res_kernel,
                         cudaFuncAttributeMaxDynamicSharedMemorySize, SMEM_RES);
    cudaFuncSetAttribute(gemm_gelu_kernel,
                         cudaFuncAttributeMaxDynamicSharedMemorySize, SMEM_BIG);
    cudaFuncSetAttribute(qkv_kernel,
                         cudaFuncAttributeMaxDynamicSharedMemorySize, SMEM_BIG);
    cudaFuncSetAttribute(lmhead_kernel,
                         cudaFuncAttributeMaxDynamicSharedMemorySize, SMEM_LMH);

    convert_all_kernel<<<(unsigned)((NP_TOT + 255) / 256), 256>>>(
        tok, Wq, Wk, Wv, Wo, W1, W2, tf, wq, wk, wv, wo, w1, w2);

    dim3 lnb(32, 8);
    embed_kernel<<<CM, CD>>>(ids, tok, pos, h);

    for (int l = 0; l < CL; l++) {
        size_t wofs  = (size_t)l * CD * CD;
        size_t bofs  = (size_t)l * CD;
        size_t w1ofs = (size_t)l * CD * CFF;
        size_t b1ofs = (size_t)l * CFF;
        size_t w2ofs = (size_t)l * CFF * CD;

        ln_kernel<<<CM / 8, lnb>>>(h, ln1s + bofs, ln1b + bofs, n);
        qkv_kernel<<<dim3(CD / 128, CM / 128, 3), 256, SMEM_BIG>>>(
            n, wq + wofs, wk + wofs, wv + wofs,
            bq + bofs, bk + bofs, bv + bofs, q, k, v);

        attn_kernel<<<dim3(16, CB * CH), 256, ATTN_SMEM>>>(q, k, v, att);

        gemm_res_kernel<<<dim3(CD / 64, CM / 128), 256, SMEM_RES>>>(
            att, wo + wofs, bo + bofs, h, h, CD, CD);

        ln_kernel<<<CM / 8, lnb>>>(h, ln2s + bofs, ln2b + bofs, n);
        gemm_gelu_kernel<<<dim3(CFF / 128, CM / 128), 256, SMEM_BIG>>>(
            n, w1 + w1ofs, b1 + b1ofs, m, CFF, CD);
        gemm_res_kernel<<<dim3(CD / 64, CM / 128), 256, SMEM_RES>>>(
            m, w2 + w2ofs, b2 + bofs, h, h, CD, CFF);
    }

    ln_kernel<<<CM / 8, lnb>>>(h, lnfs, lnfb, n);
    lmhead_kernel<<<dim3(CM / 128, (CV + 127) / 128), 256, SMEM_LMH>>>(
        n, tf, out);
}